// round 12
// baseline (speedup 1.0000x reference)
#include <cuda_runtime.h>
#include <math.h>

#define PI_D 3.14159265358979323846

// ---------------- static device scratch ----------------
__device__ float4 g_S4[512 * 128 * 128];      // state [b][X][Y], float4 = (f0, f1) complex pair
__device__ float4 g_U0[128 * 128 * 2];        // mux0, bitrev-permuted, [kxb][kyb]
__device__ float4 g_U1[2 * 2 * 64 * 64 * 2];  // mux1, bitrev-permuted, TRANSPOSED [cx][cy][kyb][kxb]
__device__ float4 g_U2[2 * 2 * 32 * 32 * 2];  // mux2, bitrev-permuted, TRANSPOSED [cx][cy][kyb][kxb]
__device__ float2 g_TW[64];                   // exp(-2*pi*i*t/128)
__device__ int    g_NR[128];                  // bitrev-domain negation table
__device__ float  g_part[512 * 2 * 10];       // partial logits per (b, xc1)

// ---- float2 complex helpers ----
__device__ __forceinline__ float2 cmul(float2 a, float2 b) {
    return make_float2(a.x * b.x - a.y * b.y, a.x * b.y + a.y * b.x);
}
__device__ __forceinline__ float2 f2add(float2 a, float2 b) { return make_float2(a.x + b.x, a.y + b.y); }
__device__ __forceinline__ float2 f2sub(float2 a, float2 b) { return make_float2(a.x - b.x, a.y - b.y); }
__device__ __forceinline__ float2 csq(float2 a) { return make_float2(a.x * a.x - a.y * a.y, 2.f * a.x * a.y); }

// ---- float4 = two complex numbers, same twiddle applied to both ----
__device__ __forceinline__ float4 f4add(float4 a, float4 b) {
    return make_float4(a.x + b.x, a.y + b.y, a.z + b.z, a.w + b.w);
}
__device__ __forceinline__ float4 f4sub(float4 a, float4 b) {
    return make_float4(a.x - b.x, a.y - b.y, a.z - b.z, a.w - b.w);
}
__device__ __forceinline__ float4 f4sc(float4 a, float s) {
    return make_float4(a.x * s, a.y * s, a.z * s, a.w * s);
}
__device__ __forceinline__ float4 c4mul(float4 v, float2 w) {
    return make_float4(v.x * w.x - v.y * w.y, v.x * w.y + v.y * w.x,
                       v.z * w.x - v.w * w.y, v.z * w.y + v.w * w.x);
}
__device__ __forceinline__ float4 c4mulc(float4 v, float2 w) {
    return make_float4(v.x * w.x + v.y * w.y, v.y * w.x - v.x * w.y,
                       v.z * w.x + v.w * w.y, v.w * w.x - v.z * w.y);
}
__device__ __forceinline__ float4 c4mulnegi(float4 v) {  // *( -i )
    return make_float4(v.y, -v.x, v.w, -v.z);
}
__device__ __forceinline__ float4 c4mulposi(float4 v) {  // *( +i )
    return make_float4(-v.y, v.x, -v.w, v.z);
}
// mux on one float4 site: q0=(x,y), q1=(z,w)
__device__ __forceinline__ float4 mux4(float4 v, float4 uA, float4 uB) {
    float4 o;
    o.x = uA.x * v.x - uA.y * v.y + uA.z * v.z - uA.w * v.w;
    o.y = uA.x * v.y + uA.y * v.x + uA.z * v.w + uA.w * v.z;
    o.z = uB.x * v.x - uB.y * v.y + uB.z * v.z - uB.w * v.w;
    o.w = uB.x * v.y + uB.y * v.x + uB.z * v.w + uB.w * v.z;
    return o;
}

// =====================================================================
// float4 FFT passes. element (line, p) at base[(line&(2^LG1-1))*SL1 + (line>>LG1)*SL2 + p*SP]
// FWD: DIF natural->bitrev; INV: DIT bitrev->natural (conj twiddles), scale on LAST.
// =====================================================================
template<bool INV, int NTT, int SP, int SL1, int LG1, int SL2, int LG2, int LOGN, int S, bool LAST>
__device__ __forceinline__ void pass4(float4* __restrict__ base,
                                      const float2* __restrict__ tw, float scale) {
    constexpr int L = 1 << (LG1 + LG2);
    constexpr int ITEMS = L << (LOGN - 2);
    constexpr int h = 1 << S;
    for (int u = threadIdx.x; u < ITEMS; u += NTT) {
        const int line = u & (L - 1);
        const int loff = (line & ((1 << LG1) - 1)) * SL1 + (line >> LG1) * SL2;
        const int v = u >> (LG1 + LG2);
        const int t = v & (h - 1);
        const int p = ((v >> S) << (S + 2)) + t;
        float4* e = base + loff + p * SP;
        float4 a = e[0], b = e[h * SP], c = e[2 * h * SP], d = e[3 * h * SP];
        const float2 w0 = tw[t << (5 - S)];
        const float2 w1 = make_float2(w0.y, -w0.x);
        const float2 w2 = csq(w0);
        if constexpr (!INV) {
            float4 ac = f4add(a, c), bd = f4add(b, d);
            float4 cP = c4mul(f4sub(a, c), w0);
            float4 dP = c4mul(f4sub(b, d), w1);
            e[0]          = f4add(ac, bd);
            e[h * SP]     = c4mul(f4sub(ac, bd), w2);
            e[2 * h * SP] = f4add(cP, dP);
            e[3 * h * SP] = c4mul(f4sub(cP, dP), w2);
        } else {
            float4 bw = c4mulc(b, w2), dw = c4mulc(d, w2);
            float4 aP = f4add(a, bw), bP = f4sub(a, bw);
            float4 cP = f4add(c, dw), dP = f4sub(c, dw);
            float4 cw = c4mulc(cP, w0), dq = c4mulc(dP, w1);
            float4 o0 = f4add(aP, cw), o2 = f4sub(aP, cw);
            float4 o1 = f4add(bP, dq), o3 = f4sub(bP, dq);
            if constexpr (LAST) {
                o0 = f4sc(o0, scale); o1 = f4sc(o1, scale);
                o2 = f4sc(o2, scale); o3 = f4sc(o3, scale);
            }
            e[0] = o0; e[h * SP] = o1; e[2 * h * SP] = o2; e[3 * h * SP] = o3;
        }
    }
    __syncthreads();
}

template<bool INV, int NTT, int SP, int SL1, int LG1, int SL2, int LG2, int LOGN, int S, bool LAST>
__device__ __forceinline__ void pass2(float4* __restrict__ base,
                                      const float2* __restrict__ tw, float scale) {
    constexpr int L = 1 << (LG1 + LG2);
    constexpr int ITEMS = L << (LOGN - 1);
    constexpr int h = 1 << S;
    for (int u = threadIdx.x; u < ITEMS; u += NTT) {
        const int line = u & (L - 1);
        const int loff = (line & ((1 << LG1) - 1)) * SL1 + (line >> LG1) * SL2;
        const int v = u >> (LG1 + LG2);
        const int t = v & (h - 1);
        const int p = ((v >> S) << (S + 1)) + t;
        float4* e = base + loff + p * SP;
        float4 a = e[0], b = e[h * SP];
        const float2 w = tw[t << (6 - S)];
        if constexpr (!INV) {
            e[0]      = f4add(a, b);
            e[h * SP] = c4mul(f4sub(a, b), w);
        } else {
            float4 bw = c4mulc(b, w);
            float4 o0 = f4add(a, bw), o1 = f4sub(a, bw);
            if constexpr (LAST) { o0 = f4sc(o0, scale); o1 = f4sc(o1, scale); }
            e[0] = o0; e[h * SP] = o1;
        }
    }
    __syncthreads();
}

template<bool INV, int NTT, int SP, int SL1, int LG1, int SL2, int LG2, int LOGN>
__device__ __forceinline__ void fft_run(float4* __restrict__ base,
                                        const float2* __restrict__ tw, float scale) {
    if constexpr (!INV) {
        if constexpr (LOGN == 6) {
            pass4<false, NTT, SP, SL1, LG1, SL2, LG2, 6, 4, false>(base, tw, 1.f);
            pass4<false, NTT, SP, SL1, LG1, SL2, LG2, 6, 2, false>(base, tw, 1.f);
            pass4<false, NTT, SP, SL1, LG1, SL2, LG2, 6, 0, false>(base, tw, 1.f);
        } else {
            pass4<false, NTT, SP, SL1, LG1, SL2, LG2, 5, 3, false>(base, tw, 1.f);
            pass4<false, NTT, SP, SL1, LG1, SL2, LG2, 5, 1, false>(base, tw, 1.f);
            pass2<false, NTT, SP, SL1, LG1, SL2, LG2, 5, 0, false>(base, tw, 1.f);
        }
    } else {
        if constexpr (LOGN == 6) {
            pass4<true, NTT, SP, SL1, LG1, SL2, LG2, 6, 0, false>(base, tw, 1.f);
            pass4<true, NTT, SP, SL1, LG1, SL2, LG2, 6, 2, false>(base, tw, 1.f);
            pass4<true, NTT, SP, SL1, LG1, SL2, LG2, 6, 4, true >(base, tw, scale);
        } else {
            pass4<true, NTT, SP, SL1, LG1, SL2, LG2, 5, 0, false>(base, tw, 1.f);
            pass4<true, NTT, SP, SL1, LG1, SL2, LG2, 5, 2, false>(base, tw, 1.f);
            pass2<true, NTT, SP, SL1, LG1, SL2, LG2, 5, 4, true >(base, tw, scale);
        }
    }
}

// ---------------- float2 passes (p1 only: packed Hermitian plane) ----------------
template<int NTT, int SP, int LG1, int LOGN, int S>
__device__ __forceinline__ void pass4s(float2* __restrict__ base,
                                       const float2* __restrict__ tw) {
    constexpr int L = 1 << LG1;
    constexpr int ITEMS = L << (LOGN - 2);
    constexpr int h = 1 << S;
    for (int u = threadIdx.x; u < ITEMS; u += NTT) {
        const int loff = (u & (L - 1));
        const int v = u >> LG1;
        const int t = v & (h - 1);
        const int p = ((v >> S) << (S + 2)) + t;
        float2* e = base + loff + p * SP;
        float2 a = e[0], b = e[h * SP], c = e[2 * h * SP], d = e[3 * h * SP];
        const float2 w0 = tw[t << (5 - S)];
        const float2 w1 = make_float2(w0.y, -w0.x);
        const float2 w2 = csq(w0);
        float2 ac = f2add(a, c), bd = f2add(b, d);
        float2 cP = cmul(f2sub(a, c), w0);
        float2 dP = cmul(f2sub(b, d), w1);
        e[0]          = f2add(ac, bd);
        e[h * SP]     = cmul(f2sub(ac, bd), w2);
        e[2 * h * SP] = f2add(cP, dP);
        e[3 * h * SP] = cmul(f2sub(cP, dP), w2);
    }
    __syncthreads();
}
template<int NTT, int SP, int LG1, int LOGN, int S>
__device__ __forceinline__ void pass2s(float2* __restrict__ base,
                                       const float2* __restrict__ tw) {
    constexpr int L = 1 << LG1;
    constexpr int ITEMS = L << (LOGN - 1);
    constexpr int h = 1 << S;
    for (int u = threadIdx.x; u < ITEMS; u += NTT) {
        const int loff = (u & (L - 1));
        const int v = u >> LG1;
        const int t = v & (h - 1);
        const int p = ((v >> S) << (S + 1)) + t;
        float2* e = base + loff + p * SP;
        float2 a = e[0], b = e[h * SP];
        const float2 w = tw[t << (6 - S)];
        e[0]      = f2add(a, b);
        e[h * SP] = cmul(f2sub(a, b), w);
    }
    __syncthreads();
}

// ---------------- K0: precompute ----------------
__device__ __forceinline__ void writeU(float4* dst, float axf, float ayf, float azf) {
    double ax = axf, ay = ayf, az = azf;
    double r = sqrt(ax * ax + ay * ay + az * az + 1e-20);
    double cr = cos(r), sn = sin(r) / r;
    dst[0] = make_float4((float)cr, (float)(-az * sn), (float)(-ay * sn), (float)(-ax * sn));
    dst[1] = make_float4((float)(ay * sn), (float)(-ax * sn), (float)cr, (float)(az * sn));
}

__global__ void k0(const float* __restrict__ mux0, const float* __restrict__ mux1,
                   const float* __restrict__ mux2) {
    int idx = blockIdx.x * blockDim.x + threadIdx.x;   // 16384 threads
    if (idx < 64) {
        double ang = -2.0 * PI_D * (double)idx / 128.0;
        g_TW[idx] = make_float2((float)cos(ang), (float)sin(ang));
    }
    if (idx < 128) {
        int k = __brev((unsigned)idx) >> 25;
        g_NR[idx] = (int)(__brev((unsigned)((128 - k) & 127)) >> 25);
    }
    {   // U0: [kxb][kyb] (consumed by p2 with Y-fastest lanes -> already coalesced)
        int kxb = idx >> 7, kyb = idx & 127;
        int kx = __brev((unsigned)kxb) >> 25, ky = __brev((unsigned)kyb) >> 25;
        const float* c = mux0 + (kx * 128 + ky) * 3;
        writeU(&g_U0[idx * 2], c[0], c[1], c[2]);
    }
    {   // U1: TRANSPOSED [cx][cy][kyb][kxb] (consumed by p35 with X-fastest lanes)
        int cx = idx >> 13, cy = (idx >> 12) & 1, kxb = (idx >> 6) & 63, kyb = idx & 63;
        int kx = __brev((unsigned)kxb) >> 26, ky = __brev((unsigned)kyb) >> 26;
        const float* c = mux1 + (((cx * 2 + cy) * 64 + kx) * 64 + ky) * 3;
        int tidx = (cx << 13) + (cy << 12) + (kyb << 6) + kxb;
        writeU(&g_U1[tidx * 2], c[0], c[1], c[2]);
    }
    if (idx < 4096) {   // U2: TRANSPOSED [cx][cy][kyb][kxb]
        int cx = idx >> 11, cy = (idx >> 10) & 1, kxb = (idx >> 5) & 31, kyb = idx & 31;
        int kx = __brev((unsigned)kxb) >> 27, ky = __brev((unsigned)kyb) >> 27;
        const float* c = mux2 + (((cx * 2 + cy) * 32 + kx) * 32 + ky) * 3;
        int tidx = (cx << 11) + (cy << 10) + (kyb << 5) + kxb;
        writeU(&g_U2[tidx * 2], c[0], c[1], c[2]);
    }
}

// ---------------- P1: encode + y-FFT128 (Hermitian packed) ----------------
#define NT1 512
__global__ __launch_bounds__(NT1) void p1(const float* __restrict__ images) {
    __shared__ float2 z[128 * 33];
    __shared__ float2 tw[64];
    const int b = blockIdx.y, X0 = blockIdx.x * 32;
    for (int i = threadIdx.x; i < 64; i += NT1) tw[i] = g_TW[i];
    for (int idx = threadIdx.x; idx < 4096; idx += NT1) {
        int l = idx >> 7, y = idx & 127;
        float I = images[(b * 128 + X0 + l) * 128 + y];
        float sv, cv;
        sincosf(0.5f * (float)PI_D * I, &sv, &cv);
        z[y * 33 + l] = make_float2(cv * (1.0f / 128.0f), sv * (1.0f / 128.0f));
    }
    __syncthreads();
    pass4s<NT1, 33, 5, 7, 5>(z, tw);
    pass4s<NT1, 33, 5, 7, 3>(z, tw);
    pass4s<NT1, 33, 5, 7, 1>(z, tw);
    pass2s<NT1, 33, 5, 7, 0>(z, tw);
    for (int idx = threadIdx.x; idx < 4096; idx += NT1) {
        int l = idx >> 7, kb = idx & 127;
        float2 Z = z[kb * 33 + l];
        float2 Zn = z[g_NR[kb] * 33 + l];
        float2 C  = make_float2(0.5f * (Z.x + Zn.x), 0.5f * (Z.y - Zn.y));
        float2 Sf = make_float2(0.5f * (Z.y + Zn.y), 0.5f * (Zn.x - Z.x));
        int X = X0 + l;
        g_S4[(b * 128 + X) * 128 + kb] = make_float4(C.x, C.y, Sf.x, Sf.y);
    }
}

// ---------------- P2: x-FFT128 + mux0 + x-IFFT128 + x-FFT64(halves) ----------------
#define NT2 512
__global__ __launch_bounds__(NT2) void p2() {
    __shared__ float4 tile[128 * 16];
    __shared__ float2 tw[64];
    const int b = blockIdx.y, y0 = blockIdx.x * 16;
    for (int i = threadIdx.x; i < 64; i += NT2) tw[i] = g_TW[i];
    __syncthreads();
    // fused: fwd7 pass4 S=5 reading directly from global
    for (int u = threadIdx.x; u < 512; u += NT2) {
        int yl = u & 15, v = u >> 4;                 // v in [0,32) = position
        const float4* g = &g_S4[(b * 128 + v) * 128 + y0 + yl];
        float4 a = g[0], bb = g[32 * 128], c = g[64 * 128], d = g[96 * 128];
        const float2 w0 = tw[v];
        const float2 w1 = make_float2(w0.y, -w0.x);
        const float2 w2 = csq(w0);
        float4 ac = f4add(a, c), bd = f4add(bb, d);
        float4 cP = c4mul(f4sub(a, c), w0);
        float4 dP = c4mul(f4sub(bb, d), w1);
        float4* e = tile + v * 16 + yl;
        e[0]       = f4add(ac, bd);
        e[32 * 16] = c4mul(f4sub(ac, bd), w2);
        e[64 * 16] = f4add(cP, dP);
        e[96 * 16] = c4mul(f4sub(cP, dP), w2);
    }
    __syncthreads();
    pass4<false, NT2, 16, 1, 4, 0, 0, 7, 3, false>(tile, tw, 1.f);
    pass4<false, NT2, 16, 1, 4, 0, 0, 7, 1, false>(tile, tw, 1.f);
    // fused: fwd7 pass2 S=0 (w=1) + mux0
    for (int u = threadIdx.x; u < 1024; u += NT2) {
        int yl = u & 15, v = u >> 4;                 // v in [0,64)
        float4* e = tile + (2 * v) * 16 + yl;
        float4 a = e[0], bb = e[16];
        float4 o0 = f4add(a, bb), o1 = f4sub(a, bb);
        int i0 = (((2 * v) << 7) + y0 + yl) * 2;
        int i1 = (((2 * v + 1) << 7) + y0 + yl) * 2;
        e[0]  = mux4(o0, g_U0[i0], g_U0[i0 + 1]);
        e[16] = mux4(o1, g_U0[i1], g_U0[i1 + 1]);
    }
    __syncthreads();
    // inv128
    pass4<true, NT2, 16, 1, 4, 0, 0, 7, 0, false>(tile, tw, 1.f);
    pass4<true, NT2, 16, 1, 4, 0, 0, 7, 2, false>(tile, tw, 1.f);
    pass4<true, NT2, 16, 1, 4, 0, 0, 7, 4, false>(tile, tw, 1.f);
    pass2<true, NT2, 16, 1, 4, 0, 0, 7, 6, true >(tile, tw, 1.0f / 128.0f);
    // fwd64 halves: S=4, S=2, then fused S=0 + global store
    pass4<false, NT2, 16, 1, 4, 1024, 1, 6, 4, false>(tile, tw, 1.f);
    pass4<false, NT2, 16, 1, 4, 1024, 1, 6, 2, false>(tile, tw, 1.f);
    for (int u = threadIdx.x; u < 512; u += NT2) {
        int yl = u & 15, half = (u >> 4) & 1, v = u >> 5;   // v in [0,16)
        float4* e = tile + half * 1024 + (4 * v) * 16 + yl;
        float4 a = e[0], bb = e[16], c = e[32], d = e[48];
        // t=0: w0=1, w1=-i, w2=1
        float4 ac = f4add(a, c), bd = f4add(bb, d);
        float4 cP = f4sub(a, c);
        float4 dP = c4mulnegi(f4sub(bb, d));
        int Xb = half * 64 + 4 * v;
        float4* g = &g_S4[(b * 128 + Xb) * 128 + y0 + yl];
        g[0]   = f4add(ac, bd);
        g[128] = f4sub(ac, bd);
        g[256] = f4add(cP, dP);
        g[384] = f4sub(cP, dP);
    }
}

// ---------------- P35: y-junction(mux1 fused) + x-junction + y-junction(mux2 fused)
//                   + final IFFT32s (measure fused) + partial GEMV ----------------
#define NT3 1024
#define P35_SMEM (132096 + 512 + 16384 + 1280)
__global__ __launch_bounds__(NT3) void p35(const float* __restrict__ W) {
    extern __shared__ char sm[];
    float4* tile = (float4*)sm;                            // [64 X][129] float4
    float2* tw   = (float2*)(sm + 132096);
    float*  prob = (float*)(sm + 132096 + 512);            // [32 ya][2 f][64 X] partials
    float*  red  = (float*)(sm + 132096 + 512 + 16384);    // 32*10 f32
    const int b = blockIdx.y, xc1 = blockIdx.x;
    for (int i = threadIdx.x; i < 64; i += NT3) tw[i] = g_TW[i];
    __syncthreads();
    // fused: inv7-y pass4 S=0 reading directly from global (t=0: w0=1, w1=-i -> conj=+i, w2=1)
    for (int u = threadIdx.x; u < 2048; u += NT3) {
        int X = u & 63, v = u >> 6;                        // v in [0,32)
        const float4* g = &g_S4[(b * 128 + xc1 * 64 + X) * 128 + 4 * v];
        float4 a = g[0], bb = g[1], c = g[2], d = g[3];
        float4 aP = f4add(a, bb), bP = f4sub(a, bb);
        float4 cP = f4add(c, d);
        float4 dq = c4mulposi(f4sub(c, d));
        float4* e = tile + X * 129 + 4 * v;
        e[0] = f4add(aP, cP);
        e[2] = f4sub(aP, cP);
        e[1] = f4add(bP, dq);
        e[3] = f4sub(bP, dq);
    }
    __syncthreads();
    pass4<true, NT3, 1, 129, 6, 0, 0, 7, 2, false>(tile, tw, 1.f);
    pass4<true, NT3, 1, 129, 6, 0, 0, 7, 4, false>(tile, tw, 1.f);
    pass2<true, NT3, 1, 129, 6, 0, 0, 7, 6, true >(tile, tw, 1.0f / 128.0f);
    // fwd64 y halves: S=4, S=2, fused S=0 + mux1 (transposed table: coalesced in X)
    pass4<false, NT3, 1, 129, 6, 64, 1, 6, 4, false>(tile, tw, 1.f);
    pass4<false, NT3, 1, 129, 6, 64, 1, 6, 2, false>(tile, tw, 1.f);
    for (int u = threadIdx.x; u < 2048; u += NT3) {
        int X = u & 63, half = (u >> 6) & 1, v = u >> 7;   // v in [0,16)
        float4* e = tile + X * 129 + half * 64 + 4 * v;
        float4 a = e[0], bb = e[1], c = e[2], d = e[3];
        // t=0: w0=1, w1=-i, w2=1
        float4 ac = f4add(a, c), bd = f4add(bb, d);
        float4 cP = f4sub(a, c);
        float4 dP = c4mulnegi(f4sub(bb, d));
        float4 o0 = f4add(ac, bd), o1 = f4sub(ac, bd);
        float4 o2 = f4add(cP, dP), o3 = f4sub(cP, dP);
        // transposed U1: index = ((cx*2+cy)<<12) + (Yb<<6) + X, Yb = 4v+k
        int ub = (((xc1 * 2 + half) << 12) + ((4 * v) << 6) + X) * 2;
        e[0] = mux4(o0, g_U1[ub],       g_U1[ub + 1]);
        e[1] = mux4(o1, g_U1[ub + 128], g_U1[ub + 129]);
        e[2] = mux4(o2, g_U1[ub + 256], g_U1[ub + 257]);
        e[3] = mux4(o3, g_U1[ub + 384], g_U1[ub + 385]);
    }
    __syncthreads();
    // x junction 64->32
    fft_run<true,  NT3, 129, 1, 7, 0,    0, 6>(tile, tw, 1.0f / 64.0f);
    fft_run<false, NT3, 129, 1, 7, 4128, 1, 5>(tile, tw, 1.f);
    // y junction 64->32: inv64 halves, fwd32 segs (S=3, S=1, fused S=0 + mux2)
    fft_run<true, NT3, 1, 129, 6, 64, 1, 6>(tile, tw, 1.0f / 64.0f);
    pass4<false, NT3, 1, 129, 6, 32, 2, 5, 3, false>(tile, tw, 1.f);
    pass4<false, NT3, 1, 129, 6, 32, 2, 5, 1, false>(tile, tw, 1.f);
    for (int u = threadIdx.x; u < 4096; u += NT3) {
        int X = u & 63, seg = (u >> 6) & 3, v = u >> 8;    // v in [0,16)
        float4* e = tile + X * 129 + seg * 32 + 2 * v;
        float4 a = e[0], bb = e[1];
        float4 o0 = f4add(a, bb), o1 = f4sub(a, bb);       // w=1
        int xc2 = X >> 5, yc2 = seg & 1;
        // transposed U2: index = ((cx*2+cy)<<10) + (Yb<<5) + (X&31), Yb = 2v+k
        int ub = (((xc2 * 2 + yc2) << 10) + ((2 * v) << 5) + (X & 31)) * 2;
        e[0] = mux4(o0, g_U2[ub],      g_U2[ub + 1]);
        e[1] = mux4(o1, g_U2[ub + 64], g_U2[ub + 65]);
    }
    __syncthreads();
    // final x inv32
    fft_run<true, NT3, 129, 1, 7, 4128, 1, 5>(tile, tw, 1.0f / 32.0f);
    // final y inv32: pass4 S=0, pass4 S=2, then FUSED last pass (S=4, scale) + measurement
    pass4<true, NT3, 1, 129, 6, 32, 2, 5, 0, false>(tile, tw, 1.f);
    pass4<true, NT3, 1, 129, 6, 32, 2, 5, 2, false>(tile, tw, 1.f);
    for (int u = threadIdx.x; u < 1024; u += NT3) {
        int X = u & 63, t = u >> 6;                        // t in [0,16)
        const float2 w = tw[t << 2];
        float s0a = 0.f, s1a = 0.f, s0b = 0.f, s1b = 0.f;
        #pragma unroll
        for (int seg = 0; seg < 4; ++seg) {
            const float4* e = tile + X * 129 + seg * 32 + t;
            float4 a = e[0], bb = e[16];
            float4 bw = c4mulc(bb, w);
            float4 o0 = f4add(a, bw), o1 = f4sub(a, bw);
            s0a += o0.x * o0.x + o0.y * o0.y;  s1a += o0.z * o0.z + o0.w * o0.w;
            s0b += o1.x * o1.x + o1.y * o1.y;  s1b += o1.z * o1.z + o1.w * o1.w;
        }
        const float sc2 = (1.0f / 32.0f) * (1.0f / 32.0f);
        // prob layout [ya][f][X]: X lane-fastest -> conflict-free
        prob[(t * 2 + 0) * 64 + X]        = s0a * sc2;
        prob[(t * 2 + 1) * 64 + X]        = s1a * sc2;
        prob[((t + 16) * 2 + 0) * 64 + X] = s0b * sc2;
        prob[((t + 16) * 2 + 1) * 64 + X] = s1b * sc2;
    }
    __syncthreads();
    // partial GEMV: combine xc2 halves deterministically per thread
    float acc[10];
    #pragma unroll
    for (int c = 0; c < 10; ++c) acc[c] = 0.f;
    {
        int xa = threadIdx.x >> 5, ya = threadIdx.x & 31;
        float p0 = prob[(ya * 2 + 0) * 64 + xa] + prob[(ya * 2 + 0) * 64 + 32 + xa];
        float p1 = prob[(ya * 2 + 1) * 64 + xa] + prob[(ya * 2 + 1) * 64 + 32 + xa];
        int j0 = threadIdx.x * 2;   // = (xa*32+ya)*2
        #pragma unroll
        for (int c = 0; c < 10; ++c) {
            float2 wv = *(const float2*)(W + c * 2048 + j0);
            acc[c] = fmaf(p0, wv.x, fmaf(p1, wv.y, acc[c]));
        }
    }
    #pragma unroll
    for (int c = 0; c < 10; ++c)
        #pragma unroll
        for (int o = 16; o > 0; o >>= 1)
            acc[c] += __shfl_down_sync(0xffffffffu, acc[c], o);
    const int warp = threadIdx.x >> 5, lane = threadIdx.x & 31;
    if (lane == 0)
        #pragma unroll
        for (int c = 0; c < 10; ++c) red[warp * 10 + c] = acc[c];
    __syncthreads();
    if (threadIdx.x < 10) {
        float s = 0.f;
        #pragma unroll
        for (int w = 0; w < 32; ++w) s += red[w * 10 + threadIdx.x];
        g_part[(b * 2 + xc1) * 10 + threadIdx.x] = s;
    }
}

// ---------------- combine ----------------
__global__ void pc(const float* __restrict__ bias, float* __restrict__ out) {
    int i = blockIdx.x * blockDim.x + threadIdx.x;
    if (i < 5120) {
        int b = i / 10, c = i % 10;
        out[i] = bias[c] + g_part[(b * 2) * 10 + c] + g_part[(b * 2 + 1) * 10 + c];
    }
}

// ---------------- launch ----------------
extern "C" void kernel_launch(void* const* d_in, const int* in_sizes, int n_in,
                              void* d_out, int out_size) {
    const float* images = (const float*)d_in[0];
    const float* mux0 = (const float*)d_in[1];
    const float* mux1 = (const float*)d_in[2];
    const float* mux2 = (const float*)d_in[3];
    const float* W = (const float*)d_in[4];
    const float* bias = (const float*)d_in[5];
    float* out = (float*)d_out;
    (void)in_sizes; (void)n_in; (void)out_size;

    cudaFuncSetAttribute(p35, cudaFuncAttributeMaxDynamicSharedMemorySize, P35_SMEM);

    k0<<<64, 256>>>(mux0, mux1, mux2);
    p1<<<dim3(4, 512), NT1>>>(images);
    p2<<<dim3(8, 512), NT2>>>();
    p35<<<dim3(2, 512), NT3, P35_SMEM>>>(W);
    pc<<<10, 512>>>(bias, out);
}

// round 13
// speedup vs baseline: 1.0903x; 1.0903x over previous
#include <cuda_runtime.h>
#include <math.h>

#define PI_D 3.14159265358979323846

// ---------------- static device scratch ----------------
__device__ float4 g_S4[512 * 128 * 128];      // state [b][X][Y], float4 = (f0, f1) complex pair
__device__ float4 g_U0[128 * 128 * 2];        // mux0, bitrev-permuted, [kxb][kyb]
__device__ float4 g_U1[2 * 2 * 64 * 64 * 2];  // mux1, bitrev-permuted, TRANSPOSED [cx][cy][kyb][kxb]
__device__ float4 g_U2[2 * 2 * 32 * 32 * 2];  // mux2, bitrev-permuted, TRANSPOSED [cx][cy][kyb][kxb]
__device__ float2 g_TW[64];                   // exp(-2*pi*i*t/128)
__device__ int    g_NR[128];                  // bitrev-domain negation table
__device__ float  g_part[512 * 2 * 10];       // partial logits per (b, xc1)

// ---- float2 complex helpers ----
__device__ __forceinline__ float2 cmul(float2 a, float2 b) {
    return make_float2(a.x * b.x - a.y * b.y, a.x * b.y + a.y * b.x);
}
__device__ __forceinline__ float2 f2add(float2 a, float2 b) { return make_float2(a.x + b.x, a.y + b.y); }
__device__ __forceinline__ float2 f2sub(float2 a, float2 b) { return make_float2(a.x - b.x, a.y - b.y); }
__device__ __forceinline__ float2 csq(float2 a) { return make_float2(a.x * a.x - a.y * a.y, 2.f * a.x * a.y); }

// ---- float4 = two complex numbers, same twiddle applied to both ----
__device__ __forceinline__ float4 f4add(float4 a, float4 b) {
    return make_float4(a.x + b.x, a.y + b.y, a.z + b.z, a.w + b.w);
}
__device__ __forceinline__ float4 f4sub(float4 a, float4 b) {
    return make_float4(a.x - b.x, a.y - b.y, a.z - b.z, a.w - b.w);
}
__device__ __forceinline__ float4 f4sc(float4 a, float s) {
    return make_float4(a.x * s, a.y * s, a.z * s, a.w * s);
}
__device__ __forceinline__ float4 c4mul(float4 v, float2 w) {
    return make_float4(v.x * w.x - v.y * w.y, v.x * w.y + v.y * w.x,
                       v.z * w.x - v.w * w.y, v.z * w.y + v.w * w.x);
}
__device__ __forceinline__ float4 c4mulc(float4 v, float2 w) {
    return make_float4(v.x * w.x + v.y * w.y, v.y * w.x - v.x * w.y,
                       v.z * w.x + v.w * w.y, v.w * w.x - v.z * w.y);
}
__device__ __forceinline__ float4 c4mulnegi(float4 v) {  // *( -i )
    return make_float4(v.y, -v.x, v.w, -v.z);
}
__device__ __forceinline__ float4 c4mulposi(float4 v) {  // *( +i )
    return make_float4(-v.y, v.x, -v.w, v.z);
}
// mux on one float4 site: q0=(x,y), q1=(z,w)
__device__ __forceinline__ float4 mux4(float4 v, float4 uA, float4 uB) {
    float4 o;
    o.x = uA.x * v.x - uA.y * v.y + uA.z * v.z - uA.w * v.w;
    o.y = uA.x * v.y + uA.y * v.x + uA.z * v.w + uA.w * v.z;
    o.z = uB.x * v.x - uB.y * v.y + uB.z * v.z - uB.w * v.w;
    o.w = uB.x * v.y + uB.y * v.x + uB.z * v.w + uB.w * v.z;
    return o;
}

// ---- register-level butterflies (exact template math) ----
// INV radix-4 last stage (S with h): inputs (a,b,c,d) at (p, p+h, p+2h, p+3h), outputs same
__device__ __forceinline__ void inv4q(float4 a, float4 b, float4 c, float4 d,
                                      float2 w0, float s,
                                      float4& o0, float4& o1, float4& o2, float4& o3) {
    float2 w1 = make_float2(w0.y, -w0.x);
    float2 w2 = csq(w0);
    float4 bw = c4mulc(b, w2), dw = c4mulc(d, w2);
    float4 aP = f4add(a, bw), bP = f4sub(a, bw);
    float4 cP = f4add(c, dw), dP = f4sub(c, dw);
    float4 cw = c4mulc(cP, w0), dq = c4mulc(dP, w1);
    o0 = f4sc(f4add(aP, cw), s); o2 = f4sc(f4sub(aP, cw), s);
    o1 = f4sc(f4add(bP, dq), s); o3 = f4sc(f4sub(bP, dq), s);
}
// FWD radix-4 stage: inputs (a,b,c,d) at (p, p+h, p+2h, p+3h), outputs same
__device__ __forceinline__ void fwd4q(float4 a, float4 b, float4 c, float4 d,
                                      float2 w0,
                                      float4& o0, float4& o1, float4& o2, float4& o3) {
    float2 w1 = make_float2(w0.y, -w0.x);
    float2 w2 = csq(w0);
    float4 ac = f4add(a, c), bd = f4add(b, d);
    float4 cP = c4mul(f4sub(a, c), w0);
    float4 dP = c4mul(f4sub(b, d), w1);
    o0 = f4add(ac, bd);
    o1 = c4mul(f4sub(ac, bd), w2);
    o2 = f4add(cP, dP);
    o3 = c4mul(f4sub(cP, dP), w2);
}

// =====================================================================
// float4 FFT passes. element (line, p) at base[(line&(2^LG1-1))*SL1 + (line>>LG1)*SL2 + p*SP]
// FWD: DIF natural->bitrev; INV: DIT bitrev->natural (conj twiddles), scale on LAST.
// =====================================================================
template<bool INV, int NTT, int SP, int SL1, int LG1, int SL2, int LG2, int LOGN, int S, bool LAST>
__device__ __forceinline__ void pass4(float4* __restrict__ base,
                                      const float2* __restrict__ tw, float scale) {
    constexpr int L = 1 << (LG1 + LG2);
    constexpr int ITEMS = L << (LOGN - 2);
    constexpr int h = 1 << S;
    for (int u = threadIdx.x; u < ITEMS; u += NTT) {
        const int line = u & (L - 1);
        const int loff = (line & ((1 << LG1) - 1)) * SL1 + (line >> LG1) * SL2;
        const int v = u >> (LG1 + LG2);
        const int t = v & (h - 1);
        const int p = ((v >> S) << (S + 2)) + t;
        float4* e = base + loff + p * SP;
        float4 a = e[0], b = e[h * SP], c = e[2 * h * SP], d = e[3 * h * SP];
        const float2 w0 = tw[t << (5 - S)];
        const float2 w1 = make_float2(w0.y, -w0.x);
        const float2 w2 = csq(w0);
        if constexpr (!INV) {
            float4 ac = f4add(a, c), bd = f4add(b, d);
            float4 cP = c4mul(f4sub(a, c), w0);
            float4 dP = c4mul(f4sub(b, d), w1);
            e[0]          = f4add(ac, bd);
            e[h * SP]     = c4mul(f4sub(ac, bd), w2);
            e[2 * h * SP] = f4add(cP, dP);
            e[3 * h * SP] = c4mul(f4sub(cP, dP), w2);
        } else {
            float4 bw = c4mulc(b, w2), dw = c4mulc(d, w2);
            float4 aP = f4add(a, bw), bP = f4sub(a, bw);
            float4 cP = f4add(c, dw), dP = f4sub(c, dw);
            float4 cw = c4mulc(cP, w0), dq = c4mulc(dP, w1);
            float4 o0 = f4add(aP, cw), o2 = f4sub(aP, cw);
            float4 o1 = f4add(bP, dq), o3 = f4sub(bP, dq);
            if constexpr (LAST) {
                o0 = f4sc(o0, scale); o1 = f4sc(o1, scale);
                o2 = f4sc(o2, scale); o3 = f4sc(o3, scale);
            }
            e[0] = o0; e[h * SP] = o1; e[2 * h * SP] = o2; e[3 * h * SP] = o3;
        }
    }
    __syncthreads();
}

template<bool INV, int NTT, int SP, int SL1, int LG1, int SL2, int LG2, int LOGN, int S, bool LAST>
__device__ __forceinline__ void pass2(float4* __restrict__ base,
                                      const float2* __restrict__ tw, float scale) {
    constexpr int L = 1 << (LG1 + LG2);
    constexpr int ITEMS = L << (LOGN - 1);
    constexpr int h = 1 << S;
    for (int u = threadIdx.x; u < ITEMS; u += NTT) {
        const int line = u & (L - 1);
        const int loff = (line & ((1 << LG1) - 1)) * SL1 + (line >> LG1) * SL2;
        const int v = u >> (LG1 + LG2);
        const int t = v & (h - 1);
        const int p = ((v >> S) << (S + 1)) + t;
        float4* e = base + loff + p * SP;
        float4 a = e[0], b = e[h * SP];
        const float2 w = tw[t << (6 - S)];
        if constexpr (!INV) {
            e[0]      = f4add(a, b);
            e[h * SP] = c4mul(f4sub(a, b), w);
        } else {
            float4 bw = c4mulc(b, w);
            float4 o0 = f4add(a, bw), o1 = f4sub(a, bw);
            if constexpr (LAST) { o0 = f4sc(o0, scale); o1 = f4sc(o1, scale); }
            e[0] = o0; e[h * SP] = o1;
        }
    }
    __syncthreads();
}

template<bool INV, int NTT, int SP, int SL1, int LG1, int SL2, int LG2, int LOGN>
__device__ __forceinline__ void fft_run(float4* __restrict__ base,
                                        const float2* __restrict__ tw, float scale) {
    if constexpr (!INV) {
        if constexpr (LOGN == 6) {
            pass4<false, NTT, SP, SL1, LG1, SL2, LG2, 6, 4, false>(base, tw, 1.f);
            pass4<false, NTT, SP, SL1, LG1, SL2, LG2, 6, 2, false>(base, tw, 1.f);
            pass4<false, NTT, SP, SL1, LG1, SL2, LG2, 6, 0, false>(base, tw, 1.f);
        } else {
            pass4<false, NTT, SP, SL1, LG1, SL2, LG2, 5, 3, false>(base, tw, 1.f);
            pass4<false, NTT, SP, SL1, LG1, SL2, LG2, 5, 1, false>(base, tw, 1.f);
            pass2<false, NTT, SP, SL1, LG1, SL2, LG2, 5, 0, false>(base, tw, 1.f);
        }
    } else {
        if constexpr (LOGN == 6) {
            pass4<true, NTT, SP, SL1, LG1, SL2, LG2, 6, 0, false>(base, tw, 1.f);
            pass4<true, NTT, SP, SL1, LG1, SL2, LG2, 6, 2, false>(base, tw, 1.f);
            pass4<true, NTT, SP, SL1, LG1, SL2, LG2, 6, 4, true >(base, tw, scale);
        } else {
            pass4<true, NTT, SP, SL1, LG1, SL2, LG2, 5, 0, false>(base, tw, 1.f);
            pass4<true, NTT, SP, SL1, LG1, SL2, LG2, 5, 2, false>(base, tw, 1.f);
            pass2<true, NTT, SP, SL1, LG1, SL2, LG2, 5, 4, true >(base, tw, scale);
        }
    }
}

// ---------------- float2 passes (p1 only: packed Hermitian plane) ----------------
template<int NTT, int SP, int LG1, int LOGN, int S>
__device__ __forceinline__ void pass4s(float2* __restrict__ base,
                                       const float2* __restrict__ tw) {
    constexpr int L = 1 << LG1;
    constexpr int ITEMS = L << (LOGN - 2);
    constexpr int h = 1 << S;
    for (int u = threadIdx.x; u < ITEMS; u += NTT) {
        const int loff = (u & (L - 1));
        const int v = u >> LG1;
        const int t = v & (h - 1);
        const int p = ((v >> S) << (S + 2)) + t;
        float2* e = base + loff + p * SP;
        float2 a = e[0], b = e[h * SP], c = e[2 * h * SP], d = e[3 * h * SP];
        const float2 w0 = tw[t << (5 - S)];
        const float2 w1 = make_float2(w0.y, -w0.x);
        const float2 w2 = csq(w0);
        float2 ac = f2add(a, c), bd = f2add(b, d);
        float2 cP = cmul(f2sub(a, c), w0);
        float2 dP = cmul(f2sub(b, d), w1);
        e[0]          = f2add(ac, bd);
        e[h * SP]     = cmul(f2sub(ac, bd), w2);
        e[2 * h * SP] = f2add(cP, dP);
        e[3 * h * SP] = cmul(f2sub(cP, dP), w2);
    }
    __syncthreads();
}
template<int NTT, int SP, int LG1, int LOGN, int S>
__device__ __forceinline__ void pass2s(float2* __restrict__ base,
                                       const float2* __restrict__ tw) {
    constexpr int L = 1 << LG1;
    constexpr int ITEMS = L << (LOGN - 1);
    constexpr int h = 1 << S;
    for (int u = threadIdx.x; u < ITEMS; u += NTT) {
        const int loff = (u & (L - 1));
        const int v = u >> LG1;
        const int t = v & (h - 1);
        const int p = ((v >> S) << (S + 1)) + t;
        float2* e = base + loff + p * SP;
        float2 a = e[0], b = e[h * SP];
        const float2 w = tw[t << (6 - S)];
        e[0]      = f2add(a, b);
        e[h * SP] = cmul(f2sub(a, b), w);
    }
    __syncthreads();
}

// ---------------- K0: precompute ----------------
__device__ __forceinline__ void writeU(float4* dst, float axf, float ayf, float azf) {
    double ax = axf, ay = ayf, az = azf;
    double r = sqrt(ax * ax + ay * ay + az * az + 1e-20);
    double cr = cos(r), sn = sin(r) / r;
    dst[0] = make_float4((float)cr, (float)(-az * sn), (float)(-ay * sn), (float)(-ax * sn));
    dst[1] = make_float4((float)(ay * sn), (float)(-ax * sn), (float)cr, (float)(az * sn));
}

__global__ void k0(const float* __restrict__ mux0, const float* __restrict__ mux1,
                   const float* __restrict__ mux2) {
    int idx = blockIdx.x * blockDim.x + threadIdx.x;   // 16384 threads
    if (idx < 64) {
        double ang = -2.0 * PI_D * (double)idx / 128.0;
        g_TW[idx] = make_float2((float)cos(ang), (float)sin(ang));
    }
    if (idx < 128) {
        int k = __brev((unsigned)idx) >> 25;
        g_NR[idx] = (int)(__brev((unsigned)((128 - k) & 127)) >> 25);
    }
    {   // U0: [kxb][kyb]
        int kxb = idx >> 7, kyb = idx & 127;
        int kx = __brev((unsigned)kxb) >> 25, ky = __brev((unsigned)kyb) >> 25;
        const float* c = mux0 + (kx * 128 + ky) * 3;
        writeU(&g_U0[idx * 2], c[0], c[1], c[2]);
    }
    {   // U1: TRANSPOSED [cx][cy][kyb][kxb]
        int cx = idx >> 13, cy = (idx >> 12) & 1, kxb = (idx >> 6) & 63, kyb = idx & 63;
        int kx = __brev((unsigned)kxb) >> 26, ky = __brev((unsigned)kyb) >> 26;
        const float* c = mux1 + (((cx * 2 + cy) * 64 + kx) * 64 + ky) * 3;
        int tidx = (cx << 13) + (cy << 12) + (kyb << 6) + kxb;
        writeU(&g_U1[tidx * 2], c[0], c[1], c[2]);
    }
    if (idx < 4096) {   // U2: TRANSPOSED [cx][cy][kyb][kxb]
        int cx = idx >> 11, cy = (idx >> 10) & 1, kxb = (idx >> 5) & 31, kyb = idx & 31;
        int kx = __brev((unsigned)kxb) >> 27, ky = __brev((unsigned)kyb) >> 27;
        const float* c = mux2 + (((cx * 2 + cy) * 32 + kx) * 32 + ky) * 3;
        int tidx = (cx << 11) + (cy << 10) + (kyb << 5) + kxb;
        writeU(&g_U2[tidx * 2], c[0], c[1], c[2]);
    }
}

// ---------------- P1: encode + y-FFT128 (Hermitian packed) ----------------
#define NT1 512
__global__ __launch_bounds__(NT1) void p1(const float* __restrict__ images) {
    __shared__ float2 z[128 * 33];
    __shared__ float2 tw[64];
    const int b = blockIdx.y, X0 = blockIdx.x * 32;
    for (int i = threadIdx.x; i < 64; i += NT1) tw[i] = g_TW[i];
    for (int idx = threadIdx.x; idx < 4096; idx += NT1) {
        int l = idx >> 7, y = idx & 127;
        float I = images[(b * 128 + X0 + l) * 128 + y];
        float sv, cv;
        sincosf(0.5f * (float)PI_D * I, &sv, &cv);
        z[y * 33 + l] = make_float2(cv * (1.0f / 128.0f), sv * (1.0f / 128.0f));
    }
    __syncthreads();
    pass4s<NT1, 33, 5, 7, 5>(z, tw);
    pass4s<NT1, 33, 5, 7, 3>(z, tw);
    pass4s<NT1, 33, 5, 7, 1>(z, tw);
    pass2s<NT1, 33, 5, 7, 0>(z, tw);
    for (int idx = threadIdx.x; idx < 4096; idx += NT1) {
        int l = idx >> 7, kb = idx & 127;
        float2 Z = z[kb * 33 + l];
        float2 Zn = z[g_NR[kb] * 33 + l];
        float2 C  = make_float2(0.5f * (Z.x + Zn.x), 0.5f * (Z.y - Zn.y));
        float2 Sf = make_float2(0.5f * (Z.y + Zn.y), 0.5f * (Zn.x - Z.x));
        int X = X0 + l;
        g_S4[(b * 128 + X) * 128 + kb] = make_float4(C.x, C.y, Sf.x, Sf.y);
    }
}

// ---------------- P2: x-FFT128 + mux0 + x-IFFT128 + x-FFT64(halves) ----------------
#define NT2 512
__global__ __launch_bounds__(NT2) void p2() {
    __shared__ float4 tile[128 * 16];
    __shared__ float2 tw[64];
    const int b = blockIdx.y, y0 = blockIdx.x * 16;
    for (int i = threadIdx.x; i < 64; i += NT2) tw[i] = g_TW[i];
    __syncthreads();
    // fused: fwd7 pass4 S=5 reading directly from global
    for (int u = threadIdx.x; u < 512; u += NT2) {
        int yl = u & 15, v = u >> 4;                 // v in [0,32) = position
        const float4* g = &g_S4[(b * 128 + v) * 128 + y0 + yl];
        float4 a = g[0], bb = g[32 * 128], c = g[64 * 128], d = g[96 * 128];
        const float2 w0 = tw[v];
        const float2 w1 = make_float2(w0.y, -w0.x);
        const float2 w2 = csq(w0);
        float4 ac = f4add(a, c), bd = f4add(bb, d);
        float4 cP = c4mul(f4sub(a, c), w0);
        float4 dP = c4mul(f4sub(bb, d), w1);
        float4* e = tile + v * 16 + yl;
        e[0]       = f4add(ac, bd);
        e[32 * 16] = c4mul(f4sub(ac, bd), w2);
        e[64 * 16] = f4add(cP, dP);
        e[96 * 16] = c4mul(f4sub(cP, dP), w2);
    }
    __syncthreads();
    pass4<false, NT2, 16, 1, 4, 0, 0, 7, 3, false>(tile, tw, 1.f);
    pass4<false, NT2, 16, 1, 4, 0, 0, 7, 1, false>(tile, tw, 1.f);
    // fused: fwd7 pass2 S=0 (w=1) + mux0
    for (int u = threadIdx.x; u < 1024; u += NT2) {
        int yl = u & 15, v = u >> 4;                 // v in [0,64)
        float4* e = tile + (2 * v) * 16 + yl;
        float4 a = e[0], bb = e[16];
        float4 o0 = f4add(a, bb), o1 = f4sub(a, bb);
        int i0 = (((2 * v) << 7) + y0 + yl) * 2;
        int i1 = (((2 * v + 1) << 7) + y0 + yl) * 2;
        e[0]  = mux4(o0, g_U0[i0], g_U0[i0 + 1]);
        e[16] = mux4(o1, g_U0[i1], g_U0[i1 + 1]);
    }
    __syncthreads();
    // inv128 S=0,2,4
    pass4<true, NT2, 16, 1, 4, 0, 0, 7, 0, false>(tile, tw, 1.f);
    pass4<true, NT2, 16, 1, 4, 0, 0, 7, 2, false>(tile, tw, 1.f);
    pass4<true, NT2, 16, 1, 4, 0, 0, 7, 4, false>(tile, tw, 1.f);
    // FUSION D: inv128 pass2 S=6 (scale 1/128) + fwd64 pass4 S=4
    for (int u = threadIdx.x; u < 256; u += NT2) {
        int yl = u & 15, t = u >> 4;                 // t in [0,16)
        float4* e = tile + yl;
        float4 p0[4], p1[4];
        #pragma unroll
        for (int k = 0; k < 4; ++k) {
            float4 a = e[(t + 16 * k) * 16], bq = e[(t + 64 + 16 * k) * 16];
            float4 bw = c4mulc(bq, tw[t + 16 * k]);
            p0[k] = f4sc(f4add(a, bw), 1.0f / 128.0f);
            p1[k] = f4sc(f4sub(a, bw), 1.0f / 128.0f);
        }
        const float2 wf = tw[2 * t];
        float4 r0, r1, r2, r3;
        fwd4q(p0[0], p0[1], p0[2], p0[3], wf, r0, r1, r2, r3);
        e[t * 16] = r0; e[(t + 16) * 16] = r1; e[(t + 32) * 16] = r2; e[(t + 48) * 16] = r3;
        fwd4q(p1[0], p1[1], p1[2], p1[3], wf, r0, r1, r2, r3);
        e[(t + 64) * 16] = r0; e[(t + 80) * 16] = r1; e[(t + 96) * 16] = r2; e[(t + 112) * 16] = r3;
    }
    __syncthreads();
    // fwd64 halves: S=2, then fused S=0 + global store
    pass4<false, NT2, 16, 1, 4, 1024, 1, 6, 2, false>(tile, tw, 1.f);
    for (int u = threadIdx.x; u < 512; u += NT2) {
        int yl = u & 15, half = (u >> 4) & 1, v = u >> 5;   // v in [0,16)
        float4* e = tile + half * 1024 + (4 * v) * 16 + yl;
        float4 a = e[0], bb = e[16], c = e[32], d = e[48];
        // t=0: w0=1, w1=-i, w2=1
        float4 ac = f4add(a, c), bd = f4add(bb, d);
        float4 cP = f4sub(a, c);
        float4 dP = c4mulnegi(f4sub(bb, d));
        int Xb = half * 64 + 4 * v;
        float4* g = &g_S4[(b * 128 + Xb) * 128 + y0 + yl];
        g[0]   = f4add(ac, bd);
        g[128] = f4sub(ac, bd);
        g[256] = f4add(cP, dP);
        g[384] = f4sub(cP, dP);
    }
}

// ---------------- P35 ----------------
#define NT3 1024
#define P35_SMEM (132096 + 512 + 16896 + 1280)
__global__ __launch_bounds__(NT3) void p35(const float* __restrict__ W) {
    extern __shared__ char sm[];
    float4* tile = (float4*)sm;                            // [64 X][129] float4
    float2* tw   = (float2*)(sm + 132096);
    float*  prob = (float*)(sm + 132096 + 512);            // [2 f][64 X][33 pitch] partials
    float*  red  = (float*)(sm + 132096 + 512 + 16896);    // 32*10 f32
    const int b = blockIdx.y, xc1 = blockIdx.x;
    for (int i = threadIdx.x; i < 64; i += NT3) tw[i] = g_TW[i];
    __syncthreads();
    // fused: inv7-y pass4 S=0 reading directly from global (t=0: w0=1, w1conj=+i, w2=1)
    for (int u = threadIdx.x; u < 2048; u += NT3) {
        int X = u & 63, v = u >> 6;                        // v in [0,32)
        const float4* g = &g_S4[(b * 128 + xc1 * 64 + X) * 128 + 4 * v];
        float4 a = g[0], bb = g[1], c = g[2], d = g[3];
        float4 aP = f4add(a, bb), bP = f4sub(a, bb);
        float4 cP = f4add(c, d);
        float4 dq = c4mulposi(f4sub(c, d));
        float4* e = tile + X * 129 + 4 * v;
        e[0] = f4add(aP, cP);
        e[2] = f4sub(aP, cP);
        e[1] = f4add(bP, dq);
        e[3] = f4sub(bP, dq);
    }
    __syncthreads();
    pass4<true, NT3, 1, 129, 6, 0, 0, 7, 2, false>(tile, tw, 1.f);
    pass4<true, NT3, 1, 129, 6, 0, 0, 7, 4, false>(tile, tw, 1.f);
    // FUSION A: inv128-y pass2 S=6 (scale 1/128) + fwd64-y pass4 S=4
    for (int u = threadIdx.x; u < 1024; u += NT3) {
        int X = u & 63, t = u >> 6;                        // t in [0,16)
        float4* e = tile + X * 129;
        float4 p0[4], p1[4];
        #pragma unroll
        for (int k = 0; k < 4; ++k) {
            float4 a = e[t + 16 * k], bq = e[t + 64 + 16 * k];
            float4 bw = c4mulc(bq, tw[t + 16 * k]);
            p0[k] = f4sc(f4add(a, bw), 1.0f / 128.0f);
            p1[k] = f4sc(f4sub(a, bw), 1.0f / 128.0f);
        }
        const float2 wf = tw[2 * t];
        float4 r0, r1, r2, r3;
        fwd4q(p0[0], p0[1], p0[2], p0[3], wf, r0, r1, r2, r3);
        e[t] = r0; e[t + 16] = r1; e[t + 32] = r2; e[t + 48] = r3;
        fwd4q(p1[0], p1[1], p1[2], p1[3], wf, r0, r1, r2, r3);
        e[t + 64] = r0; e[t + 80] = r1; e[t + 96] = r2; e[t + 112] = r3;
    }
    __syncthreads();
    // fwd64 y halves: S=2, fused S=0 + mux1
    pass4<false, NT3, 1, 129, 6, 64, 1, 6, 2, false>(tile, tw, 1.f);
    for (int u = threadIdx.x; u < 2048; u += NT3) {
        int X = u & 63, half = (u >> 6) & 1, v = u >> 7;   // v in [0,16)
        float4* e = tile + X * 129 + half * 64 + 4 * v;
        float4 a = e[0], bb = e[1], c = e[2], d = e[3];
        float4 ac = f4add(a, c), bd = f4add(bb, d);
        float4 cP = f4sub(a, c);
        float4 dP = c4mulnegi(f4sub(bb, d));
        float4 o0 = f4add(ac, bd), o1 = f4sub(ac, bd);
        float4 o2 = f4add(cP, dP), o3 = f4sub(cP, dP);
        int ub = (((xc1 * 2 + half) << 12) + ((4 * v) << 6) + X) * 2;
        e[0] = mux4(o0, g_U1[ub],       g_U1[ub + 1]);
        e[1] = mux4(o1, g_U1[ub + 128], g_U1[ub + 129]);
        e[2] = mux4(o2, g_U1[ub + 256], g_U1[ub + 257]);
        e[3] = mux4(o3, g_U1[ub + 384], g_U1[ub + 385]);
    }
    __syncthreads();
    // x junction 64->32: inv64 S=0, S=2, FUSION B (inv S=4 + fwd32 S=3), fwd32 S=1, pass2 S=0
    pass4<true, NT3, 129, 1, 7, 0, 0, 6, 0, false>(tile, tw, 1.f);
    pass4<true, NT3, 129, 1, 7, 0, 0, 6, 2, false>(tile, tw, 1.f);
    for (int u = threadIdx.x; u < 1024; u += NT3) {
        int y = u & 127, t = u >> 7;                       // t in [0,8)
        float4* e = tile + y;
        float4 q0 = e[t * 129],        q1 = e[(t + 8) * 129];
        float4 q2 = e[(t + 16) * 129], q3 = e[(t + 24) * 129];
        float4 q4 = e[(t + 32) * 129], q5 = e[(t + 40) * 129];
        float4 q6 = e[(t + 48) * 129], q7 = e[(t + 56) * 129];
        float4 A0, A1, A2, A3, B0, B1, B2, B3;
        inv4q(q0, q2, q4, q6, tw[2 * t],      1.0f / 64.0f, A0, A1, A2, A3);
        inv4q(q1, q3, q5, q7, tw[2 * t + 16], 1.0f / 64.0f, B0, B1, B2, B3);
        const float2 wf = tw[4 * t];
        float4 r0, r1, r2, r3;
        fwd4q(A0, B0, A1, B1, wf, r0, r1, r2, r3);
        e[t * 129] = r0; e[(t + 8) * 129] = r1; e[(t + 16) * 129] = r2; e[(t + 24) * 129] = r3;
        fwd4q(A2, B2, A3, B3, wf, r0, r1, r2, r3);
        e[(t + 32) * 129] = r0; e[(t + 40) * 129] = r1; e[(t + 48) * 129] = r2; e[(t + 56) * 129] = r3;
    }
    __syncthreads();
    pass4<false, NT3, 129, 1, 7, 4128, 1, 5, 1, false>(tile, tw, 1.f);
    pass2<false, NT3, 129, 1, 7, 4128, 1, 5, 0, false>(tile, tw, 1.f);
    // y junction 64->32: inv64 S=0, S=2, FUSION C (inv S=4 + fwd32 S=3), fwd32 S=1, fused S=0+mux2
    pass4<true, NT3, 1, 129, 6, 64, 1, 6, 0, false>(tile, tw, 1.f);
    pass4<true, NT3, 1, 129, 6, 64, 1, 6, 2, false>(tile, tw, 1.f);
    for (int u = threadIdx.x; u < 1024; u += NT3) {
        int X = u & 63, half = (u >> 6) & 1, t = u >> 7;   // t in [0,8)
        float4* e = tile + X * 129 + half * 64;
        float4 q0 = e[t],      q1 = e[t + 8],  q2 = e[t + 16], q3 = e[t + 24];
        float4 q4 = e[t + 32], q5 = e[t + 40], q6 = e[t + 48], q7 = e[t + 56];
        float4 A0, A1, A2, A3, B0, B1, B2, B3;
        inv4q(q0, q2, q4, q6, tw[2 * t],      1.0f / 64.0f, A0, A1, A2, A3);
        inv4q(q1, q3, q5, q7, tw[2 * t + 16], 1.0f / 64.0f, B0, B1, B2, B3);
        const float2 wf = tw[4 * t];
        float4 r0, r1, r2, r3;
        fwd4q(A0, B0, A1, B1, wf, r0, r1, r2, r3);
        e[t] = r0; e[t + 8] = r1; e[t + 16] = r2; e[t + 24] = r3;
        fwd4q(A2, B2, A3, B3, wf, r0, r1, r2, r3);
        e[t + 32] = r0; e[t + 40] = r1; e[t + 48] = r2; e[t + 56] = r3;
    }
    __syncthreads();
    pass4<false, NT3, 1, 129, 6, 32, 2, 5, 1, false>(tile, tw, 1.f);
    for (int u = threadIdx.x; u < 4096; u += NT3) {
        int X = u & 63, seg = (u >> 6) & 3, v = u >> 8;    // v in [0,16)
        float4* e = tile + X * 129 + seg * 32 + 2 * v;
        float4 a = e[0], bb = e[1];
        float4 o0 = f4add(a, bb), o1 = f4sub(a, bb);       // w=1
        int xc2 = X >> 5, yc2 = seg & 1;
        int ub = (((xc2 * 2 + yc2) << 10) + ((2 * v) << 5) + (X & 31)) * 2;
        e[0] = mux4(o0, g_U2[ub],      g_U2[ub + 1]);
        e[1] = mux4(o1, g_U2[ub + 64], g_U2[ub + 65]);
    }
    __syncthreads();
    // final x inv32
    fft_run<true, NT3, 129, 1, 7, 4128, 1, 5>(tile, tw, 1.0f / 32.0f);
    // final y inv32: pass4 S=0, pass4 S=2, FUSED last pass (S=4) + measurement
    pass4<true, NT3, 1, 129, 6, 32, 2, 5, 0, false>(tile, tw, 1.f);
    pass4<true, NT3, 1, 129, 6, 32, 2, 5, 2, false>(tile, tw, 1.f);
    for (int u = threadIdx.x; u < 1024; u += NT3) {
        int X = u & 63, t = u >> 6;                        // t in [0,16)
        const float2 w = tw[t << 2];
        float s0a = 0.f, s1a = 0.f, s0b = 0.f, s1b = 0.f;
        #pragma unroll
        for (int seg = 0; seg < 4; ++seg) {
            const float4* e = tile + X * 129 + seg * 32 + t;
            float4 a = e[0], bb = e[16];
            float4 bw = c4mulc(bb, w);
            float4 o0 = f4add(a, bw), o1 = f4sub(a, bw);
            s0a += o0.x * o0.x + o0.y * o0.y;  s1a += o0.z * o0.z + o0.w * o0.w;
            s0b += o1.x * o1.x + o1.y * o1.y;  s1b += o1.z * o1.z + o1.w * o1.w;
        }
        const float sc2 = (1.0f / 32.0f) * (1.0f / 32.0f);
        // prob layout [f][X][pitch 33], ya index: stores lanes X-fastest stride 33 -> conflict-free
        prob[X * 33 + t]               = s0a * sc2;
        prob[2112 + X * 33 + t]        = s1a * sc2;
        prob[X * 33 + t + 16]          = s0b * sc2;
        prob[2112 + X * 33 + t + 16]   = s1b * sc2;
    }
    __syncthreads();
    // partial GEMV: lanes ya-fastest stride 1 -> conflict-free
    float acc[10];
    #pragma unroll
    for (int c = 0; c < 10; ++c) acc[c] = 0.f;
    {
        int xa = threadIdx.x >> 5, ya = threadIdx.x & 31;
        float p0 = prob[xa * 33 + ya]        + prob[(xa + 32) * 33 + ya];
        float p1 = prob[2112 + xa * 33 + ya] + prob[2112 + (xa + 32) * 33 + ya];
        int j0 = threadIdx.x * 2;   // = (xa*32+ya)*2
        #pragma unroll
        for (int c = 0; c < 10; ++c) {
            float2 wv = *(const float2*)(W + c * 2048 + j0);
            acc[c] = fmaf(p0, wv.x, fmaf(p1, wv.y, acc[c]));
        }
    }
    #pragma unroll
    for (int c = 0; c < 10; ++c)
        #pragma unroll
        for (int o = 16; o > 0; o >>= 1)
            acc[c] += __shfl_down_sync(0xffffffffu, acc[c], o);
    const int warp = threadIdx.x >> 5, lane = threadIdx.x & 31;
    if (lane == 0)
        #pragma unroll
        for (int c = 0; c < 10; ++c) red[warp * 10 + c] = acc[c];
    __syncthreads();
    if (threadIdx.x < 10) {
        float s = 0.f;
        #pragma unroll
        for (int w = 0; w < 32; ++w) s += red[w * 10 + threadIdx.x];
        g_part[(b * 2 + xc1) * 10 + threadIdx.x] = s;
    }
}

// ---------------- combine ----------------
__global__ void pc(const float* __restrict__ bias, float* __restrict__ out) {
    int i = blockIdx.x * blockDim.x + threadIdx.x;
    if (i < 5120) {
        int b = i / 10, c = i % 10;
        out[i] = bias[c] + g_part[(b * 2) * 10 + c] + g_part[(b * 2 + 1) * 10 + c];
    }
}

// ---------------- launch ----------------
extern "C" void kernel_launch(void* const* d_in, const int* in_sizes, int n_in,
                              void* d_out, int out_size) {
    const float* images = (const float*)d_in[0];
    const float* mux0 = (const float*)d_in[1];
    const float* mux1 = (const float*)d_in[2];
    const float* mux2 = (const float*)d_in[3];
    const float* W = (const float*)d_in[4];
    const float* bias = (const float*)d_in[5];
    float* out = (float*)d_out;
    (void)in_sizes; (void)n_in; (void)out_size;

    cudaFuncSetAttribute(p35, cudaFuncAttributeMaxDynamicSharedMemorySize, P35_SMEM);

    k0<<<64, 256>>>(mux0, mux1, mux2);
    p1<<<dim3(4, 512), NT1>>>(images);
    p2<<<dim3(8, 512), NT2>>>();
    p35<<<dim3(2, 512), NT3, P35_SMEM>>>(W);
    pc<<<10, 512>>>(bias, out);
}

// round 14
// speedup vs baseline: 1.1350x; 1.0410x over previous
#include <cuda_runtime.h>
#include <math.h>

#define PI_D 3.14159265358979323846
#define SQH 0.70710678118654752440f

// ---------------- static device scratch ----------------
__device__ float4 g_S4[512 * 128 * 128];      // state [b][X][Y], float4 = (f0, f1) complex pair
__device__ float4 g_U0[128 * 128 * 2];        // mux0, bitrev-permuted, [kxb][kyb]
__device__ float4 g_U1[2 * 2 * 64 * 64 * 2];  // mux1, bitrev-permuted, TRANSPOSED [cx][cy][kyb][kxb]
__device__ float4 g_U2[2 * 2 * 32 * 32 * 2];  // mux2, bitrev-permuted, TRANSPOSED [cx][cy][kyb][kxb]
__device__ float2 g_TW[64];                   // exp(-2*pi*i*t/128)
__device__ int    g_NR[128];                  // bitrev-domain negation table
__device__ float  g_part[512 * 2 * 10];       // partial logits per (b, xc1)

// ---- float2 complex helpers ----
__device__ __forceinline__ float2 cmul(float2 a, float2 b) {
    return make_float2(a.x * b.x - a.y * b.y, a.x * b.y + a.y * b.x);
}
__device__ __forceinline__ float2 f2add(float2 a, float2 b) { return make_float2(a.x + b.x, a.y + b.y); }
__device__ __forceinline__ float2 f2sub(float2 a, float2 b) { return make_float2(a.x - b.x, a.y - b.y); }
__device__ __forceinline__ float2 csq(float2 a) { return make_float2(a.x * a.x - a.y * a.y, 2.f * a.x * a.y); }

// ---- float4 = two complex numbers, same twiddle applied to both ----
__device__ __forceinline__ float4 f4add(float4 a, float4 b) {
    return make_float4(a.x + b.x, a.y + b.y, a.z + b.z, a.w + b.w);
}
__device__ __forceinline__ float4 f4sub(float4 a, float4 b) {
    return make_float4(a.x - b.x, a.y - b.y, a.z - b.z, a.w - b.w);
}
__device__ __forceinline__ float4 f4sc(float4 a, float s) {
    return make_float4(a.x * s, a.y * s, a.z * s, a.w * s);
}
__device__ __forceinline__ float4 c4mul(float4 v, float2 w) {
    return make_float4(v.x * w.x - v.y * w.y, v.x * w.y + v.y * w.x,
                       v.z * w.x - v.w * w.y, v.z * w.y + v.w * w.x);
}
__device__ __forceinline__ float4 c4mulc(float4 v, float2 w) {
    return make_float4(v.x * w.x + v.y * w.y, v.y * w.x - v.x * w.y,
                       v.z * w.x + v.w * w.y, v.w * w.x - v.z * w.y);
}
__device__ __forceinline__ float4 c4mulnegi(float4 v) {  // *( -i )
    return make_float4(v.y, -v.x, v.w, -v.z);
}
__device__ __forceinline__ float4 c4mulposi(float4 v) {  // *( +i )
    return make_float4(-v.y, v.x, -v.w, v.z);
}
// mux on one float4 site: q0=(x,y), q1=(z,w)
__device__ __forceinline__ float4 mux4(float4 v, float4 uA, float4 uB) {
    float4 o;
    o.x = uA.x * v.x - uA.y * v.y + uA.z * v.z - uA.w * v.w;
    o.y = uA.x * v.y + uA.y * v.x + uA.z * v.w + uA.w * v.z;
    o.z = uB.x * v.x - uB.y * v.y + uB.z * v.z - uB.w * v.w;
    o.w = uB.x * v.y + uB.y * v.x + uB.z * v.w + uB.w * v.z;
    return o;
}

// ---- register-level butterflies (exact template math) ----
__device__ __forceinline__ void inv4q(float4 a, float4 b, float4 c, float4 d,
                                      float2 w0, float s,
                                      float4& o0, float4& o1, float4& o2, float4& o3) {
    float2 w1 = make_float2(w0.y, -w0.x);
    float2 w2 = csq(w0);
    float4 bw = c4mulc(b, w2), dw = c4mulc(d, w2);
    float4 aP = f4add(a, bw), bP = f4sub(a, bw);
    float4 cP = f4add(c, dw), dP = f4sub(c, dw);
    float4 cw = c4mulc(cP, w0), dq = c4mulc(dP, w1);
    o0 = f4sc(f4add(aP, cw), s); o2 = f4sc(f4sub(aP, cw), s);
    o1 = f4sc(f4add(bP, dq), s); o3 = f4sc(f4sub(bP, dq), s);
}
__device__ __forceinline__ void fwd4q(float4 a, float4 b, float4 c, float4 d,
                                      float2 w0,
                                      float4& o0, float4& o1, float4& o2, float4& o3) {
    float2 w1 = make_float2(w0.y, -w0.x);
    float2 w2 = csq(w0);
    float4 ac = f4add(a, c), bd = f4add(b, d);
    float4 cP = c4mul(f4sub(a, c), w0);
    float4 dP = c4mul(f4sub(b, d), w1);
    o0 = f4add(ac, bd);
    o1 = c4mul(f4sub(ac, bd), w2);
    o2 = f4add(cP, dP);
    o3 = c4mul(f4sub(cP, dP), w2);
}
// full 8-point DIF (stages h=4,2,1 of a 32/64-FFT within an 8-block; natural->bitrev in-block)
__device__ __forceinline__ void fwd8q(float4* z) {
    const float2 tw16c = make_float2(SQH, -SQH);    // tw[16] = e^{-i pi/4}
    const float2 tw48c = make_float2(-SQH, -SQH);   // tw[48] = e^{-3i pi/4}
    float4 s0 = f4add(z[0], z[4]), s1 = f4add(z[1], z[5]);
    float4 s2 = f4add(z[2], z[6]), s3 = f4add(z[3], z[7]);
    float4 t0 = f4sub(z[0], z[4]);
    float4 t1 = c4mul(f4sub(z[1], z[5]), tw16c);
    float4 t2 = c4mulnegi(f4sub(z[2], z[6]));
    float4 t3 = c4mul(f4sub(z[3], z[7]), tw48c);
    float4 m0 = f4add(s0, s2), m2 = f4sub(s0, s2);
    float4 m1 = f4add(s1, s3), m3 = c4mulnegi(f4sub(s1, s3));
    z[0] = f4add(m0, m1); z[1] = f4sub(m0, m1);
    z[2] = f4add(m2, m3); z[3] = f4sub(m2, m3);
    float4 n0 = f4add(t0, t2), n2 = f4sub(t0, t2);
    float4 n1 = f4add(t1, t3), n3 = c4mulnegi(f4sub(t1, t3));
    z[4] = f4add(n0, n1); z[5] = f4sub(n0, n1);
    z[6] = f4add(n2, n3); z[7] = f4sub(n2, n3);
}

// =====================================================================
// float4 FFT passes. element (line, p) at base[(line&(2^LG1-1))*SL1 + (line>>LG1)*SL2 + p*SP]
// FWD: DIF natural->bitrev; INV: DIT bitrev->natural (conj twiddles), scale on LAST.
// =====================================================================
template<bool INV, int NTT, int SP, int SL1, int LG1, int SL2, int LG2, int LOGN, int S, bool LAST>
__device__ __forceinline__ void pass4(float4* __restrict__ base,
                                      const float2* __restrict__ tw, float scale) {
    constexpr int L = 1 << (LG1 + LG2);
    constexpr int ITEMS = L << (LOGN - 2);
    constexpr int h = 1 << S;
    for (int u = threadIdx.x; u < ITEMS; u += NTT) {
        const int line = u & (L - 1);
        const int loff = (line & ((1 << LG1) - 1)) * SL1 + (line >> LG1) * SL2;
        const int v = u >> (LG1 + LG2);
        const int t = v & (h - 1);
        const int p = ((v >> S) << (S + 2)) + t;
        float4* e = base + loff + p * SP;
        float4 a = e[0], b = e[h * SP], c = e[2 * h * SP], d = e[3 * h * SP];
        const float2 w0 = tw[t << (5 - S)];
        const float2 w1 = make_float2(w0.y, -w0.x);
        const float2 w2 = csq(w0);
        if constexpr (!INV) {
            float4 ac = f4add(a, c), bd = f4add(b, d);
            float4 cP = c4mul(f4sub(a, c), w0);
            float4 dP = c4mul(f4sub(b, d), w1);
            e[0]          = f4add(ac, bd);
            e[h * SP]     = c4mul(f4sub(ac, bd), w2);
            e[2 * h * SP] = f4add(cP, dP);
            e[3 * h * SP] = c4mul(f4sub(cP, dP), w2);
        } else {
            float4 bw = c4mulc(b, w2), dw = c4mulc(d, w2);
            float4 aP = f4add(a, bw), bP = f4sub(a, bw);
            float4 cP = f4add(c, dw), dP = f4sub(c, dw);
            float4 cw = c4mulc(cP, w0), dq = c4mulc(dP, w1);
            float4 o0 = f4add(aP, cw), o2 = f4sub(aP, cw);
            float4 o1 = f4add(bP, dq), o3 = f4sub(bP, dq);
            if constexpr (LAST) {
                o0 = f4sc(o0, scale); o1 = f4sc(o1, scale);
                o2 = f4sc(o2, scale); o3 = f4sc(o3, scale);
            }
            e[0] = o0; e[h * SP] = o1; e[2 * h * SP] = o2; e[3 * h * SP] = o3;
        }
    }
    __syncthreads();
}

template<bool INV, int NTT, int SP, int SL1, int LG1, int SL2, int LG2, int LOGN, int S, bool LAST>
__device__ __forceinline__ void pass2(float4* __restrict__ base,
                                      const float2* __restrict__ tw, float scale) {
    constexpr int L = 1 << (LG1 + LG2);
    constexpr int ITEMS = L << (LOGN - 1);
    constexpr int h = 1 << S;
    for (int u = threadIdx.x; u < ITEMS; u += NTT) {
        const int line = u & (L - 1);
        const int loff = (line & ((1 << LG1) - 1)) * SL1 + (line >> LG1) * SL2;
        const int v = u >> (LG1 + LG2);
        const int t = v & (h - 1);
        const int p = ((v >> S) << (S + 1)) + t;
        float4* e = base + loff + p * SP;
        float4 a = e[0], b = e[h * SP];
        const float2 w = tw[t << (6 - S)];
        if constexpr (!INV) {
            e[0]      = f4add(a, b);
            e[h * SP] = c4mul(f4sub(a, b), w);
        } else {
            float4 bw = c4mulc(b, w);
            float4 o0 = f4add(a, bw), o1 = f4sub(a, bw);
            if constexpr (LAST) { o0 = f4sc(o0, scale); o1 = f4sc(o1, scale); }
            e[0] = o0; e[h * SP] = o1;
        }
    }
    __syncthreads();
}

// ---------------- float2 passes (p1 only: packed Hermitian plane) ----------------
template<int NTT, int SP, int LG1, int LOGN, int S>
__device__ __forceinline__ void pass4s(float2* __restrict__ base,
                                       const float2* __restrict__ tw) {
    constexpr int L = 1 << LG1;
    constexpr int ITEMS = L << (LOGN - 2);
    constexpr int h = 1 << S;
    for (int u = threadIdx.x; u < ITEMS; u += NTT) {
        const int loff = (u & (L - 1));
        const int v = u >> LG1;
        const int t = v & (h - 1);
        const int p = ((v >> S) << (S + 2)) + t;
        float2* e = base + loff + p * SP;
        float2 a = e[0], b = e[h * SP], c = e[2 * h * SP], d = e[3 * h * SP];
        const float2 w0 = tw[t << (5 - S)];
        const float2 w1 = make_float2(w0.y, -w0.x);
        const float2 w2 = csq(w0);
        float2 ac = f2add(a, c), bd = f2add(b, d);
        float2 cP = cmul(f2sub(a, c), w0);
        float2 dP = cmul(f2sub(b, d), w1);
        e[0]          = f2add(ac, bd);
        e[h * SP]     = cmul(f2sub(ac, bd), w2);
        e[2 * h * SP] = f2add(cP, dP);
        e[3 * h * SP] = cmul(f2sub(cP, dP), w2);
    }
    __syncthreads();
}
template<int NTT, int SP, int LG1, int LOGN, int S>
__device__ __forceinline__ void pass2s(float2* __restrict__ base,
                                       const float2* __restrict__ tw) {
    constexpr int L = 1 << LG1;
    constexpr int ITEMS = L << (LOGN - 1);
    constexpr int h = 1 << S;
    for (int u = threadIdx.x; u < ITEMS; u += NTT) {
        const int loff = (u & (L - 1));
        const int v = u >> LG1;
        const int t = v & (h - 1);
        const int p = ((v >> S) << (S + 1)) + t;
        float2* e = base + loff + p * SP;
        float2 a = e[0], b = e[h * SP];
        const float2 w = tw[t << (6 - S)];
        e[0]      = f2add(a, b);
        e[h * SP] = cmul(f2sub(a, b), w);
    }
    __syncthreads();
}

// ---------------- K0: precompute ----------------
__device__ __forceinline__ void writeU(float4* dst, float axf, float ayf, float azf) {
    double ax = axf, ay = ayf, az = azf;
    double r = sqrt(ax * ax + ay * ay + az * az + 1e-20);
    double cr = cos(r), sn = sin(r) / r;
    dst[0] = make_float4((float)cr, (float)(-az * sn), (float)(-ay * sn), (float)(-ax * sn));
    dst[1] = make_float4((float)(ay * sn), (float)(-ax * sn), (float)cr, (float)(az * sn));
}

__global__ void k0(const float* __restrict__ mux0, const float* __restrict__ mux1,
                   const float* __restrict__ mux2) {
    int idx = blockIdx.x * blockDim.x + threadIdx.x;   // 16384 threads
    if (idx < 64) {
        double ang = -2.0 * PI_D * (double)idx / 128.0;
        g_TW[idx] = make_float2((float)cos(ang), (float)sin(ang));
    }
    if (idx < 128) {
        int k = __brev((unsigned)idx) >> 25;
        g_NR[idx] = (int)(__brev((unsigned)((128 - k) & 127)) >> 25);
    }
    {   // U0: [kxb][kyb]
        int kxb = idx >> 7, kyb = idx & 127;
        int kx = __brev((unsigned)kxb) >> 25, ky = __brev((unsigned)kyb) >> 25;
        const float* c = mux0 + (kx * 128 + ky) * 3;
        writeU(&g_U0[idx * 2], c[0], c[1], c[2]);
    }
    {   // U1: TRANSPOSED [cx][cy][kyb][kxb]
        int cx = idx >> 13, cy = (idx >> 12) & 1, kxb = (idx >> 6) & 63, kyb = idx & 63;
        int kx = __brev((unsigned)kxb) >> 26, ky = __brev((unsigned)kyb) >> 26;
        const float* c = mux1 + (((cx * 2 + cy) * 64 + kx) * 64 + ky) * 3;
        int tidx = (cx << 13) + (cy << 12) + (kyb << 6) + kxb;
        writeU(&g_U1[tidx * 2], c[0], c[1], c[2]);
    }
    if (idx < 4096) {   // U2: TRANSPOSED [cx][cy][kyb][kxb]
        int cx = idx >> 11, cy = (idx >> 10) & 1, kxb = (idx >> 5) & 31, kyb = idx & 31;
        int kx = __brev((unsigned)kxb) >> 27, ky = __brev((unsigned)kyb) >> 27;
        const float* c = mux2 + (((cx * 2 + cy) * 32 + kx) * 32 + ky) * 3;
        int tidx = (cx << 11) + (cy << 10) + (kyb << 5) + kxb;
        writeU(&g_U2[tidx * 2], c[0], c[1], c[2]);
    }
}

// ---------------- P1: encode + y-FFT128 (Hermitian packed) ----------------
#define NT1 512
__global__ __launch_bounds__(NT1) void p1(const float* __restrict__ images) {
    __shared__ float2 z[128 * 33];
    __shared__ float2 tw[64];
    const int b = blockIdx.y, X0 = blockIdx.x * 32;
    for (int i = threadIdx.x; i < 64; i += NT1) tw[i] = g_TW[i];
    for (int idx = threadIdx.x; idx < 4096; idx += NT1) {
        int l = idx >> 7, y = idx & 127;
        float I = images[(b * 128 + X0 + l) * 128 + y];
        float sv, cv;
        sincosf(0.5f * (float)PI_D * I, &sv, &cv);
        z[y * 33 + l] = make_float2(cv * (1.0f / 128.0f), sv * (1.0f / 128.0f));
    }
    __syncthreads();
    pass4s<NT1, 33, 5, 7, 5>(z, tw);
    pass4s<NT1, 33, 5, 7, 3>(z, tw);
    pass4s<NT1, 33, 5, 7, 1>(z, tw);
    pass2s<NT1, 33, 5, 7, 0>(z, tw);
    for (int idx = threadIdx.x; idx < 4096; idx += NT1) {
        int l = idx >> 7, kb = idx & 127;
        float2 Z = z[kb * 33 + l];
        float2 Zn = z[g_NR[kb] * 33 + l];
        float2 C  = make_float2(0.5f * (Z.x + Zn.x), 0.5f * (Z.y - Zn.y));
        float2 Sf = make_float2(0.5f * (Z.y + Zn.y), 0.5f * (Zn.x - Z.x));
        int X = X0 + l;
        g_S4[(b * 128 + X) * 128 + kb] = make_float4(C.x, C.y, Sf.x, Sf.y);
    }
}

// ---------------- P2: x-FFT128 + mux0 + x-IFFT128 + x-FFT64(halves) ----------------
#define NT2 512
__global__ __launch_bounds__(NT2) void p2() {
    __shared__ float4 tile[128 * 16];
    __shared__ float2 tw[64];
    const int b = blockIdx.y, y0 = blockIdx.x * 16;
    for (int i = threadIdx.x; i < 64; i += NT2) tw[i] = g_TW[i];
    __syncthreads();
    // fused: fwd7 pass4 S=5 reading directly from global
    for (int u = threadIdx.x; u < 512; u += NT2) {
        int yl = u & 15, v = u >> 4;                 // v in [0,32) = position
        const float4* g = &g_S4[(b * 128 + v) * 128 + y0 + yl];
        float4 a = g[0], bb = g[32 * 128], c = g[64 * 128], d = g[96 * 128];
        const float2 w0 = tw[v];
        const float2 w1 = make_float2(w0.y, -w0.x);
        const float2 w2 = csq(w0);
        float4 ac = f4add(a, c), bd = f4add(bb, d);
        float4 cP = c4mul(f4sub(a, c), w0);
        float4 dP = c4mul(f4sub(bb, d), w1);
        float4* e = tile + v * 16 + yl;
        e[0]       = f4add(ac, bd);
        e[32 * 16] = c4mul(f4sub(ac, bd), w2);
        e[64 * 16] = f4add(cP, dP);
        e[96 * 16] = c4mul(f4sub(cP, dP), w2);
    }
    __syncthreads();
    pass4<false, NT2, 16, 1, 4, 0, 0, 7, 3, false>(tile, tw, 1.f);
    pass4<false, NT2, 16, 1, 4, 0, 0, 7, 1, false>(tile, tw, 1.f);
    // fused: fwd7 pass2 S=0 (w=1) + mux0
    for (int u = threadIdx.x; u < 1024; u += NT2) {
        int yl = u & 15, v = u >> 4;                 // v in [0,64)
        float4* e = tile + (2 * v) * 16 + yl;
        float4 a = e[0], bb = e[16];
        float4 o0 = f4add(a, bb), o1 = f4sub(a, bb);
        int i0 = (((2 * v) << 7) + y0 + yl) * 2;
        int i1 = (((2 * v + 1) << 7) + y0 + yl) * 2;
        e[0]  = mux4(o0, g_U0[i0], g_U0[i0 + 1]);
        e[16] = mux4(o1, g_U0[i1], g_U0[i1 + 1]);
    }
    __syncthreads();
    // inv128 S=0,2,4
    pass4<true, NT2, 16, 1, 4, 0, 0, 7, 0, false>(tile, tw, 1.f);
    pass4<true, NT2, 16, 1, 4, 0, 0, 7, 2, false>(tile, tw, 1.f);
    pass4<true, NT2, 16, 1, 4, 0, 0, 7, 4, false>(tile, tw, 1.f);
    // FUSION D: inv128 pass2 S=6 (scale 1/128) + fwd64 pass4 S=4
    for (int u = threadIdx.x; u < 256; u += NT2) {
        int yl = u & 15, t = u >> 4;                 // t in [0,16)
        float4* e = tile + yl;
        float4 p0[4], p1[4];
        #pragma unroll
        for (int k = 0; k < 4; ++k) {
            float4 a = e[(t + 16 * k) * 16], bq = e[(t + 64 + 16 * k) * 16];
            float4 bw = c4mulc(bq, tw[t + 16 * k]);
            p0[k] = f4sc(f4add(a, bw), 1.0f / 128.0f);
            p1[k] = f4sc(f4sub(a, bw), 1.0f / 128.0f);
        }
        const float2 wf = tw[2 * t];
        float4 r0, r1, r2, r3;
        fwd4q(p0[0], p0[1], p0[2], p0[3], wf, r0, r1, r2, r3);
        e[t * 16] = r0; e[(t + 16) * 16] = r1; e[(t + 32) * 16] = r2; e[(t + 48) * 16] = r3;
        fwd4q(p1[0], p1[1], p1[2], p1[3], wf, r0, r1, r2, r3);
        e[(t + 64) * 16] = r0; e[(t + 80) * 16] = r1; e[(t + 96) * 16] = r2; e[(t + 112) * 16] = r3;
    }
    __syncthreads();
    // fwd64 halves: S=2, then fused S=0 + global store
    pass4<false, NT2, 16, 1, 4, 1024, 1, 6, 2, false>(tile, tw, 1.f);
    for (int u = threadIdx.x; u < 512; u += NT2) {
        int yl = u & 15, half = (u >> 4) & 1, v = u >> 5;   // v in [0,16)
        float4* e = tile + half * 1024 + (4 * v) * 16 + yl;
        float4 a = e[0], bb = e[16], c = e[32], d = e[48];
        float4 ac = f4add(a, c), bd = f4add(bb, d);
        float4 cP = f4sub(a, c);
        float4 dP = c4mulnegi(f4sub(bb, d));
        int Xb = half * 64 + 4 * v;
        float4* g = &g_S4[(b * 128 + Xb) * 128 + y0 + yl];
        g[0]   = f4add(ac, bd);
        g[128] = f4sub(ac, bd);
        g[256] = f4add(cP, dP);
        g[384] = f4sub(cP, dP);
    }
}

// ---------------- P35 ----------------
#define NT3 1024
#define P35_SMEM (132096 + 512 + 16896 + 1280)
__global__ __launch_bounds__(NT3) void p35(const float* __restrict__ W) {
    extern __shared__ char sm[];
    float4* tile = (float4*)sm;                            // [64 X][129] float4
    float2* tw   = (float2*)(sm + 132096);
    float*  prob = (float*)(sm + 132096 + 512);            // [2 f][64 X][33 pitch]
    float*  red  = (float*)(sm + 132096 + 512 + 16896);    // 32*10 f32
    const int b = blockIdx.y, xc1 = blockIdx.x;
    for (int i = threadIdx.x; i < 64; i += NT3) tw[i] = g_TW[i];
    __syncthreads();
    // fused: inv7-y pass4 S=0 reading directly from global (t=0: w0=1, w1conj=+i, w2=1)
    for (int u = threadIdx.x; u < 2048; u += NT3) {
        int X = u & 63, v = u >> 6;                        // v in [0,32)
        const float4* g = &g_S4[(b * 128 + xc1 * 64 + X) * 128 + 4 * v];
        float4 a = g[0], bb = g[1], c = g[2], d = g[3];
        float4 aP = f4add(a, bb), bP = f4sub(a, bb);
        float4 cP = f4add(c, d);
        float4 dq = c4mulposi(f4sub(c, d));
        float4* e = tile + X * 129 + 4 * v;
        e[0] = f4add(aP, cP);
        e[2] = f4sub(aP, cP);
        e[1] = f4add(bP, dq);
        e[3] = f4sub(bP, dq);
    }
    __syncthreads();
    pass4<true, NT3, 1, 129, 6, 0, 0, 7, 2, false>(tile, tw, 1.f);
    pass4<true, NT3, 1, 129, 6, 0, 0, 7, 4, false>(tile, tw, 1.f);
    // FUSION A: inv128-y pass2 S=6 (scale 1/128) + fwd64-y pass4 S=4
    for (int u = threadIdx.x; u < 1024; u += NT3) {
        int X = u & 63, t = u >> 6;                        // t in [0,16)
        float4* e = tile + X * 129;
        float4 p0[4], p1[4];
        #pragma unroll
        for (int k = 0; k < 4; ++k) {
            float4 a = e[t + 16 * k], bq = e[t + 64 + 16 * k];
            float4 bw = c4mulc(bq, tw[t + 16 * k]);
            p0[k] = f4sc(f4add(a, bw), 1.0f / 128.0f);
            p1[k] = f4sc(f4sub(a, bw), 1.0f / 128.0f);
        }
        const float2 wf = tw[2 * t];
        float4 r0, r1, r2, r3;
        fwd4q(p0[0], p0[1], p0[2], p0[3], wf, r0, r1, r2, r3);
        e[t] = r0; e[t + 16] = r1; e[t + 32] = r2; e[t + 48] = r3;
        fwd4q(p1[0], p1[1], p1[2], p1[3], wf, r0, r1, r2, r3);
        e[t + 64] = r0; e[t + 80] = r1; e[t + 96] = r2; e[t + 112] = r3;
    }
    __syncthreads();
    // fwd64 y halves: S=2, fused S=0 + mux1
    pass4<false, NT3, 1, 129, 6, 64, 1, 6, 2, false>(tile, tw, 1.f);
    for (int u = threadIdx.x; u < 2048; u += NT3) {
        int X = u & 63, half = (u >> 6) & 1, v = u >> 7;   // v in [0,16)
        float4* e = tile + X * 129 + half * 64 + 4 * v;
        float4 a = e[0], bb = e[1], c = e[2], d = e[3];
        float4 ac = f4add(a, c), bd = f4add(bb, d);
        float4 cP = f4sub(a, c);
        float4 dP = c4mulnegi(f4sub(bb, d));
        float4 o0 = f4add(ac, bd), o1 = f4sub(ac, bd);
        float4 o2 = f4add(cP, dP), o3 = f4sub(cP, dP);
        int ub = (((xc1 * 2 + half) << 12) + ((4 * v) << 6) + X) * 2;
        e[0] = mux4(o0, g_U1[ub],       g_U1[ub + 1]);
        e[1] = mux4(o1, g_U1[ub + 128], g_U1[ub + 129]);
        e[2] = mux4(o2, g_U1[ub + 256], g_U1[ub + 257]);
        e[3] = mux4(o3, g_U1[ub + 384], g_U1[ub + 385]);
    }
    __syncthreads();
    // x junction 64->32: inv64 S=0, S=2, FUSION B (inv S=4 + fwd32 S=3), then MERGE P (fwd32 stages 2,1,0)
    pass4<true, NT3, 129, 1, 7, 0, 0, 6, 0, false>(tile, tw, 1.f);
    pass4<true, NT3, 129, 1, 7, 0, 0, 6, 2, false>(tile, tw, 1.f);
    for (int u = threadIdx.x; u < 1024; u += NT3) {
        int y = u & 127, t = u >> 7;                       // t in [0,8)
        float4* e = tile + y;
        float4 q0 = e[t * 129],        q1 = e[(t + 8) * 129];
        float4 q2 = e[(t + 16) * 129], q3 = e[(t + 24) * 129];
        float4 q4 = e[(t + 32) * 129], q5 = e[(t + 40) * 129];
        float4 q6 = e[(t + 48) * 129], q7 = e[(t + 56) * 129];
        float4 A0, A1, A2, A3, B0, B1, B2, B3;
        inv4q(q0, q2, q4, q6, tw[2 * t],      1.0f / 64.0f, A0, A1, A2, A3);
        inv4q(q1, q3, q5, q7, tw[2 * t + 16], 1.0f / 64.0f, B0, B1, B2, B3);
        const float2 wf = tw[4 * t];
        float4 r0, r1, r2, r3;
        fwd4q(A0, B0, A1, B1, wf, r0, r1, r2, r3);
        e[t * 129] = r0; e[(t + 8) * 129] = r1; e[(t + 16) * 129] = r2; e[(t + 24) * 129] = r3;
        fwd4q(A2, B2, A3, B3, wf, r0, r1, r2, r3);
        e[(t + 32) * 129] = r0; e[(t + 40) * 129] = r1; e[(t + 48) * 129] = r2; e[(t + 56) * 129] = r3;
    }
    __syncthreads();
    // MERGE P: fwd32-x stages 2,1,0 as 8-point DIF tail (lanes = y, stride 1 -> conflict-free)
    for (int u = threadIdx.x; u < 1024; u += NT3) {
        int y = u & 127, r = u >> 7;                       // r in [0,8)
        int m = r & 3, xs = r >> 2;
        float4* e = tile + (xs * 32 + 8 * m) * 129 + y;
        float4 z[8];
        #pragma unroll
        for (int j = 0; j < 8; ++j) z[j] = e[j * 129];
        fwd8q(z);
        #pragma unroll
        for (int j = 0; j < 8; ++j) e[j * 129] = z[j];
    }
    __syncthreads();
    // y junction 64->32: inv64 S=0, S=2, FUSION C (inv S=4 + fwd32 S=3), then MERGE Q (fwd32 stages 2,1,0 + mux2)
    pass4<true, NT3, 1, 129, 6, 64, 1, 6, 0, false>(tile, tw, 1.f);
    pass4<true, NT3, 1, 129, 6, 64, 1, 6, 2, false>(tile, tw, 1.f);
    for (int u = threadIdx.x; u < 1024; u += NT3) {
        int X = u & 63, half = (u >> 6) & 1, t = u >> 7;   // t in [0,8)
        float4* e = tile + X * 129 + half * 64;
        float4 q0 = e[t],      q1 = e[t + 8],  q2 = e[t + 16], q3 = e[t + 24];
        float4 q4 = e[t + 32], q5 = e[t + 40], q6 = e[t + 48], q7 = e[t + 56];
        float4 A0, A1, A2, A3, B0, B1, B2, B3;
        inv4q(q0, q2, q4, q6, tw[2 * t],      1.0f / 64.0f, A0, A1, A2, A3);
        inv4q(q1, q3, q5, q7, tw[2 * t + 16], 1.0f / 64.0f, B0, B1, B2, B3);
        const float2 wf = tw[4 * t];
        float4 r0, r1, r2, r3;
        fwd4q(A0, B0, A1, B1, wf, r0, r1, r2, r3);
        e[t] = r0; e[t + 8] = r1; e[t + 16] = r2; e[t + 24] = r3;
        fwd4q(A2, B2, A3, B3, wf, r0, r1, r2, r3);
        e[t + 32] = r0; e[t + 40] = r1; e[t + 48] = r2; e[t + 56] = r3;
    }
    __syncthreads();
    // MERGE Q: fwd32-y stages 2,1,0 + mux2 (lanes = X, stride 129 -> conflict-free)
    for (int u = threadIdx.x; u < 1024; u += NT3) {
        int X = u & 63, r = u >> 6;                        // r in [0,16)
        int seg = r & 3, m = r >> 2;
        float4* e = tile + X * 129 + seg * 32 + 8 * m;
        float4 z[8];
        #pragma unroll
        for (int j = 0; j < 8; ++j) z[j] = e[j];
        fwd8q(z);
        int xc2 = X >> 5, yc2 = seg & 1;
        int ubase = ((xc2 * 2 + yc2) << 10) + ((8 * m) << 5) + (X & 31);
        #pragma unroll
        for (int j = 0; j < 8; ++j) {
            int ui = (ubase + 32 * j) * 2;
            e[j] = mux4(z[j], g_U2[ui], g_U2[ui + 1]);
        }
    }
    __syncthreads();
    // final x inv32: pass4 S=0, then MERGE R (stages 2,3,4 + scale 1/32)
    pass4<true, NT3, 129, 1, 7, 4128, 1, 5, 0, false>(tile, tw, 1.f);
    for (int u = threadIdx.x; u < 1024; u += NT3) {
        int y = u & 127, r = u >> 7;                       // r in [0,8)
        int t = r & 3, xs = r >> 2;
        float4* e = tile + (xs * 32 + t) * 129 + y;
        float4 z0 = e[0],          z1 = e[4 * 129],  z2 = e[8 * 129],  z3 = e[12 * 129];
        float4 z4 = e[16 * 129],   z5 = e[20 * 129], z6 = e[24 * 129], z7 = e[28 * 129];
        const float2 wA  = tw[16 * t];
        const float2 wB  = tw[8 * t];
        const float2 wB2 = make_float2(wB.y, -wB.x);                       // tw[8t+32]
        const float2 wC  = tw[4 * t];
        const float2 wC1 = cmul(wC, make_float2(SQH, -SQH));               // tw[4t+16]
        const float2 wC2 = make_float2(wC.y, -wC.x);                       // tw[4t+32]
        const float2 wC3 = cmul(wC, make_float2(-SQH, -SQH));              // tw[4t+48]
        float4 b1 = c4mulc(z1, wA), b3 = c4mulc(z3, wA), b5 = c4mulc(z5, wA), b7 = c4mulc(z7, wA);
        float4 u0 = f4add(z0, b1), u1 = f4sub(z0, b1);
        float4 u2 = f4add(z2, b3), u3 = f4sub(z2, b3);
        float4 u4 = f4add(z4, b5), u5 = f4sub(z4, b5);
        float4 u6 = f4add(z6, b7), u7 = f4sub(z6, b7);
        float4 c2 = c4mulc(u2, wB), c3 = c4mulc(u3, wB2), c6 = c4mulc(u6, wB), c7 = c4mulc(u7, wB2);
        float4 v0 = f4add(u0, c2), v2 = f4sub(u0, c2);
        float4 v1 = f4add(u1, c3), v3 = f4sub(u1, c3);
        float4 v4 = f4add(u4, c6), v6 = f4sub(u4, c6);
        float4 v5 = f4add(u5, c7), v7 = f4sub(u5, c7);
        float4 d4 = c4mulc(v4, wC), d5 = c4mulc(v5, wC1), d6 = c4mulc(v6, wC2), d7 = c4mulc(v7, wC3);
        const float s = 1.0f / 32.0f;
        e[0]        = f4sc(f4add(v0, d4), s);  e[16 * 129] = f4sc(f4sub(v0, d4), s);
        e[4 * 129]  = f4sc(f4add(v1, d5), s);  e[20 * 129] = f4sc(f4sub(v1, d5), s);
        e[8 * 129]  = f4sc(f4add(v2, d6), s);  e[24 * 129] = f4sc(f4sub(v2, d6), s);
        e[12 * 129] = f4sc(f4add(v3, d7), s);  e[28 * 129] = f4sc(f4sub(v3, d7), s);
    }
    __syncthreads();
    // final y inv32: pass4 S=0, pass4 S=2, FUSED last pass (S=4) + measurement
    pass4<true, NT3, 1, 129, 6, 32, 2, 5, 0, false>(tile, tw, 1.f);
    pass4<true, NT3, 1, 129, 6, 32, 2, 5, 2, false>(tile, tw, 1.f);
    for (int u = threadIdx.x; u < 1024; u += NT3) {
        int X = u & 63, t = u >> 6;                        // t in [0,16)
        const float2 w = tw[t << 2];
        float s0a = 0.f, s1a = 0.f, s0b = 0.f, s1b = 0.f;
        #pragma unroll
        for (int seg = 0; seg < 4; ++seg) {
            const float4* e = tile + X * 129 + seg * 32 + t;
            float4 a = e[0], bb = e[16];
            float4 bw = c4mulc(bb, w);
            float4 o0 = f4add(a, bw), o1 = f4sub(a, bw);
            s0a += o0.x * o0.x + o0.y * o0.y;  s1a += o0.z * o0.z + o0.w * o0.w;
            s0b += o1.x * o1.x + o1.y * o1.y;  s1b += o1.z * o1.z + o1.w * o1.w;
        }
        const float sc2 = (1.0f / 32.0f) * (1.0f / 32.0f);
        prob[X * 33 + t]               = s0a * sc2;
        prob[2112 + X * 33 + t]        = s1a * sc2;
        prob[X * 33 + t + 16]          = s0b * sc2;
        prob[2112 + X * 33 + t + 16]   = s1b * sc2;
    }
    __syncthreads();
    // partial GEMV: lanes ya-fastest stride 1 -> conflict-free
    float acc[10];
    #pragma unroll
    for (int c = 0; c < 10; ++c) acc[c] = 0.f;
    {
        int xa = threadIdx.x >> 5, ya = threadIdx.x & 31;
        float p0 = prob[xa * 33 + ya]        + prob[(xa + 32) * 33 + ya];
        float p1 = prob[2112 + xa * 33 + ya] + prob[2112 + (xa + 32) * 33 + ya];
        int j0 = threadIdx.x * 2;
        #pragma unroll
        for (int c = 0; c < 10; ++c) {
            float2 wv = *(const float2*)(W + c * 2048 + j0);
            acc[c] = fmaf(p0, wv.x, fmaf(p1, wv.y, acc[c]));
        }
    }
    #pragma unroll
    for (int c = 0; c < 10; ++c)
        #pragma unroll
        for (int o = 16; o > 0; o >>= 1)
            acc[c] += __shfl_down_sync(0xffffffffu, acc[c], o);
    const int warp = threadIdx.x >> 5, lane = threadIdx.x & 31;
    if (lane == 0)
        #pragma unroll
        for (int c = 0; c < 10; ++c) red[warp * 10 + c] = acc[c];
    __syncthreads();
    if (threadIdx.x < 10) {
        float s = 0.f;
        #pragma unroll
        for (int w = 0; w < 32; ++w) s += red[w * 10 + threadIdx.x];
        g_part[(b * 2 + xc1) * 10 + threadIdx.x] = s;
    }
}

// ---------------- combine ----------------
__global__ void pc(const float* __restrict__ bias, float* __restrict__ out) {
    int i = blockIdx.x * blockDim.x + threadIdx.x;
    if (i < 5120) {
        int b = i / 10, c = i % 10;
        out[i] = bias[c] + g_part[(b * 2) * 10 + c] + g_part[(b * 2 + 1) * 10 + c];
    }
}

// ---------------- launch ----------------
extern "C" void kernel_launch(void* const* d_in, const int* in_sizes, int n_in,
                              void* d_out, int out_size) {
    const float* images = (const float*)d_in[0];
    const float* mux0 = (const float*)d_in[1];
    const float* mux1 = (const float*)d_in[2];
    const float* mux2 = (const float*)d_in[3];
    const float* W = (const float*)d_in[4];
    const float* bias = (const float*)d_in[5];
    float* out = (float*)d_out;
    (void)in_sizes; (void)n_in; (void)out_size;

    cudaFuncSetAttribute(p35, cudaFuncAttributeMaxDynamicSharedMemorySize, P35_SMEM);

    k0<<<64, 256>>>(mux0, mux1, mux2);
    p1<<<dim3(4, 512), NT1>>>(images);
    p2<<<dim3(8, 512), NT2>>>();
    p35<<<dim3(2, 512), NT3, P35_SMEM>>>(W);
    pc<<<10, 512>>>(bias, out);
}

// round 15
// speedup vs baseline: 1.1944x; 1.0524x over previous
#include <cuda_runtime.h>
#include <math.h>

#define PI_D 3.14159265358979323846
#define SQH 0.70710678118654752440f

// ---------------- static device scratch ----------------
__device__ float4 g_S4[512 * 128 * 128];      // state [b][X][Y], float4 = (f0, f1) complex pair
__device__ float4 g_U0[128 * 128 * 2];        // mux0, bitrev-permuted, [kxb][kyb]
__device__ float4 g_U1[2 * 2 * 64 * 64 * 2];  // mux1, bitrev-permuted, TRANSPOSED [cx][cy][kyb][kxb]
__device__ float4 g_U2[2 * 2 * 32 * 32 * 2];  // mux2, bitrev-permuted, TRANSPOSED [cx][cy][kyb][kxb]
__device__ float2 g_TW[64];                   // exp(-2*pi*i*t/128)
__device__ int    g_NR[128];                  // bitrev-domain negation table
__device__ float  g_part[512 * 2 * 10];       // partial logits per (b, xc1)

// ---- float2 complex helpers ----
__device__ __forceinline__ float2 cmul(float2 a, float2 b) {
    return make_float2(a.x * b.x - a.y * b.y, a.x * b.y + a.y * b.x);
}
__device__ __forceinline__ float2 f2add(float2 a, float2 b) { return make_float2(a.x + b.x, a.y + b.y); }
__device__ __forceinline__ float2 f2sub(float2 a, float2 b) { return make_float2(a.x - b.x, a.y - b.y); }
__device__ __forceinline__ float2 csq(float2 a) { return make_float2(a.x * a.x - a.y * a.y, 2.f * a.x * a.y); }

// ---- float4 = two complex numbers, same twiddle applied to both ----
__device__ __forceinline__ float4 f4add(float4 a, float4 b) {
    return make_float4(a.x + b.x, a.y + b.y, a.z + b.z, a.w + b.w);
}
__device__ __forceinline__ float4 f4sub(float4 a, float4 b) {
    return make_float4(a.x - b.x, a.y - b.y, a.z - b.z, a.w - b.w);
}
__device__ __forceinline__ float4 f4sc(float4 a, float s) {
    return make_float4(a.x * s, a.y * s, a.z * s, a.w * s);
}
__device__ __forceinline__ float4 c4mul(float4 v, float2 w) {
    return make_float4(v.x * w.x - v.y * w.y, v.x * w.y + v.y * w.x,
                       v.z * w.x - v.w * w.y, v.z * w.y + v.w * w.x);
}
__device__ __forceinline__ float4 c4mulc(float4 v, float2 w) {
    return make_float4(v.x * w.x + v.y * w.y, v.y * w.x - v.x * w.y,
                       v.z * w.x + v.w * w.y, v.w * w.x - v.z * w.y);
}
__device__ __forceinline__ float4 c4mulnegi(float4 v) {  // *( -i )
    return make_float4(v.y, -v.x, v.w, -v.z);
}
__device__ __forceinline__ float4 c4mulposi(float4 v) {  // *( +i )
    return make_float4(-v.y, v.x, -v.w, v.z);
}
// mux on one float4 site: q0=(x,y), q1=(z,w)
__device__ __forceinline__ float4 mux4(float4 v, float4 uA, float4 uB) {
    float4 o;
    o.x = uA.x * v.x - uA.y * v.y + uA.z * v.z - uA.w * v.w;
    o.y = uA.x * v.y + uA.y * v.x + uA.z * v.w + uA.w * v.z;
    o.z = uB.x * v.x - uB.y * v.y + uB.z * v.z - uB.w * v.w;
    o.w = uB.x * v.y + uB.y * v.x + uB.z * v.w + uB.w * v.z;
    return o;
}

// ---- register-level butterflies (exact template math) ----
__device__ __forceinline__ void inv4q(float4 a, float4 b, float4 c, float4 d,
                                      float2 w0, float s,
                                      float4& o0, float4& o1, float4& o2, float4& o3) {
    float2 w1 = make_float2(w0.y, -w0.x);
    float2 w2 = csq(w0);
    float4 bw = c4mulc(b, w2), dw = c4mulc(d, w2);
    float4 aP = f4add(a, bw), bP = f4sub(a, bw);
    float4 cP = f4add(c, dw), dP = f4sub(c, dw);
    float4 cw = c4mulc(cP, w0), dq = c4mulc(dP, w1);
    o0 = f4sc(f4add(aP, cw), s); o2 = f4sc(f4sub(aP, cw), s);
    o1 = f4sc(f4add(bP, dq), s); o3 = f4sc(f4sub(bP, dq), s);
}
__device__ __forceinline__ void fwd4q(float4 a, float4 b, float4 c, float4 d,
                                      float2 w0,
                                      float4& o0, float4& o1, float4& o2, float4& o3) {
    float2 w1 = make_float2(w0.y, -w0.x);
    float2 w2 = csq(w0);
    float4 ac = f4add(a, c), bd = f4add(b, d);
    float4 cP = c4mul(f4sub(a, c), w0);
    float4 dP = c4mul(f4sub(b, d), w1);
    o0 = f4add(ac, bd);
    o1 = c4mul(f4sub(ac, bd), w2);
    o2 = f4add(cP, dP);
    o3 = c4mul(f4sub(cP, dP), w2);
}
// full 8-point DIF (stages h=4,2,1; natural->bitrev in-block, t=0)
__device__ __forceinline__ void fwd8q(float4* z) {
    const float2 tw16c = make_float2(SQH, -SQH);    // e^{-i pi/4}
    const float2 tw48c = make_float2(-SQH, -SQH);   // e^{-3i pi/4}
    float4 s0 = f4add(z[0], z[4]), s1 = f4add(z[1], z[5]);
    float4 s2 = f4add(z[2], z[6]), s3 = f4add(z[3], z[7]);
    float4 t0 = f4sub(z[0], z[4]);
    float4 t1 = c4mul(f4sub(z[1], z[5]), tw16c);
    float4 t2 = c4mulnegi(f4sub(z[2], z[6]));
    float4 t3 = c4mul(f4sub(z[3], z[7]), tw48c);
    float4 m0 = f4add(s0, s2), m2 = f4sub(s0, s2);
    float4 m1 = f4add(s1, s3), m3 = c4mulnegi(f4sub(s1, s3));
    z[0] = f4add(m0, m1); z[1] = f4sub(m0, m1);
    z[2] = f4add(m2, m3); z[3] = f4sub(m2, m3);
    float4 n0 = f4add(t0, t2), n2 = f4sub(t0, t2);
    float4 n1 = f4add(t1, t3), n3 = c4mulnegi(f4sub(t1, t3));
    z[4] = f4add(n0, n1); z[5] = f4sub(n0, n1);
    z[6] = f4add(n2, n3); z[7] = f4sub(n2, n3);
}
// 8-point DIT block for inv stages S,S+1,S+2 on elements z[j] at positions t + j*h.
// w = W(t, 8h) (= tw[t << (4-S)]); R4-verified pass8-INV algebra; scale folded.
__device__ __forceinline__ void inv8t(float4* z, float2 w, float s) {
    const float2 w1 = cmul(w, make_float2(SQH, -SQH));
    const float2 w2 = make_float2(w.y, -w.x);
    const float2 w3 = cmul(w, make_float2(-SQH, -SQH));
    const float2 u2 = csq(w);
    const float2 u2m = make_float2(u2.y, -u2.x);
    const float2 v4 = csq(u2);
    float4 q1 = c4mulc(z[1], v4), q3 = c4mulc(z[3], v4);
    float4 q5 = c4mulc(z[5], v4), q7 = c4mulc(z[7], v4);
    float4 c0 = f4add(z[0], q1), c1 = f4sub(z[0], q1);
    float4 c2 = f4add(z[2], q3), c3 = f4sub(z[2], q3);
    float4 c4_ = f4add(z[4], q5), c5 = f4sub(z[4], q5);
    float4 c6 = f4add(z[6], q7), c7 = f4sub(z[6], q7);
    float4 r2 = c4mulc(c2, u2), r3 = c4mulc(c3, u2m);
    float4 r6 = c4mulc(c6, u2), r7 = c4mulc(c7, u2m);
    float4 g0 = f4add(c0, r2), g2 = f4sub(c0, r2);
    float4 g1 = f4add(c1, r3), g3 = f4sub(c1, r3);
    float4 g4 = f4add(c4_, r6), g6 = f4sub(c4_, r6);
    float4 g5 = f4add(c5, r7), g7 = f4sub(c5, r7);
    float4 h4 = c4mulc(g4, w), h5 = c4mulc(g5, w1);
    float4 h6 = c4mulc(g6, w2), h7 = c4mulc(g7, w3);
    z[0] = f4sc(f4add(g0, h4), s); z[4] = f4sc(f4sub(g0, h4), s);
    z[1] = f4sc(f4add(g1, h5), s); z[5] = f4sc(f4sub(g1, h5), s);
    z[2] = f4sc(f4add(g2, h6), s); z[6] = f4sc(f4sub(g2, h6), s);
    z[3] = f4sc(f4add(g3, h7), s); z[7] = f4sc(f4sub(g3, h7), s);
}

// =====================================================================
// float4 FFT passes (template sweeps kept for the remaining mid-stages)
// =====================================================================
template<bool INV, int NTT, int SP, int SL1, int LG1, int SL2, int LG2, int LOGN, int S, bool LAST>
__device__ __forceinline__ void pass4(float4* __restrict__ base,
                                      const float2* __restrict__ tw, float scale) {
    constexpr int L = 1 << (LG1 + LG2);
    constexpr int ITEMS = L << (LOGN - 2);
    constexpr int h = 1 << S;
    for (int u = threadIdx.x; u < ITEMS; u += NTT) {
        const int line = u & (L - 1);
        const int loff = (line & ((1 << LG1) - 1)) * SL1 + (line >> LG1) * SL2;
        const int v = u >> (LG1 + LG2);
        const int t = v & (h - 1);
        const int p = ((v >> S) << (S + 2)) + t;
        float4* e = base + loff + p * SP;
        float4 a = e[0], b = e[h * SP], c = e[2 * h * SP], d = e[3 * h * SP];
        const float2 w0 = tw[t << (5 - S)];
        const float2 w1 = make_float2(w0.y, -w0.x);
        const float2 w2 = csq(w0);
        if constexpr (!INV) {
            float4 ac = f4add(a, c), bd = f4add(b, d);
            float4 cP = c4mul(f4sub(a, c), w0);
            float4 dP = c4mul(f4sub(b, d), w1);
            e[0]          = f4add(ac, bd);
            e[h * SP]     = c4mul(f4sub(ac, bd), w2);
            e[2 * h * SP] = f4add(cP, dP);
            e[3 * h * SP] = c4mul(f4sub(cP, dP), w2);
        } else {
            float4 bw = c4mulc(b, w2), dw = c4mulc(d, w2);
            float4 aP = f4add(a, bw), bP = f4sub(a, bw);
            float4 cP = f4add(c, dw), dP = f4sub(c, dw);
            float4 cw = c4mulc(cP, w0), dq = c4mulc(dP, w1);
            float4 o0 = f4add(aP, cw), o2 = f4sub(aP, cw);
            float4 o1 = f4add(bP, dq), o3 = f4sub(bP, dq);
            if constexpr (LAST) {
                o0 = f4sc(o0, scale); o1 = f4sc(o1, scale);
                o2 = f4sc(o2, scale); o3 = f4sc(o3, scale);
            }
            e[0] = o0; e[h * SP] = o1; e[2 * h * SP] = o2; e[3 * h * SP] = o3;
        }
    }
    __syncthreads();
}

// ---------------- float2 passes (p1 only) ----------------
template<int NTT, int SP, int LG1, int LOGN, int S>
__device__ __forceinline__ void pass4s(float2* __restrict__ base,
                                       const float2* __restrict__ tw) {
    constexpr int L = 1 << LG1;
    constexpr int ITEMS = L << (LOGN - 2);
    constexpr int h = 1 << S;
    for (int u = threadIdx.x; u < ITEMS; u += NTT) {
        const int loff = (u & (L - 1));
        const int v = u >> LG1;
        const int t = v & (h - 1);
        const int p = ((v >> S) << (S + 2)) + t;
        float2* e = base + loff + p * SP;
        float2 a = e[0], b = e[h * SP], c = e[2 * h * SP], d = e[3 * h * SP];
        const float2 w0 = tw[t << (5 - S)];
        const float2 w1 = make_float2(w0.y, -w0.x);
        const float2 w2 = csq(w0);
        float2 ac = f2add(a, c), bd = f2add(b, d);
        float2 cP = cmul(f2sub(a, c), w0);
        float2 dP = cmul(f2sub(b, d), w1);
        e[0]          = f2add(ac, bd);
        e[h * SP]     = cmul(f2sub(ac, bd), w2);
        e[2 * h * SP] = f2add(cP, dP);
        e[3 * h * SP] = cmul(f2sub(cP, dP), w2);
    }
    __syncthreads();
}
template<int NTT, int SP, int LG1, int LOGN, int S>
__device__ __forceinline__ void pass2s(float2* __restrict__ base,
                                       const float2* __restrict__ tw) {
    constexpr int L = 1 << LG1;
    constexpr int ITEMS = L << (LOGN - 1);
    constexpr int h = 1 << S;
    for (int u = threadIdx.x; u < ITEMS; u += NTT) {
        const int loff = (u & (L - 1));
        const int v = u >> LG1;
        const int t = v & (h - 1);
        const int p = ((v >> S) << (S + 1)) + t;
        float2* e = base + loff + p * SP;
        float2 a = e[0], b = e[h * SP];
        const float2 w = tw[t << (6 - S)];
        e[0]      = f2add(a, b);
        e[h * SP] = cmul(f2sub(a, b), w);
    }
    __syncthreads();
}

// ---------------- K0: precompute ----------------
__device__ __forceinline__ void writeU(float4* dst, float axf, float ayf, float azf) {
    double ax = axf, ay = ayf, az = azf;
    double r = sqrt(ax * ax + ay * ay + az * az + 1e-20);
    double cr = cos(r), sn = sin(r) / r;
    dst[0] = make_float4((float)cr, (float)(-az * sn), (float)(-ay * sn), (float)(-ax * sn));
    dst[1] = make_float4((float)(ay * sn), (float)(-ax * sn), (float)cr, (float)(az * sn));
}

__global__ void k0(const float* __restrict__ mux0, const float* __restrict__ mux1,
                   const float* __restrict__ mux2) {
    int idx = blockIdx.x * blockDim.x + threadIdx.x;   // 16384 threads
    if (idx < 64) {
        double ang = -2.0 * PI_D * (double)idx / 128.0;
        g_TW[idx] = make_float2((float)cos(ang), (float)sin(ang));
    }
    if (idx < 128) {
        int k = __brev((unsigned)idx) >> 25;
        g_NR[idx] = (int)(__brev((unsigned)((128 - k) & 127)) >> 25);
    }
    {   // U0: [kxb][kyb]
        int kxb = idx >> 7, kyb = idx & 127;
        int kx = __brev((unsigned)kxb) >> 25, ky = __brev((unsigned)kyb) >> 25;
        const float* c = mux0 + (kx * 128 + ky) * 3;
        writeU(&g_U0[idx * 2], c[0], c[1], c[2]);
    }
    {   // U1: TRANSPOSED [cx][cy][kyb][kxb]
        int cx = idx >> 13, cy = (idx >> 12) & 1, kxb = (idx >> 6) & 63, kyb = idx & 63;
        int kx = __brev((unsigned)kxb) >> 26, ky = __brev((unsigned)kyb) >> 26;
        const float* c = mux1 + (((cx * 2 + cy) * 64 + kx) * 64 + ky) * 3;
        int tidx = (cx << 13) + (cy << 12) + (kyb << 6) + kxb;
        writeU(&g_U1[tidx * 2], c[0], c[1], c[2]);
    }
    if (idx < 4096) {   // U2: TRANSPOSED [cx][cy][kyb][kxb]
        int cx = idx >> 11, cy = (idx >> 10) & 1, kxb = (idx >> 5) & 31, kyb = idx & 31;
        int kx = __brev((unsigned)kxb) >> 27, ky = __brev((unsigned)kyb) >> 27;
        const float* c = mux2 + (((cx * 2 + cy) * 32 + kx) * 32 + ky) * 3;
        int tidx = (cx << 11) + (cy << 10) + (kyb << 5) + kxb;
        writeU(&g_U2[tidx * 2], c[0], c[1], c[2]);
    }
}

// ---------------- P1: encode + y-FFT128 (Hermitian packed) ----------------
#define NT1 512
__global__ __launch_bounds__(NT1) void p1(const float* __restrict__ images) {
    __shared__ float2 z[128 * 33];
    __shared__ float2 tw[64];
    const int b = blockIdx.y, X0 = blockIdx.x * 32;
    for (int i = threadIdx.x; i < 64; i += NT1) tw[i] = g_TW[i];
    for (int idx = threadIdx.x; idx < 4096; idx += NT1) {
        int l = idx >> 7, y = idx & 127;
        float I = images[(b * 128 + X0 + l) * 128 + y];
        float sv, cv;
        sincosf(0.5f * (float)PI_D * I, &sv, &cv);
        z[y * 33 + l] = make_float2(cv * (1.0f / 128.0f), sv * (1.0f / 128.0f));
    }
    __syncthreads();
    pass4s<NT1, 33, 5, 7, 5>(z, tw);
    pass4s<NT1, 33, 5, 7, 3>(z, tw);
    pass4s<NT1, 33, 5, 7, 1>(z, tw);
    pass2s<NT1, 33, 5, 7, 0>(z, tw);
    for (int idx = threadIdx.x; idx < 4096; idx += NT1) {
        int l = idx >> 7, kb = idx & 127;
        float2 Z = z[kb * 33 + l];
        float2 Zn = z[g_NR[kb] * 33 + l];
        float2 C  = make_float2(0.5f * (Z.x + Zn.x), 0.5f * (Z.y - Zn.y));
        float2 Sf = make_float2(0.5f * (Z.y + Zn.y), 0.5f * (Zn.x - Z.x));
        int X = X0 + l;
        g_S4[(b * 128 + X) * 128 + kb] = make_float4(C.x, C.y, Sf.x, Sf.y);
    }
}

// ---------------- P2: x-FFT128 + mux0 + x-IFFT128 + x-FFT64(halves) ----------------
#define NT2 512
__global__ __launch_bounds__(NT2) void p2() {
    __shared__ float4 tile[128 * 16];
    __shared__ float2 tw[64];
    const int b = blockIdx.y, y0 = blockIdx.x * 16;
    for (int i = threadIdx.x; i < 64; i += NT2) tw[i] = g_TW[i];
    __syncthreads();
    // fused: fwd7 pass4 S=5 reading directly from global
    for (int u = threadIdx.x; u < 512; u += NT2) {
        int yl = u & 15, v = u >> 4;                 // v in [0,32) = position
        const float4* g = &g_S4[(b * 128 + v) * 128 + y0 + yl];
        float4 a = g[0], bb = g[32 * 128], c = g[64 * 128], d = g[96 * 128];
        const float2 w0 = tw[v];
        const float2 w1 = make_float2(w0.y, -w0.x);
        const float2 w2 = csq(w0);
        float4 ac = f4add(a, c), bd = f4add(bb, d);
        float4 cP = c4mul(f4sub(a, c), w0);
        float4 dP = c4mul(f4sub(bb, d), w1);
        float4* e = tile + v * 16 + yl;
        e[0]       = f4add(ac, bd);
        e[32 * 16] = c4mul(f4sub(ac, bd), w2);
        e[64 * 16] = f4add(cP, dP);
        e[96 * 16] = c4mul(f4sub(cP, dP), w2);
    }
    __syncthreads();
    pass4<false, NT2, 16, 1, 4, 0, 0, 7, 3, false>(tile, tw, 1.f);
    pass4<false, NT2, 16, 1, 4, 0, 0, 7, 1, false>(tile, tw, 1.f);
    // fused: fwd7 pass2 S=0 (w=1) + mux0
    for (int u = threadIdx.x; u < 1024; u += NT2) {
        int yl = u & 15, v = u >> 4;                 // v in [0,64)
        float4* e = tile + (2 * v) * 16 + yl;
        float4 a = e[0], bb = e[16];
        float4 o0 = f4add(a, bb), o1 = f4sub(a, bb);
        int i0 = (((2 * v) << 7) + y0 + yl) * 2;
        int i1 = (((2 * v + 1) << 7) + y0 + yl) * 2;
        e[0]  = mux4(o0, g_U0[i0], g_U0[i0 + 1]);
        e[16] = mux4(o1, g_U0[i1], g_U0[i1 + 1]);
    }
    __syncthreads();
    // inv128 stages 0,1,2 (8 consecutive positions, t=0)
    for (int u = threadIdx.x; u < 256; u += NT2) {
        int yl = u & 15, v = u >> 4;                 // v in [0,16)
        float4* e = tile + (8 * v) * 16 + yl;
        float4 z[8];
        #pragma unroll
        for (int j = 0; j < 8; ++j) z[j] = e[j * 16];
        inv8t(z, make_float2(1.f, 0.f), 1.f);
        #pragma unroll
        for (int j = 0; j < 8; ++j) e[j * 16] = z[j];
    }
    __syncthreads();
    // inv128 stages 3,4,5 (stride 8, blocks of 64)
    for (int u = threadIdx.x; u < 256; u += NT2) {
        int yl = u & 15, blk = (u >> 4) & 1, t = u >> 5;  // t in [0,8)
        float4* e = tile + (blk * 64 + t) * 16 + yl;
        float4 z[8];
        #pragma unroll
        for (int j = 0; j < 8; ++j) z[j] = e[j * 8 * 16];
        inv8t(z, tw[2 * t], 1.f);
        #pragma unroll
        for (int j = 0; j < 8; ++j) e[j * 8 * 16] = z[j];
    }
    __syncthreads();
    // FUSION D: inv128 stage 6 (scale 1/128) + fwd64 stages h=32,16
    for (int u = threadIdx.x; u < 256; u += NT2) {
        int yl = u & 15, t = u >> 4;                 // t in [0,16)
        float4* e = tile + yl;
        float4 p0[4], p1[4];
        #pragma unroll
        for (int k = 0; k < 4; ++k) {
            float4 a = e[(t + 16 * k) * 16], bq = e[(t + 64 + 16 * k) * 16];
            float4 bw = c4mulc(bq, tw[t + 16 * k]);
            p0[k] = f4sc(f4add(a, bw), 1.0f / 128.0f);
            p1[k] = f4sc(f4sub(a, bw), 1.0f / 128.0f);
        }
        const float2 wf = tw[2 * t];
        float4 r0, r1, r2, r3;
        fwd4q(p0[0], p0[1], p0[2], p0[3], wf, r0, r1, r2, r3);
        e[t * 16] = r0; e[(t + 16) * 16] = r1; e[(t + 32) * 16] = r2; e[(t + 48) * 16] = r3;
        fwd4q(p1[0], p1[1], p1[2], p1[3], wf, r0, r1, r2, r3);
        e[(t + 64) * 16] = r0; e[(t + 80) * 16] = r1; e[(t + 96) * 16] = r2; e[(t + 112) * 16] = r3;
    }
    __syncthreads();
    // fwd64 halves: h=8,4, then fused h=2,1 + global store
    pass4<false, NT2, 16, 1, 4, 1024, 1, 6, 2, false>(tile, tw, 1.f);
    for (int u = threadIdx.x; u < 512; u += NT2) {
        int yl = u & 15, half = (u >> 4) & 1, v = u >> 5;   // v in [0,16)
        float4* e = tile + half * 1024 + (4 * v) * 16 + yl;
        float4 a = e[0], bb = e[16], c = e[32], d = e[48];
        float4 ac = f4add(a, c), bd = f4add(bb, d);
        float4 cP = f4sub(a, c);
        float4 dP = c4mulnegi(f4sub(bb, d));
        int Xb = half * 64 + 4 * v;
        float4* g = &g_S4[(b * 128 + Xb) * 128 + y0 + yl];
        g[0]   = f4add(ac, bd);
        g[128] = f4sub(ac, bd);
        g[256] = f4add(cP, dP);
        g[384] = f4sub(cP, dP);
    }
}

// ---------------- P35 ----------------
#define NT3 1024
#define P35_SMEM (132096 + 512 + 16896 + 1280)
__global__ __launch_bounds__(NT3) void p35(const float* __restrict__ W) {
    extern __shared__ char sm[];
    float4* tile = (float4*)sm;                            // [64 X][129] float4
    float2* tw   = (float2*)(sm + 132096);
    float*  prob = (float*)(sm + 132096 + 512);            // [2 f][64 X][33 pitch]
    float*  red  = (float*)(sm + 132096 + 512 + 16896);    // 32*10 f32
    const int b = blockIdx.y, xc1 = blockIdx.x;
    for (int i = threadIdx.x; i < 64; i += NT3) tw[i] = g_TW[i];
    __syncthreads();
    // inv128-y stages 0,1,2 reading directly from global (8 consecutive y, t=0)
    for (int u = threadIdx.x; u < 1024; u += NT3) {
        int X = u & 63, v = u >> 6;                        // v in [0,16)
        const float4* g = &g_S4[(b * 128 + xc1 * 64 + X) * 128 + 8 * v];
        float4 z[8];
        #pragma unroll
        for (int j = 0; j < 8; ++j) z[j] = g[j];
        inv8t(z, make_float2(1.f, 0.f), 1.f);
        float4* e = tile + X * 129 + 8 * v;
        #pragma unroll
        for (int j = 0; j < 8; ++j) e[j] = z[j];
    }
    __syncthreads();
    // inv128-y stages 3,4,5 (stride 8, blocks of 64)
    for (int u = threadIdx.x; u < 1024; u += NT3) {
        int X = u & 63, blk = (u >> 6) & 1, t = u >> 7;    // t in [0,8)
        float4* e = tile + X * 129 + blk * 64 + t;
        float4 z[8];
        #pragma unroll
        for (int j = 0; j < 8; ++j) z[j] = e[8 * j];
        inv8t(z, tw[2 * t], 1.f);
        #pragma unroll
        for (int j = 0; j < 8; ++j) e[8 * j] = z[j];
    }
    __syncthreads();
    // FUSION A: inv128-y stage 6 (scale 1/128) + fwd64-y stages h=32,16
    for (int u = threadIdx.x; u < 1024; u += NT3) {
        int X = u & 63, t = u >> 6;                        // t in [0,16)
        float4* e = tile + X * 129;
        float4 p0[4], p1[4];
        #pragma unroll
        for (int k = 0; k < 4; ++k) {
            float4 a = e[t + 16 * k], bq = e[t + 64 + 16 * k];
            float4 bw = c4mulc(bq, tw[t + 16 * k]);
            p0[k] = f4sc(f4add(a, bw), 1.0f / 128.0f);
            p1[k] = f4sc(f4sub(a, bw), 1.0f / 128.0f);
        }
        const float2 wf = tw[2 * t];
        float4 r0, r1, r2, r3;
        fwd4q(p0[0], p0[1], p0[2], p0[3], wf, r0, r1, r2, r3);
        e[t] = r0; e[t + 16] = r1; e[t + 32] = r2; e[t + 48] = r3;
        fwd4q(p1[0], p1[1], p1[2], p1[3], wf, r0, r1, r2, r3);
        e[t + 64] = r0; e[t + 80] = r1; e[t + 96] = r2; e[t + 112] = r3;
    }
    __syncthreads();
    // fwd64 y halves: h=8,4, then fused h=2,1 + mux1
    pass4<false, NT3, 1, 129, 6, 64, 1, 6, 2, false>(tile, tw, 1.f);
    for (int u = threadIdx.x; u < 2048; u += NT3) {
        int X = u & 63, half = (u >> 6) & 1, v = u >> 7;   // v in [0,16)
        float4* e = tile + X * 129 + half * 64 + 4 * v;
        float4 a = e[0], bb = e[1], c = e[2], d = e[3];
        float4 ac = f4add(a, c), bd = f4add(bb, d);
        float4 cP = f4sub(a, c);
        float4 dP = c4mulnegi(f4sub(bb, d));
        float4 o0 = f4add(ac, bd), o1 = f4sub(ac, bd);
        float4 o2 = f4add(cP, dP), o3 = f4sub(cP, dP);
        int ub = (((xc1 * 2 + half) << 12) + ((4 * v) << 6) + X) * 2;
        e[0] = mux4(o0, g_U1[ub],       g_U1[ub + 1]);
        e[1] = mux4(o1, g_U1[ub + 128], g_U1[ub + 129]);
        e[2] = mux4(o2, g_U1[ub + 256], g_U1[ub + 257]);
        e[3] = mux4(o3, g_U1[ub + 384], g_U1[ub + 385]);
    }
    __syncthreads();
    // x junction: inv64-x stages 0,1,2 (8 consecutive X, t=0)
    for (int u = threadIdx.x; u < 1024; u += NT3) {
        int y = u & 127, m = u >> 7;                       // m in [0,8)
        float4* e = tile + (8 * m) * 129 + y;
        float4 z[8];
        #pragma unroll
        for (int j = 0; j < 8; ++j) z[j] = e[j * 129];
        inv8t(z, make_float2(1.f, 0.f), 1.f);
        #pragma unroll
        for (int j = 0; j < 8; ++j) e[j * 129] = z[j];
    }
    __syncthreads();
    // FUSION B': inv64-x stages 3,4,5 (scale 1/64) + fwd32-x stages h=16,8
    for (int u = threadIdx.x; u < 1024; u += NT3) {
        int y = u & 127, t = u >> 7;                       // t in [0,8)
        float4* e = tile + t * 129 + y;
        float4 z[8];
        #pragma unroll
        for (int j = 0; j < 8; ++j) z[j] = e[8 * j * 129];
        inv8t(z, tw[2 * t], 1.0f / 64.0f);
        const float2 wf = tw[4 * t];
        float4 r0, r1, r2, r3;
        fwd4q(z[0], z[1], z[2], z[3], wf, r0, r1, r2, r3);
        e[0] = r0; e[8 * 129] = r1; e[16 * 129] = r2; e[24 * 129] = r3;
        fwd4q(z[4], z[5], z[6], z[7], wf, r0, r1, r2, r3);
        e[32 * 129] = r0; e[40 * 129] = r1; e[48 * 129] = r2; e[56 * 129] = r3;
    }
    __syncthreads();
    // MERGE P: fwd32-x stages h=4,2,1 (8-pt DIF)
    for (int u = threadIdx.x; u < 1024; u += NT3) {
        int y = u & 127, r = u >> 7;                       // r in [0,8)
        int m = r & 3, xs = r >> 2;
        float4* e = tile + (xs * 32 + 8 * m) * 129 + y;
        float4 z[8];
        #pragma unroll
        for (int j = 0; j < 8; ++j) z[j] = e[j * 129];
        fwd8q(z);
        #pragma unroll
        for (int j = 0; j < 8; ++j) e[j * 129] = z[j];
    }
    __syncthreads();
    // y junction: inv64-y stages 0,1,2 (8 consecutive y within halves, t=0)
    for (int u = threadIdx.x; u < 1024; u += NT3) {
        int X = u & 63, half = (u >> 6) & 1, m = u >> 7;   // m in [0,8)
        float4* e = tile + X * 129 + half * 64 + 8 * m;
        float4 z[8];
        #pragma unroll
        for (int j = 0; j < 8; ++j) z[j] = e[j];
        inv8t(z, make_float2(1.f, 0.f), 1.f);
        #pragma unroll
        for (int j = 0; j < 8; ++j) e[j] = z[j];
    }
    __syncthreads();
    // FUSION C': inv64-y stages 3,4,5 (scale 1/64) + fwd32-y stages h=16,8
    for (int u = threadIdx.x; u < 1024; u += NT3) {
        int X = u & 63, half = (u >> 6) & 1, t = u >> 7;   // t in [0,8)
        float4* e = tile + X * 129 + half * 64 + t;
        float4 z[8];
        #pragma unroll
        for (int j = 0; j < 8; ++j) z[j] = e[8 * j];
        inv8t(z, tw[2 * t], 1.0f / 64.0f);
        const float2 wf = tw[4 * t];
        float4 r0, r1, r2, r3;
        fwd4q(z[0], z[1], z[2], z[3], wf, r0, r1, r2, r3);
        e[0] = r0; e[8] = r1; e[16] = r2; e[24] = r3;
        fwd4q(z[4], z[5], z[6], z[7], wf, r0, r1, r2, r3);
        e[32] = r0; e[40] = r1; e[48] = r2; e[56] = r3;
    }
    __syncthreads();
    // MERGE Q: fwd32-y stages h=4,2,1 + mux2
    for (int u = threadIdx.x; u < 1024; u += NT3) {
        int X = u & 63, r = u >> 6;                        // r in [0,16)
        int seg = r & 3, m = r >> 2;
        float4* e = tile + X * 129 + seg * 32 + 8 * m;
        float4 z[8];
        #pragma unroll
        for (int j = 0; j < 8; ++j) z[j] = e[j];
        fwd8q(z);
        int xc2 = X >> 5, yc2 = seg & 1;
        int ubase = ((xc2 * 2 + yc2) << 10) + ((8 * m) << 5) + (X & 31);
        #pragma unroll
        for (int j = 0; j < 8; ++j) {
            int ui = (ubase + 32 * j) * 2;
            e[j] = mux4(z[j], g_U2[ui], g_U2[ui + 1]);
        }
    }
    __syncthreads();
    // final x inv32: pass4 stages 0,1, then MERGE R (stages 2,3,4 + scale 1/32)
    pass4<true, NT3, 129, 1, 7, 4128, 1, 5, 0, false>(tile, tw, 1.f);
    for (int u = threadIdx.x; u < 1024; u += NT3) {
        int y = u & 127, r = u >> 7;                       // r in [0,8)
        int t = r & 3, xs = r >> 2;
        float4* e = tile + (xs * 32 + t) * 129 + y;
        float4 z[8];
        #pragma unroll
        for (int j = 0; j < 8; ++j) z[j] = e[4 * j * 129];
        inv8t(z, tw[4 * t], 1.0f / 32.0f);
        #pragma unroll
        for (int j = 0; j < 8; ++j) e[4 * j * 129] = z[j];
    }
    __syncthreads();
    // final y inv32: stages 0,1,2 (8 consecutive within segs, t=0)
    for (int u = threadIdx.x; u < 1024; u += NT3) {
        int X = u & 63, seg = (u >> 6) & 3, m = u >> 8;    // m in [0,4)
        float4* e = tile + X * 129 + seg * 32 + 8 * m;
        float4 z[8];
        #pragma unroll
        for (int j = 0; j < 8; ++j) z[j] = e[j];
        inv8t(z, make_float2(1.f, 0.f), 1.f);
        #pragma unroll
        for (int j = 0; j < 8; ++j) e[j] = z[j];
    }
    __syncthreads();
    // measure': final y inv32 stages 3,4 (inv4q, scale 1/32) + |.|^2 accumulate over segs
    for (int u = threadIdx.x; u < 512; u += NT3) {
        int X = u & 63, t = u >> 6;                        // t in [0,8)
        const float2 w0 = tw[4 * t];
        float s0[4], s1[4];
        #pragma unroll
        for (int j = 0; j < 4; ++j) { s0[j] = 0.f; s1[j] = 0.f; }
        #pragma unroll
        for (int seg = 0; seg < 4; ++seg) {
            const float4* e = tile + X * 129 + seg * 32 + t;
            float4 o0, o1, o2, o3;
            inv4q(e[0], e[8], e[16], e[24], w0, 1.0f / 32.0f, o0, o1, o2, o3);
            s0[0] += o0.x * o0.x + o0.y * o0.y;  s1[0] += o0.z * o0.z + o0.w * o0.w;
            s0[1] += o1.x * o1.x + o1.y * o1.y;  s1[1] += o1.z * o1.z + o1.w * o1.w;
            s0[2] += o2.x * o2.x + o2.y * o2.y;  s1[2] += o2.z * o2.z + o2.w * o2.w;
            s0[3] += o3.x * o3.x + o3.y * o3.y;  s1[3] += o3.z * o3.z + o3.w * o3.w;
        }
        #pragma unroll
        for (int j = 0; j < 4; ++j) {
            prob[X * 33 + t + 8 * j]        = s0[j];
            prob[2112 + X * 33 + t + 8 * j] = s1[j];
        }
    }
    __syncthreads();
    // partial GEMV: lanes ya-fastest stride 1 -> conflict-free
    float acc[10];
    #pragma unroll
    for (int c = 0; c < 10; ++c) acc[c] = 0.f;
    {
        int xa = threadIdx.x >> 5, ya = threadIdx.x & 31;
        float p0 = prob[xa * 33 + ya]        + prob[(xa + 32) * 33 + ya];
        float p1 = prob[2112 + xa * 33 + ya] + prob[2112 + (xa + 32) * 33 + ya];
        int j0 = threadIdx.x * 2;
        #pragma unroll
        for (int c = 0; c < 10; ++c) {
            float2 wv = *(const float2*)(W + c * 2048 + j0);
            acc[c] = fmaf(p0, wv.x, fmaf(p1, wv.y, acc[c]));
        }
    }
    #pragma unroll
    for (int c = 0; c < 10; ++c)
        #pragma unroll
        for (int o = 16; o > 0; o >>= 1)
            acc[c] += __shfl_down_sync(0xffffffffu, acc[c], o);
    const int warp = threadIdx.x >> 5, lane = threadIdx.x & 31;
    if (lane == 0)
        #pragma unroll
        for (int c = 0; c < 10; ++c) red[warp * 10 + c] = acc[c];
    __syncthreads();
    if (threadIdx.x < 10) {
        float s = 0.f;
        #pragma unroll
        for (int w = 0; w < 32; ++w) s += red[w * 10 + threadIdx.x];
        g_part[(b * 2 + xc1) * 10 + threadIdx.x] = s;
    }
}

// ---------------- combine ----------------
__global__ void pc(const float* __restrict__ bias, float* __restrict__ out) {
    int i = blockIdx.x * blockDim.x + threadIdx.x;
    if (i < 5120) {
        int b = i / 10, c = i % 10;
        out[i] = bias[c] + g_part[(b * 2) * 10 + c] + g_part[(b * 2 + 1) * 10 + c];
    }
}

// ---------------- launch ----------------
extern "C" void kernel_launch(void* const* d_in, const int* in_sizes, int n_in,
                              void* d_out, int out_size) {
    const float* images = (const float*)d_in[0];
    const float* mux0 = (const float*)d_in[1];
    const float* mux1 = (const float*)d_in[2];
    const float* mux2 = (const float*)d_in[3];
    const float* W = (const float*)d_in[4];
    const float* bias = (const float*)d_in[5];
    float* out = (float*)d_out;
    (void)in_sizes; (void)n_in; (void)out_size;

    cudaFuncSetAttribute(p35, cudaFuncAttributeMaxDynamicSharedMemorySize, P35_SMEM);

    k0<<<64, 256>>>(mux0, mux1, mux2);
    p1<<<dim3(4, 512), NT1>>>(images);
    p2<<<dim3(8, 512), NT2>>>();
    p35<<<dim3(2, 512), NT3, P35_SMEM>>>(W);
    pc<<<10, 512>>>(bias, out);
}

// round 16
// speedup vs baseline: 1.3192x; 1.1044x over previous
#include <cuda_runtime.h>
#include <math.h>

#define PI_D 3.14159265358979323846
#define SQH 0.70710678118654752440f

// ---------------- static device scratch ----------------
__device__ float4 g_S4[512 * 128 * 128];      // state [b][X][Y], float4 = (f0, f1) complex pair
__device__ float4 g_U0[128 * 128];            // mux0 SU(2)-compressed (u00,u01), bitrev [kxb][kyb]
__device__ float4 g_U1[2 * 2 * 64 * 64];      // mux1 compressed, TRANSPOSED [cx][cy][kyb][kxb]
__device__ float4 g_U2[2 * 2 * 32 * 32];      // mux2 compressed, TRANSPOSED [cx][cy][kyb][kxb]
__device__ float2 g_TW[64];                   // exp(-2*pi*i*t/128)
__device__ int    g_NR[128];                  // bitrev-domain negation table
__device__ float  g_part[512 * 2 * 10];       // partial logits per (b, xc1)

// ---- float2 complex helpers ----
__device__ __forceinline__ float2 cmul(float2 a, float2 b) {
    return make_float2(a.x * b.x - a.y * b.y, a.x * b.y + a.y * b.x);
}
__device__ __forceinline__ float2 f2add(float2 a, float2 b) { return make_float2(a.x + b.x, a.y + b.y); }
__device__ __forceinline__ float2 f2sub(float2 a, float2 b) { return make_float2(a.x - b.x, a.y - b.y); }
__device__ __forceinline__ float2 f2negi(float2 a) { return make_float2(a.y, -a.x); }   // * -i
__device__ __forceinline__ float2 csq(float2 a) { return make_float2(a.x * a.x - a.y * a.y, 2.f * a.x * a.y); }

// ---- float4 = two complex numbers, same twiddle applied to both ----
__device__ __forceinline__ float4 f4add(float4 a, float4 b) {
    return make_float4(a.x + b.x, a.y + b.y, a.z + b.z, a.w + b.w);
}
__device__ __forceinline__ float4 f4sub(float4 a, float4 b) {
    return make_float4(a.x - b.x, a.y - b.y, a.z - b.z, a.w - b.w);
}
__device__ __forceinline__ float4 f4sc(float4 a, float s) {
    return make_float4(a.x * s, a.y * s, a.z * s, a.w * s);
}
__device__ __forceinline__ float4 c4mul(float4 v, float2 w) {
    return make_float4(v.x * w.x - v.y * w.y, v.x * w.y + v.y * w.x,
                       v.z * w.x - v.w * w.y, v.z * w.y + v.w * w.x);
}
__device__ __forceinline__ float4 c4mulc(float4 v, float2 w) {
    return make_float4(v.x * w.x + v.y * w.y, v.y * w.x - v.x * w.y,
                       v.z * w.x + v.w * w.y, v.w * w.x - v.z * w.y);
}
__device__ __forceinline__ float4 c4mulnegi(float4 v) {  // *( -i )
    return make_float4(v.y, -v.x, v.w, -v.z);
}
__device__ __forceinline__ float4 c4mulposi(float4 v) {  // *( +i )
    return make_float4(-v.y, v.x, -v.w, v.z);
}
// SU(2) mux: u = (u00.re, u00.im, u01.re, u01.im); u10=-conj(u01), u11=conj(u00)
__device__ __forceinline__ float4 mux4su(float4 v, float4 u) {
    float4 o;
    o.x = u.x * v.x - u.y * v.y + u.z * v.z - u.w * v.w;
    o.y = u.x * v.y + u.y * v.x + u.z * v.w + u.w * v.z;
    o.z = -u.z * v.x - u.w * v.y + u.x * v.z + u.y * v.w;
    o.w = -u.z * v.y + u.w * v.x + u.x * v.w - u.y * v.z;
    return o;
}

// ---- register-level butterflies (exact template math) ----
__device__ __forceinline__ void inv4q(float4 a, float4 b, float4 c, float4 d,
                                      float2 w0, float s,
                                      float4& o0, float4& o1, float4& o2, float4& o3) {
    float2 w1 = make_float2(w0.y, -w0.x);
    float2 w2 = csq(w0);
    float4 bw = c4mulc(b, w2), dw = c4mulc(d, w2);
    float4 aP = f4add(a, bw), bP = f4sub(a, bw);
    float4 cP = f4add(c, dw), dP = f4sub(c, dw);
    float4 cw = c4mulc(cP, w0), dq = c4mulc(dP, w1);
    o0 = f4sc(f4add(aP, cw), s); o2 = f4sc(f4sub(aP, cw), s);
    o1 = f4sc(f4add(bP, dq), s); o3 = f4sc(f4sub(bP, dq), s);
}
__device__ __forceinline__ void fwd4q(float4 a, float4 b, float4 c, float4 d,
                                      float2 w0,
                                      float4& o0, float4& o1, float4& o2, float4& o3) {
    float2 w1 = make_float2(w0.y, -w0.x);
    float2 w2 = csq(w0);
    float4 ac = f4add(a, c), bd = f4add(b, d);
    float4 cP = c4mul(f4sub(a, c), w0);
    float4 dP = c4mul(f4sub(b, d), w1);
    o0 = f4add(ac, bd);
    o1 = c4mul(f4sub(ac, bd), w2);
    o2 = f4add(cP, dP);
    o3 = c4mul(f4sub(cP, dP), w2);
}
// full 8-point DIF (stages h=4,2,1; natural->bitrev in-block, t=0)
__device__ __forceinline__ void fwd8q(float4* z) {
    const float2 tw16c = make_float2(SQH, -SQH);
    const float2 tw48c = make_float2(-SQH, -SQH);
    float4 s0 = f4add(z[0], z[4]), s1 = f4add(z[1], z[5]);
    float4 s2 = f4add(z[2], z[6]), s3 = f4add(z[3], z[7]);
    float4 t0 = f4sub(z[0], z[4]);
    float4 t1 = c4mul(f4sub(z[1], z[5]), tw16c);
    float4 t2 = c4mulnegi(f4sub(z[2], z[6]));
    float4 t3 = c4mul(f4sub(z[3], z[7]), tw48c);
    float4 m0 = f4add(s0, s2), m2 = f4sub(s0, s2);
    float4 m1 = f4add(s1, s3), m3 = c4mulnegi(f4sub(s1, s3));
    z[0] = f4add(m0, m1); z[1] = f4sub(m0, m1);
    z[2] = f4add(m2, m3); z[3] = f4sub(m2, m3);
    float4 n0 = f4add(t0, t2), n2 = f4sub(t0, t2);
    float4 n1 = f4add(t1, t3), n3 = c4mulnegi(f4sub(t1, t3));
    z[4] = f4add(n0, n1); z[5] = f4sub(n0, n1);
    z[6] = f4add(n2, n3); z[7] = f4sub(n2, n3);
}
// general 8-point DIF block for fwd stages S+2,S+1,S; z[j] at positions t + j*h, w = W(t,8h)
__device__ __forceinline__ void fwd8t(float4* z, float2 w) {
    const float2 w1 = cmul(w, make_float2(SQH, -SQH));
    const float2 w2 = make_float2(w.y, -w.x);
    const float2 w3 = cmul(w, make_float2(-SQH, -SQH));
    const float2 u2 = csq(w);
    const float2 u2m = make_float2(u2.y, -u2.x);
    const float2 v4 = csq(u2);
    float4 s0 = f4add(z[0], z[4]), s1 = f4add(z[1], z[5]);
    float4 s2 = f4add(z[2], z[6]), s3 = f4add(z[3], z[7]);
    float4 t0 = c4mul(f4sub(z[0], z[4]), w);
    float4 t1 = c4mul(f4sub(z[1], z[5]), w1);
    float4 t2 = c4mul(f4sub(z[2], z[6]), w2);
    float4 t3 = c4mul(f4sub(z[3], z[7]), w3);
    float4 a0 = f4add(s0, s2), a2 = c4mul(f4sub(s0, s2), u2);
    float4 a1 = f4add(s1, s3), a3 = c4mul(f4sub(s1, s3), u2m);
    float4 b0 = f4add(t0, t2), b2 = c4mul(f4sub(t0, t2), u2);
    float4 b1 = f4add(t1, t3), b3 = c4mul(f4sub(t1, t3), u2m);
    z[0] = f4add(a0, a1); z[1] = c4mul(f4sub(a0, a1), v4);
    z[2] = f4add(a2, a3); z[3] = c4mul(f4sub(a2, a3), v4);
    z[4] = f4add(b0, b1); z[5] = c4mul(f4sub(b0, b1), v4);
    z[6] = f4add(b2, b3); z[7] = c4mul(f4sub(b2, b3), v4);
}
// 8-point DIT block for inv stages S,S+1,S+2; w = W(t,8h), scale folded
__device__ __forceinline__ void inv8t(float4* z, float2 w, float s) {
    const float2 w1 = cmul(w, make_float2(SQH, -SQH));
    const float2 w2 = make_float2(w.y, -w.x);
    const float2 w3 = cmul(w, make_float2(-SQH, -SQH));
    const float2 u2 = csq(w);
    const float2 u2m = make_float2(u2.y, -u2.x);
    const float2 v4 = csq(u2);
    float4 q1 = c4mulc(z[1], v4), q3 = c4mulc(z[3], v4);
    float4 q5 = c4mulc(z[5], v4), q7 = c4mulc(z[7], v4);
    float4 c0 = f4add(z[0], q1), c1 = f4sub(z[0], q1);
    float4 c2 = f4add(z[2], q3), c3 = f4sub(z[2], q3);
    float4 c4_ = f4add(z[4], q5), c5 = f4sub(z[4], q5);
    float4 c6 = f4add(z[6], q7), c7 = f4sub(z[6], q7);
    float4 r2 = c4mulc(c2, u2), r3 = c4mulc(c3, u2m);
    float4 r6 = c4mulc(c6, u2), r7 = c4mulc(c7, u2m);
    float4 g0 = f4add(c0, r2), g2 = f4sub(c0, r2);
    float4 g1 = f4add(c1, r3), g3 = f4sub(c1, r3);
    float4 g4 = f4add(c4_, r6), g6 = f4sub(c4_, r6);
    float4 g5 = f4add(c5, r7), g7 = f4sub(c5, r7);
    float4 h4 = c4mulc(g4, w), h5 = c4mulc(g5, w1);
    float4 h6 = c4mulc(g6, w2), h7 = c4mulc(g7, w3);
    z[0] = f4sc(f4add(g0, h4), s); z[4] = f4sc(f4sub(g0, h4), s);
    z[1] = f4sc(f4add(g1, h5), s); z[5] = f4sc(f4sub(g1, h5), s);
    z[2] = f4sc(f4add(g2, h6), s); z[6] = f4sc(f4sub(g2, h6), s);
    z[3] = f4sc(f4add(g3, h7), s); z[7] = f4sc(f4sub(g3, h7), s);
}

// =====================================================================
// template sweeps kept for remaining mid-stages
// =====================================================================
template<bool INV, int NTT, int SP, int SL1, int LG1, int SL2, int LG2, int LOGN, int S, bool LAST>
__device__ __forceinline__ void pass4(float4* __restrict__ base,
                                      const float2* __restrict__ tw, float scale) {
    constexpr int L = 1 << (LG1 + LG2);
    constexpr int ITEMS = L << (LOGN - 2);
    constexpr int h = 1 << S;
    for (int u = threadIdx.x; u < ITEMS; u += NTT) {
        const int line = u & (L - 1);
        const int loff = (line & ((1 << LG1) - 1)) * SL1 + (line >> LG1) * SL2;
        const int v = u >> (LG1 + LG2);
        const int t = v & (h - 1);
        const int p = ((v >> S) << (S + 2)) + t;
        float4* e = base + loff + p * SP;
        float4 a = e[0], b = e[h * SP], c = e[2 * h * SP], d = e[3 * h * SP];
        const float2 w0 = tw[t << (5 - S)];
        const float2 w1 = make_float2(w0.y, -w0.x);
        const float2 w2 = csq(w0);
        if constexpr (!INV) {
            float4 ac = f4add(a, c), bd = f4add(b, d);
            float4 cP = c4mul(f4sub(a, c), w0);
            float4 dP = c4mul(f4sub(b, d), w1);
            e[0]          = f4add(ac, bd);
            e[h * SP]     = c4mul(f4sub(ac, bd), w2);
            e[2 * h * SP] = f4add(cP, dP);
            e[3 * h * SP] = c4mul(f4sub(cP, dP), w2);
        } else {
            float4 bw = c4mulc(b, w2), dw = c4mulc(d, w2);
            float4 aP = f4add(a, bw), bP = f4sub(a, bw);
            float4 cP = f4add(c, dw), dP = f4sub(c, dw);
            float4 cw = c4mulc(cP, w0), dq = c4mulc(dP, w1);
            float4 o0 = f4add(aP, cw), o2 = f4sub(aP, cw);
            float4 o1 = f4add(bP, dq), o3 = f4sub(bP, dq);
            if constexpr (LAST) {
                o0 = f4sc(o0, scale); o1 = f4sc(o1, scale);
                o2 = f4sc(o2, scale); o3 = f4sc(o3, scale);
            }
            e[0] = o0; e[h * SP] = o1; e[2 * h * SP] = o2; e[3 * h * SP] = o3;
        }
    }
    __syncthreads();
}

// ---------------- float2 passes (p1 only) ----------------
// 8-point DIF block for stages S+2,S+1,S (float2)
template<int NTT, int SP, int LG1, int LOGN, int S>
__device__ __forceinline__ void pass8s(float2* __restrict__ base,
                                       const float2* __restrict__ tw) {
    constexpr int L = 1 << LG1;
    constexpr int ITEMS = L << (LOGN - 3);
    constexpr int h = 1 << S;
    for (int u = threadIdx.x; u < ITEMS; u += NTT) {
        const int loff = (u & (L - 1));
        const int v = u >> LG1;
        const int t = v & (h - 1);
        const int p = ((v >> S) << (S + 3)) + t;
        float2* e = base + loff + p * SP;
        const float2 w = tw[t << (4 - S)];
        const float2 w1 = cmul(w, make_float2(SQH, -SQH));
        const float2 w2 = make_float2(w.y, -w.x);
        const float2 w3 = cmul(w, make_float2(-SQH, -SQH));
        const float2 u2 = csq(w);
        const float2 u2m = make_float2(u2.y, -u2.x);
        const float2 v4 = csq(u2);
        float2 d0 = e[0],          d1 = e[h * SP],     d2 = e[2 * h * SP], d3 = e[3 * h * SP];
        float2 d4 = e[4 * h * SP], d5 = e[5 * h * SP], d6 = e[6 * h * SP], d7 = e[7 * h * SP];
        float2 s0 = f2add(d0, d4), s1 = f2add(d1, d5), s2 = f2add(d2, d6), s3 = f2add(d3, d7);
        float2 t0 = cmul(f2sub(d0, d4), w);
        float2 t1 = cmul(f2sub(d1, d5), w1);
        float2 t2 = cmul(f2sub(d2, d6), w2);
        float2 t3 = cmul(f2sub(d3, d7), w3);
        float2 a0 = f2add(s0, s2), a2 = cmul(f2sub(s0, s2), u2);
        float2 a1 = f2add(s1, s3), a3 = cmul(f2sub(s1, s3), u2m);
        float2 b0 = f2add(t0, t2), b2 = cmul(f2sub(t0, t2), u2);
        float2 b1 = f2add(t1, t3), b3 = cmul(f2sub(t1, t3), u2m);
        e[0]          = f2add(a0, a1);  e[h * SP]     = cmul(f2sub(a0, a1), v4);
        e[2 * h * SP] = f2add(a2, a3);  e[3 * h * SP] = cmul(f2sub(a2, a3), v4);
        e[4 * h * SP] = f2add(b0, b1);  e[5 * h * SP] = cmul(f2sub(b0, b1), v4);
        e[6 * h * SP] = f2add(b2, b3);  e[7 * h * SP] = cmul(f2sub(b2, b3), v4);
    }
    __syncthreads();
}
template<int NTT, int SP, int LG1, int LOGN, int S>
__device__ __forceinline__ void pass2s(float2* __restrict__ base,
                                       const float2* __restrict__ tw) {
    constexpr int L = 1 << LG1;
    constexpr int ITEMS = L << (LOGN - 1);
    constexpr int h = 1 << S;
    for (int u = threadIdx.x; u < ITEMS; u += NTT) {
        const int loff = (u & (L - 1));
        const int v = u >> LG1;
        const int t = v & (h - 1);
        const int p = ((v >> S) << (S + 1)) + t;
        float2* e = base + loff + p * SP;
        float2 a = e[0], b = e[h * SP];
        const float2 w = tw[t << (6 - S)];
        e[0]      = f2add(a, b);
        e[h * SP] = cmul(f2sub(a, b), w);
    }
    __syncthreads();
}

// ---------------- K0: precompute ----------------
__device__ __forceinline__ void writeU(float4* dst, float axf, float ayf, float azf) {
    double ax = axf, ay = ayf, az = azf;
    double r = sqrt(ax * ax + ay * ay + az * az + 1e-20);
    double cr = cos(r), sn = sin(r) / r;
    // (u00.re, u00.im, u01.re, u01.im); u10/u11 derived by SU(2) symmetry
    dst[0] = make_float4((float)cr, (float)(-az * sn), (float)(-ay * sn), (float)(-ax * sn));
}

__global__ void k0(const float* __restrict__ mux0, const float* __restrict__ mux1,
                   const float* __restrict__ mux2) {
    int idx = blockIdx.x * blockDim.x + threadIdx.x;   // 16384 threads
    if (idx < 64) {
        double ang = -2.0 * PI_D * (double)idx / 128.0;
        g_TW[idx] = make_float2((float)cos(ang), (float)sin(ang));
    }
    if (idx < 128) {
        int k = __brev((unsigned)idx) >> 25;
        g_NR[idx] = (int)(__brev((unsigned)((128 - k) & 127)) >> 25);
    }
    {   // U0: [kxb][kyb]
        int kxb = idx >> 7, kyb = idx & 127;
        int kx = __brev((unsigned)kxb) >> 25, ky = __brev((unsigned)kyb) >> 25;
        const float* c = mux0 + (kx * 128 + ky) * 3;
        writeU(&g_U0[idx], c[0], c[1], c[2]);
    }
    {   // U1: TRANSPOSED [cx][cy][kyb][kxb]
        int cx = idx >> 13, cy = (idx >> 12) & 1, kxb = (idx >> 6) & 63, kyb = idx & 63;
        int kx = __brev((unsigned)kxb) >> 26, ky = __brev((unsigned)kyb) >> 26;
        const float* c = mux1 + (((cx * 2 + cy) * 64 + kx) * 64 + ky) * 3;
        int tidx = (cx << 13) + (cy << 12) + (kyb << 6) + kxb;
        writeU(&g_U1[tidx], c[0], c[1], c[2]);
    }
    if (idx < 4096) {   // U2: TRANSPOSED [cx][cy][kyb][kxb]
        int cx = idx >> 11, cy = (idx >> 10) & 1, kxb = (idx >> 5) & 31, kyb = idx & 31;
        int kx = __brev((unsigned)kxb) >> 27, ky = __brev((unsigned)kyb) >> 27;
        const float* c = mux2 + (((cx * 2 + cy) * 32 + kx) * 32 + ky) * 3;
        int tidx = (cx << 11) + (cy << 10) + (kyb << 5) + kxb;
        writeU(&g_U2[tidx], c[0], c[1], c[2]);
    }
}

// ---------------- P1: encode + y-FFT128 (Hermitian packed) ----------------
#define NT1 512
__global__ __launch_bounds__(NT1) void p1(const float* __restrict__ images) {
    __shared__ float2 z[128 * 33];
    __shared__ float2 tw[64];
    const int b = blockIdx.y, X0 = blockIdx.x * 32;
    for (int i = threadIdx.x; i < 64; i += NT1) tw[i] = g_TW[i];
    for (int idx = threadIdx.x; idx < 4096; idx += NT1) {
        int l = idx >> 7, y = idx & 127;
        float I = images[(b * 128 + X0 + l) * 128 + y];
        float sv, cv;
        sincosf(0.5f * (float)PI_D * I, &sv, &cv);
        z[y * 33 + l] = make_float2(cv * (1.0f / 128.0f), sv * (1.0f / 128.0f));
    }
    __syncthreads();
    pass8s<NT1, 33, 5, 7, 4>(z, tw);   // stages 6,5,4
    pass8s<NT1, 33, 5, 7, 1>(z, tw);   // stages 3,2,1
    pass2s<NT1, 33, 5, 7, 0>(z, tw);   // stage 0
    for (int idx = threadIdx.x; idx < 4096; idx += NT1) {
        int l = idx >> 7, kb = idx & 127;
        float2 Z = z[kb * 33 + l];
        float2 Zn = z[g_NR[kb] * 33 + l];
        float2 C  = make_float2(0.5f * (Z.x + Zn.x), 0.5f * (Z.y - Zn.y));
        float2 Sf = make_float2(0.5f * (Z.y + Zn.y), 0.5f * (Zn.x - Z.x));
        int X = X0 + l;
        g_S4[(b * 128 + X) * 128 + kb] = make_float4(C.x, C.y, Sf.x, Sf.y);
    }
}

// ---------------- P2: x-FFT128 + mux0 + x-IFFT128 + x-FFT64(halves) ----------------
#define NT2 512
__global__ __launch_bounds__(NT2) void p2() {
    __shared__ float4 tile[128 * 16];
    __shared__ float2 tw[64];
    const int b = blockIdx.y, y0 = blockIdx.x * 16;
    for (int i = threadIdx.x; i < 64; i += NT2) tw[i] = g_TW[i];
    __syncthreads();
    // fused: fwd128 stages 6,5 reading directly from global
    for (int u = threadIdx.x; u < 512; u += NT2) {
        int yl = u & 15, v = u >> 4;                 // v in [0,32) = position
        const float4* g = &g_S4[(b * 128 + v) * 128 + y0 + yl];
        float4 a = g[0], bb = g[32 * 128], c = g[64 * 128], d = g[96 * 128];
        float4 r0, r1, r2, r3;
        fwd4q(a, bb, c, d, tw[v], r0, r1, r2, r3);
        float4* e = tile + v * 16 + yl;
        e[0] = r0; e[32 * 16] = r1; e[64 * 16] = r2; e[96 * 16] = r3;
    }
    __syncthreads();
    // fwd128 stages 4,3,2 (8-pt DIF blocks of 32, t in [0,4))
    for (int u = threadIdx.x; u < 256; u += NT2) {
        int yl = u & 15, r = u >> 4;                 // r in [0,16)
        int blk = r >> 2, t = r & 3;
        float4* e = tile + (blk * 32 + t) * 16 + yl;
        float4 z[8];
        #pragma unroll
        for (int j = 0; j < 8; ++j) z[j] = e[j * 64];
        fwd8t(z, tw[t << 2]);
        #pragma unroll
        for (int j = 0; j < 8; ++j) e[j * 64] = z[j];
    }
    __syncthreads();
    // fused: fwd128 stages 1,0 (t=0 quad) + mux0
    for (int u = threadIdx.x; u < 512; u += NT2) {
        int yl = u & 15, v = u >> 4;                 // v in [0,32)
        float4* e = tile + (4 * v) * 16 + yl;
        float4 r0, r1, r2, r3;
        fwd4q(e[0], e[16], e[32], e[48], make_float2(1.f, 0.f), r0, r1, r2, r3);
        int i0 = ((4 * v) << 7) + y0 + yl;
        e[0]  = mux4su(r0, g_U0[i0]);
        e[16] = mux4su(r1, g_U0[i0 + 128]);
        e[32] = mux4su(r2, g_U0[i0 + 256]);
        e[48] = mux4su(r3, g_U0[i0 + 384]);
    }
    __syncthreads();
    // inv128 stages 0,1,2 (8 consecutive positions, t=0)
    for (int u = threadIdx.x; u < 256; u += NT2) {
        int yl = u & 15, v = u >> 4;                 // v in [0,16)
        float4* e = tile + (8 * v) * 16 + yl;
        float4 z[8];
        #pragma unroll
        for (int j = 0; j < 8; ++j) z[j] = e[j * 16];
        inv8t(z, make_float2(1.f, 0.f), 1.f);
        #pragma unroll
        for (int j = 0; j < 8; ++j) e[j * 16] = z[j];
    }
    __syncthreads();
    // inv128 stages 3,4,5 (stride 8, blocks of 64)
    for (int u = threadIdx.x; u < 256; u += NT2) {
        int yl = u & 15, blk = (u >> 4) & 1, t = u >> 5;  // t in [0,8)
        float4* e = tile + (blk * 64 + t) * 16 + yl;
        float4 z[8];
        #pragma unroll
        for (int j = 0; j < 8; ++j) z[j] = e[j * 8 * 16];
        inv8t(z, tw[2 * t], 1.f);
        #pragma unroll
        for (int j = 0; j < 8; ++j) e[j * 8 * 16] = z[j];
    }
    __syncthreads();
    // FUSION D: inv128 stage 6 (scale 1/128) + fwd64 stages h=32,16
    for (int u = threadIdx.x; u < 256; u += NT2) {
        int yl = u & 15, t = u >> 4;                 // t in [0,16)
        float4* e = tile + yl;
        float4 p0[4], p1[4];
        #pragma unroll
        for (int k = 0; k < 4; ++k) {
            float4 a = e[(t + 16 * k) * 16], bq = e[(t + 64 + 16 * k) * 16];
            float4 bw = c4mulc(bq, tw[t + 16 * k]);
            p0[k] = f4sc(f4add(a, bw), 1.0f / 128.0f);
            p1[k] = f4sc(f4sub(a, bw), 1.0f / 128.0f);
        }
        const float2 wf = tw[2 * t];
        float4 r0, r1, r2, r3;
        fwd4q(p0[0], p0[1], p0[2], p0[3], wf, r0, r1, r2, r3);
        e[t * 16] = r0; e[(t + 16) * 16] = r1; e[(t + 32) * 16] = r2; e[(t + 48) * 16] = r3;
        fwd4q(p1[0], p1[1], p1[2], p1[3], wf, r0, r1, r2, r3);
        e[(t + 64) * 16] = r0; e[(t + 80) * 16] = r1; e[(t + 96) * 16] = r2; e[(t + 112) * 16] = r3;
    }
    __syncthreads();
    // fwd64 halves: h=8,4, then fused h=2,1 + global store
    pass4<false, NT2, 16, 1, 4, 1024, 1, 6, 2, false>(tile, tw, 1.f);
    for (int u = threadIdx.x; u < 512; u += NT2) {
        int yl = u & 15, half = (u >> 4) & 1, v = u >> 5;   // v in [0,16)
        float4* e = tile + half * 1024 + (4 * v) * 16 + yl;
        float4 a = e[0], bb = e[16], c = e[32], d = e[48];
        float4 ac = f4add(a, c), bd = f4add(bb, d);
        float4 cP = f4sub(a, c);
        float4 dP = c4mulnegi(f4sub(bb, d));
        int Xb = half * 64 + 4 * v;
        float4* g = &g_S4[(b * 128 + Xb) * 128 + y0 + yl];
        g[0]   = f4add(ac, bd);
        g[128] = f4sub(ac, bd);
        g[256] = f4add(cP, dP);
        g[384] = f4sub(cP, dP);
    }
}

// ---------------- P35 ----------------
#define NT3 1024
#define P35_SMEM (132096 + 512 + 16896 + 1280)
__global__ __launch_bounds__(NT3) void p35(const float* __restrict__ W) {
    extern __shared__ char sm[];
    float4* tile = (float4*)sm;                            // [64 X][129] float4
    float2* tw   = (float2*)(sm + 132096);
    float*  prob = (float*)(sm + 132096 + 512);            // [2 f][64 X][33 pitch]
    float*  red  = (float*)(sm + 132096 + 512 + 16896);    // 32*10 f32
    const int b = blockIdx.y, xc1 = blockIdx.x;
    for (int i = threadIdx.x; i < 64; i += NT3) tw[i] = g_TW[i];
    __syncthreads();
    // inv128-y stages 0,1,2 reading directly from global (8 consecutive y, t=0)
    for (int u = threadIdx.x; u < 1024; u += NT3) {
        int X = u & 63, v = u >> 6;                        // v in [0,16)
        const float4* g = &g_S4[(b * 128 + xc1 * 64 + X) * 128 + 8 * v];
        float4 z[8];
        #pragma unroll
        for (int j = 0; j < 8; ++j) z[j] = g[j];
        inv8t(z, make_float2(1.f, 0.f), 1.f);
        float4* e = tile + X * 129 + 8 * v;
        #pragma unroll
        for (int j = 0; j < 8; ++j) e[j] = z[j];
    }
    __syncthreads();
    // inv128-y stages 3,4,5 (stride 8, blocks of 64)
    for (int u = threadIdx.x; u < 1024; u += NT3) {
        int X = u & 63, blk = (u >> 6) & 1, t = u >> 7;    // t in [0,8)
        float4* e = tile + X * 129 + blk * 64 + t;
        float4 z[8];
        #pragma unroll
        for (int j = 0; j < 8; ++j) z[j] = e[8 * j];
        inv8t(z, tw[2 * t], 1.f);
        #pragma unroll
        for (int j = 0; j < 8; ++j) e[8 * j] = z[j];
    }
    __syncthreads();
    // FUSION A: inv128-y stage 6 (scale 1/128) + fwd64-y stages h=32,16
    for (int u = threadIdx.x; u < 1024; u += NT3) {
        int X = u & 63, t = u >> 6;                        // t in [0,16)
        float4* e = tile + X * 129;
        float4 p0[4], p1[4];
        #pragma unroll
        for (int k = 0; k < 4; ++k) {
            float4 a = e[t + 16 * k], bq = e[t + 64 + 16 * k];
            float4 bw = c4mulc(bq, tw[t + 16 * k]);
            p0[k] = f4sc(f4add(a, bw), 1.0f / 128.0f);
            p1[k] = f4sc(f4sub(a, bw), 1.0f / 128.0f);
        }
        const float2 wf = tw[2 * t];
        float4 r0, r1, r2, r3;
        fwd4q(p0[0], p0[1], p0[2], p0[3], wf, r0, r1, r2, r3);
        e[t] = r0; e[t + 16] = r1; e[t + 32] = r2; e[t + 48] = r3;
        fwd4q(p1[0], p1[1], p1[2], p1[3], wf, r0, r1, r2, r3);
        e[t + 64] = r0; e[t + 80] = r1; e[t + 96] = r2; e[t + 112] = r3;
    }
    __syncthreads();
    // fwd64 y halves: h=8,4, then fused h=2,1 + mux1
    pass4<false, NT3, 1, 129, 6, 64, 1, 6, 2, false>(tile, tw, 1.f);
    for (int u = threadIdx.x; u < 2048; u += NT3) {
        int X = u & 63, half = (u >> 6) & 1, v = u >> 7;   // v in [0,16)
        float4* e = tile + X * 129 + half * 64 + 4 * v;
        float4 r0, r1, r2, r3;
        fwd4q(e[0], e[1], e[2], e[3], make_float2(1.f, 0.f), r0, r1, r2, r3);
        int ub = ((xc1 * 2 + half) << 12) + ((4 * v) << 6) + X;
        e[0] = mux4su(r0, g_U1[ub]);
        e[1] = mux4su(r1, g_U1[ub + 64]);
        e[2] = mux4su(r2, g_U1[ub + 128]);
        e[3] = mux4su(r3, g_U1[ub + 192]);
    }
    __syncthreads();
    // x junction: inv64-x stages 0,1,2 (8 consecutive X, t=0)
    for (int u = threadIdx.x; u < 1024; u += NT3) {
        int y = u & 127, m = u >> 7;                       // m in [0,8)
        float4* e = tile + (8 * m) * 129 + y;
        float4 z[8];
        #pragma unroll
        for (int j = 0; j < 8; ++j) z[j] = e[j * 129];
        inv8t(z, make_float2(1.f, 0.f), 1.f);
        #pragma unroll
        for (int j = 0; j < 8; ++j) e[j * 129] = z[j];
    }
    __syncthreads();
    // FUSION B': inv64-x stages 3,4,5 (scale 1/64) + fwd32-x stages h=16,8
    for (int u = threadIdx.x; u < 1024; u += NT3) {
        int y = u & 127, t = u >> 7;                       // t in [0,8)
        float4* e = tile + t * 129 + y;
        float4 z[8];
        #pragma unroll
        for (int j = 0; j < 8; ++j) z[j] = e[8 * j * 129];
        inv8t(z, tw[2 * t], 1.0f / 64.0f);
        const float2 wf = tw[4 * t];
        float4 r0, r1, r2, r3;
        fwd4q(z[0], z[1], z[2], z[3], wf, r0, r1, r2, r3);
        e[0] = r0; e[8 * 129] = r1; e[16 * 129] = r2; e[24 * 129] = r3;
        fwd4q(z[4], z[5], z[6], z[7], wf, r0, r1, r2, r3);
        e[32 * 129] = r0; e[40 * 129] = r1; e[48 * 129] = r2; e[56 * 129] = r3;
    }
    __syncthreads();
    // MERGE P: fwd32-x stages h=4,2,1 (8-pt DIF)
    for (int u = threadIdx.x; u < 1024; u += NT3) {
        int y = u & 127, r = u >> 7;                       // r in [0,8)
        int m = r & 3, xs = r >> 2;
        float4* e = tile + (xs * 32 + 8 * m) * 129 + y;
        float4 z[8];
        #pragma unroll
        for (int j = 0; j < 8; ++j) z[j] = e[j * 129];
        fwd8q(z);
        #pragma unroll
        for (int j = 0; j < 8; ++j) e[j * 129] = z[j];
    }
    __syncthreads();
    // y junction: inv64-y stages 0,1,2 (8 consecutive y within halves, t=0)
    for (int u = threadIdx.x; u < 1024; u += NT3) {
        int X = u & 63, half = (u >> 6) & 1, m = u >> 7;   // m in [0,8)
        float4* e = tile + X * 129 + half * 64 + 8 * m;
        float4 z[8];
        #pragma unroll
        for (int j = 0; j < 8; ++j) z[j] = e[j];
        inv8t(z, make_float2(1.f, 0.f), 1.f);
        #pragma unroll
        for (int j = 0; j < 8; ++j) e[j] = z[j];
    }
    __syncthreads();
    // FUSION C': inv64-y stages 3,4,5 (scale 1/64) + fwd32-y stages h=16,8
    for (int u = threadIdx.x; u < 1024; u += NT3) {
        int X = u & 63, half = (u >> 6) & 1, t = u >> 7;   // t in [0,8)
        float4* e = tile + X * 129 + half * 64 + t;
        float4 z[8];
        #pragma unroll
        for (int j = 0; j < 8; ++j) z[j] = e[8 * j];
        inv8t(z, tw[2 * t], 1.0f / 64.0f);
        const float2 wf = tw[4 * t];
        float4 r0, r1, r2, r3;
        fwd4q(z[0], z[1], z[2], z[3], wf, r0, r1, r2, r3);
        e[0] = r0; e[8] = r1; e[16] = r2; e[24] = r3;
        fwd4q(z[4], z[5], z[6], z[7], wf, r0, r1, r2, r3);
        e[32] = r0; e[40] = r1; e[48] = r2; e[56] = r3;
    }
    __syncthreads();
    // MERGE Q: fwd32-y stages h=4,2,1 + mux2
    for (int u = threadIdx.x; u < 1024; u += NT3) {
        int X = u & 63, r = u >> 6;                        // r in [0,16)
        int seg = r & 3, m = r >> 2;
        float4* e = tile + X * 129 + seg * 32 + 8 * m;
        float4 z[8];
        #pragma unroll
        for (int j = 0; j < 8; ++j) z[j] = e[j];
        fwd8q(z);
        int xc2 = X >> 5, yc2 = seg & 1;
        int ubase = ((xc2 * 2 + yc2) << 10) + ((8 * m) << 5) + (X & 31);
        #pragma unroll
        for (int j = 0; j < 8; ++j)
            e[j] = mux4su(z[j], g_U2[ubase + 32 * j]);
    }
    __syncthreads();
    // final x inv32: pass4 stages 0,1, then MERGE R (stages 2,3,4 + scale 1/32)
    pass4<true, NT3, 129, 1, 7, 4128, 1, 5, 0, false>(tile, tw, 1.f);
    for (int u = threadIdx.x; u < 1024; u += NT3) {
        int y = u & 127, r = u >> 7;                       // r in [0,8)
        int t = r & 3, xs = r >> 2;
        float4* e = tile + (xs * 32 + t) * 129 + y;
        float4 z[8];
        #pragma unroll
        for (int j = 0; j < 8; ++j) z[j] = e[4 * j * 129];
        inv8t(z, tw[4 * t], 1.0f / 32.0f);
        #pragma unroll
        for (int j = 0; j < 8; ++j) e[4 * j * 129] = z[j];
    }
    __syncthreads();
    // final y inv32: stages 0,1,2 (8 consecutive within segs, t=0)
    for (int u = threadIdx.x; u < 1024; u += NT3) {
        int X = u & 63, seg = (u >> 6) & 3, m = u >> 8;    // m in [0,4)
        float4* e = tile + X * 129 + seg * 32 + 8 * m;
        float4 z[8];
        #pragma unroll
        for (int j = 0; j < 8; ++j) z[j] = e[j];
        inv8t(z, make_float2(1.f, 0.f), 1.f);
        #pragma unroll
        for (int j = 0; j < 8; ++j) e[j] = z[j];
    }
    __syncthreads();
    // measure': final y inv32 stages 3,4 (inv4q, scale 1/32) + |.|^2 accumulate over segs
    for (int u = threadIdx.x; u < 512; u += NT3) {
        int X = u & 63, t = u >> 6;                        // t in [0,8)
        const float2 w0 = tw[4 * t];
        float s0[4], s1[4];
        #pragma unroll
        for (int j = 0; j < 4; ++j) { s0[j] = 0.f; s1[j] = 0.f; }
        #pragma unroll
        for (int seg = 0; seg < 4; ++seg) {
            const float4* e = tile + X * 129 + seg * 32 + t;
            float4 o0, o1, o2, o3;
            inv4q(e[0], e[8], e[16], e[24], w0, 1.0f / 32.0f, o0, o1, o2, o3);
            s0[0] += o0.x * o0.x + o0.y * o0.y;  s1[0] += o0.z * o0.z + o0.w * o0.w;
            s0[1] += o1.x * o1.x + o1.y * o1.y;  s1[1] += o1.z * o1.z + o1.w * o1.w;
            s0[2] += o2.x * o2.x + o2.y * o2.y;  s1[2] += o2.z * o2.z + o2.w * o2.w;
            s0[3] += o3.x * o3.x + o3.y * o3.y;  s1[3] += o3.z * o3.z + o3.w * o3.w;
        }
        #pragma unroll
        for (int j = 0; j < 4; ++j) {
            prob[X * 33 + t + 8 * j]        = s0[j];
            prob[2112 + X * 33 + t + 8 * j] = s1[j];
        }
    }
    __syncthreads();
    // partial GEMV: lanes ya-fastest stride 1 -> conflict-free
    float acc[10];
    #pragma unroll
    for (int c = 0; c < 10; ++c) acc[c] = 0.f;
    {
        int xa = threadIdx.x >> 5, ya = threadIdx.x & 31;
        float p0 = prob[xa * 33 + ya]        + prob[(xa + 32) * 33 + ya];
        float p1 = prob[2112 + xa * 33 + ya] + prob[2112 + (xa + 32) * 33 + ya];
        int j0 = threadIdx.x * 2;
        #pragma unroll
        for (int c = 0; c < 10; ++c) {
            float2 wv = *(const float2*)(W + c * 2048 + j0);
            acc[c] = fmaf(p0, wv.x, fmaf(p1, wv.y, acc[c]));
        }
    }
    #pragma unroll
    for (int c = 0; c < 10; ++c)
        #pragma unroll
        for (int o = 16; o > 0; o >>= 1)
            acc[c] += __shfl_down_sync(0xffffffffu, acc[c], o);
    const int warp = threadIdx.x >> 5, lane = threadIdx.x & 31;
    if (lane == 0)
        #pragma unroll
        for (int c = 0; c < 10; ++c) red[warp * 10 + c] = acc[c];
    __syncthreads();
    if (threadIdx.x < 10) {
        float s = 0.f;
        #pragma unroll
        for (int w = 0; w < 32; ++w) s += red[w * 10 + threadIdx.x];
        g_part[(b * 2 + xc1) * 10 + threadIdx.x] = s;
    }
}

// ---------------- combine ----------------
__global__ void pc(const float* __restrict__ bias, float* __restrict__ out) {
    int i = blockIdx.x * blockDim.x + threadIdx.x;
    if (i < 5120) {
        int b = i / 10, c = i % 10;
        out[i] = bias[c] + g_part[(b * 2) * 10 + c] + g_part[(b * 2 + 1) * 10 + c];
    }
}

// ---------------- launch ----------------
extern "C" void kernel_launch(void* const* d_in, const int* in_sizes, int n_in,
                              void* d_out, int out_size) {
    const float* images = (const float*)d_in[0];
    const float* mux0 = (const float*)d_in[1];
    const float* mux1 = (const float*)d_in[2];
    const float* mux2 = (const float*)d_in[3];
    const float* W = (const float*)d_in[4];
    const float* bias = (const float*)d_in[5];
    float* out = (float*)d_out;
    (void)in_sizes; (void)n_in; (void)out_size;

    cudaFuncSetAttribute(p35, cudaFuncAttributeMaxDynamicSharedMemorySize, P35_SMEM);

    k0<<<64, 256>>>(mux0, mux1, mux2);
    p1<<<dim3(4, 512), NT1>>>(images);
    p2<<<dim3(8, 512), NT2>>>();
    p35<<<dim3(2, 512), NT3, P35_SMEM>>>(W);
    pc<<<10, 512>>>(bias, out);
}

// round 17
// speedup vs baseline: 1.3362x; 1.0129x over previous
#include <cuda_runtime.h>
#include <math.h>

#define PI_D 3.14159265358979323846
#define SQH 0.70710678118654752440f

// ---------------- static device scratch ----------------
__device__ float4 g_S4[512 * 128 * 128];      // state [b][X][Y], float4 = (f0, f1) complex pair
__device__ float4 g_U0[128 * 128];            // mux0 SU(2)-compressed (u00,u01), bitrev [kxb][kyb]
__device__ float4 g_U1[2 * 2 * 64 * 64];      // mux1 compressed, TRANSPOSED [cx][cy][kyb][kxb]
__device__ float4 g_U2[2 * 2 * 32 * 32];      // mux2 compressed, TRANSPOSED [cx][cy][kyb][kxb]
__device__ float2 g_TW[64];                   // exp(-2*pi*i*t/128)
__device__ float  g_part[512 * 2 * 10];       // partial logits per (b, xc1)

// ---- float2 complex helpers ----
__device__ __forceinline__ float2 cmul(float2 a, float2 b) {
    return make_float2(a.x * b.x - a.y * b.y, a.x * b.y + a.y * b.x);
}
__device__ __forceinline__ float2 f2add(float2 a, float2 b) { return make_float2(a.x + b.x, a.y + b.y); }
__device__ __forceinline__ float2 f2sub(float2 a, float2 b) { return make_float2(a.x - b.x, a.y - b.y); }
__device__ __forceinline__ float2 f2negi(float2 a) { return make_float2(a.y, -a.x); }
__device__ __forceinline__ float2 csq(float2 a) { return make_float2(a.x * a.x - a.y * a.y, 2.f * a.x * a.y); }

// ---- float4 = two complex numbers, same twiddle applied to both ----
__device__ __forceinline__ float4 f4add(float4 a, float4 b) {
    return make_float4(a.x + b.x, a.y + b.y, a.z + b.z, a.w + b.w);
}
__device__ __forceinline__ float4 f4sub(float4 a, float4 b) {
    return make_float4(a.x - b.x, a.y - b.y, a.z - b.z, a.w - b.w);
}
__device__ __forceinline__ float4 f4sc(float4 a, float s) {
    return make_float4(a.x * s, a.y * s, a.z * s, a.w * s);
}
__device__ __forceinline__ float4 c4mul(float4 v, float2 w) {
    return make_float4(v.x * w.x - v.y * w.y, v.x * w.y + v.y * w.x,
                       v.z * w.x - v.w * w.y, v.z * w.y + v.w * w.x);
}
__device__ __forceinline__ float4 c4mulc(float4 v, float2 w) {
    return make_float4(v.x * w.x + v.y * w.y, v.y * w.x - v.x * w.y,
                       v.z * w.x + v.w * w.y, v.w * w.x - v.z * w.y);
}
__device__ __forceinline__ float4 c4mulnegi(float4 v) {  // *( -i )
    return make_float4(v.y, -v.x, v.w, -v.z);
}
// SU(2) mux: u = (u00.re, u00.im, u01.re, u01.im); u10=-conj(u01), u11=conj(u00)
__device__ __forceinline__ float4 mux4su(float4 v, float4 u) {
    float4 o;
    o.x = u.x * v.x - u.y * v.y + u.z * v.z - u.w * v.w;
    o.y = u.x * v.y + u.y * v.x + u.z * v.w + u.w * v.z;
    o.z = -u.z * v.x - u.w * v.y + u.x * v.z + u.y * v.w;
    o.w = -u.z * v.y + u.w * v.x + u.x * v.w - u.y * v.z;
    return o;
}

// ---- register-level butterflies (exact template math) ----
__device__ __forceinline__ void inv4q(float4 a, float4 b, float4 c, float4 d,
                                      float2 w0, float s,
                                      float4& o0, float4& o1, float4& o2, float4& o3) {
    float2 w1 = make_float2(w0.y, -w0.x);
    float2 w2 = csq(w0);
    float4 bw = c4mulc(b, w2), dw = c4mulc(d, w2);
    float4 aP = f4add(a, bw), bP = f4sub(a, bw);
    float4 cP = f4add(c, dw), dP = f4sub(c, dw);
    float4 cw = c4mulc(cP, w0), dq = c4mulc(dP, w1);
    o0 = f4sc(f4add(aP, cw), s); o2 = f4sc(f4sub(aP, cw), s);
    o1 = f4sc(f4add(bP, dq), s); o3 = f4sc(f4sub(bP, dq), s);
}
__device__ __forceinline__ void fwd4q(float4 a, float4 b, float4 c, float4 d,
                                      float2 w0,
                                      float4& o0, float4& o1, float4& o2, float4& o3) {
    float2 w1 = make_float2(w0.y, -w0.x);
    float2 w2 = csq(w0);
    float4 ac = f4add(a, c), bd = f4add(b, d);
    float4 cP = c4mul(f4sub(a, c), w0);
    float4 dP = c4mul(f4sub(b, d), w1);
    o0 = f4add(ac, bd);
    o1 = c4mul(f4sub(ac, bd), w2);
    o2 = f4add(cP, dP);
    o3 = c4mul(f4sub(cP, dP), w2);
}
// full 8-point DIF (stages h=4,2,1; natural->bitrev in-block, t=0)
__device__ __forceinline__ void fwd8q(float4* z) {
    const float2 tw16c = make_float2(SQH, -SQH);
    const float2 tw48c = make_float2(-SQH, -SQH);
    float4 s0 = f4add(z[0], z[4]), s1 = f4add(z[1], z[5]);
    float4 s2 = f4add(z[2], z[6]), s3 = f4add(z[3], z[7]);
    float4 t0 = f4sub(z[0], z[4]);
    float4 t1 = c4mul(f4sub(z[1], z[5]), tw16c);
    float4 t2 = c4mulnegi(f4sub(z[2], z[6]));
    float4 t3 = c4mul(f4sub(z[3], z[7]), tw48c);
    float4 m0 = f4add(s0, s2), m2 = f4sub(s0, s2);
    float4 m1 = f4add(s1, s3), m3 = c4mulnegi(f4sub(s1, s3));
    z[0] = f4add(m0, m1); z[1] = f4sub(m0, m1);
    z[2] = f4add(m2, m3); z[3] = f4sub(m2, m3);
    float4 n0 = f4add(t0, t2), n2 = f4sub(t0, t2);
    float4 n1 = f4add(t1, t3), n3 = c4mulnegi(f4sub(t1, t3));
    z[4] = f4add(n0, n1); z[5] = f4sub(n0, n1);
    z[6] = f4add(n2, n3); z[7] = f4sub(n2, n3);
}
// general 8-point DIF block for fwd stages S+2,S+1,S; z[j] at positions t + j*h, w = W(t,8h)
__device__ __forceinline__ void fwd8t(float4* z, float2 w) {
    const float2 w1 = cmul(w, make_float2(SQH, -SQH));
    const float2 w2 = make_float2(w.y, -w.x);
    const float2 w3 = cmul(w, make_float2(-SQH, -SQH));
    const float2 u2 = csq(w);
    const float2 u2m = make_float2(u2.y, -u2.x);
    const float2 v4 = csq(u2);
    float4 s0 = f4add(z[0], z[4]), s1 = f4add(z[1], z[5]);
    float4 s2 = f4add(z[2], z[6]), s3 = f4add(z[3], z[7]);
    float4 t0 = c4mul(f4sub(z[0], z[4]), w);
    float4 t1 = c4mul(f4sub(z[1], z[5]), w1);
    float4 t2 = c4mul(f4sub(z[2], z[6]), w2);
    float4 t3 = c4mul(f4sub(z[3], z[7]), w3);
    float4 a0 = f4add(s0, s2), a2 = c4mul(f4sub(s0, s2), u2);
    float4 a1 = f4add(s1, s3), a3 = c4mul(f4sub(s1, s3), u2m);
    float4 b0 = f4add(t0, t2), b2 = c4mul(f4sub(t0, t2), u2);
    float4 b1 = f4add(t1, t3), b3 = c4mul(f4sub(t1, t3), u2m);
    z[0] = f4add(a0, a1); z[1] = c4mul(f4sub(a0, a1), v4);
    z[2] = f4add(a2, a3); z[3] = c4mul(f4sub(a2, a3), v4);
    z[4] = f4add(b0, b1); z[5] = c4mul(f4sub(b0, b1), v4);
    z[6] = f4add(b2, b3); z[7] = c4mul(f4sub(b2, b3), v4);
}
// 8-point DIT block for inv stages S,S+1,S+2; w = W(t,8h), scale folded
__device__ __forceinline__ void inv8t(float4* z, float2 w, float s) {
    const float2 w1 = cmul(w, make_float2(SQH, -SQH));
    const float2 w2 = make_float2(w.y, -w.x);
    const float2 w3 = cmul(w, make_float2(-SQH, -SQH));
    const float2 u2 = csq(w);
    const float2 u2m = make_float2(u2.y, -u2.x);
    const float2 v4 = csq(u2);
    float4 q1 = c4mulc(z[1], v4), q3 = c4mulc(z[3], v4);
    float4 q5 = c4mulc(z[5], v4), q7 = c4mulc(z[7], v4);
    float4 c0 = f4add(z[0], q1), c1 = f4sub(z[0], q1);
    float4 c2 = f4add(z[2], q3), c3 = f4sub(z[2], q3);
    float4 c4_ = f4add(z[4], q5), c5 = f4sub(z[4], q5);
    float4 c6 = f4add(z[6], q7), c7 = f4sub(z[6], q7);
    float4 r2 = c4mulc(c2, u2), r3 = c4mulc(c3, u2m);
    float4 r6 = c4mulc(c6, u2), r7 = c4mulc(c7, u2m);
    float4 g0 = f4add(c0, r2), g2 = f4sub(c0, r2);
    float4 g1 = f4add(c1, r3), g3 = f4sub(c1, r3);
    float4 g4 = f4add(c4_, r6), g6 = f4sub(c4_, r6);
    float4 g5 = f4add(c5, r7), g7 = f4sub(c5, r7);
    float4 h4 = c4mulc(g4, w), h5 = c4mulc(g5, w1);
    float4 h6 = c4mulc(g6, w2), h7 = c4mulc(g7, w3);
    z[0] = f4sc(f4add(g0, h4), s); z[4] = f4sc(f4sub(g0, h4), s);
    z[1] = f4sc(f4add(g1, h5), s); z[5] = f4sc(f4sub(g1, h5), s);
    z[2] = f4sc(f4add(g2, h6), s); z[6] = f4sc(f4sub(g2, h6), s);
    z[3] = f4sc(f4add(g3, h7), s); z[7] = f4sc(f4sub(g3, h7), s);
}
// float2 general 8-point DIF (for p1)
__device__ __forceinline__ void fwd8t2(float2* z, float2 w) {
    const float2 w1 = cmul(w, make_float2(SQH, -SQH));
    const float2 w2 = make_float2(w.y, -w.x);
    const float2 w3 = cmul(w, make_float2(-SQH, -SQH));
    const float2 u2 = csq(w);
    const float2 u2m = make_float2(u2.y, -u2.x);
    const float2 v4 = csq(u2);
    float2 s0 = f2add(z[0], z[4]), s1 = f2add(z[1], z[5]);
    float2 s2 = f2add(z[2], z[6]), s3 = f2add(z[3], z[7]);
    float2 t0 = cmul(f2sub(z[0], z[4]), w);
    float2 t1 = cmul(f2sub(z[1], z[5]), w1);
    float2 t2 = cmul(f2sub(z[2], z[6]), w2);
    float2 t3 = cmul(f2sub(z[3], z[7]), w3);
    float2 a0 = f2add(s0, s2), a2 = cmul(f2sub(s0, s2), u2);
    float2 a1 = f2add(s1, s3), a3 = cmul(f2sub(s1, s3), u2m);
    float2 b0 = f2add(t0, t2), b2 = cmul(f2sub(t0, t2), u2);
    float2 b1 = f2add(t1, t3), b3 = cmul(f2sub(t1, t3), u2m);
    z[0] = f2add(a0, a1); z[1] = cmul(f2sub(a0, a1), v4);
    z[2] = f2add(a2, a3); z[3] = cmul(f2sub(a2, a3), v4);
    z[4] = f2add(b0, b1); z[5] = cmul(f2sub(b0, b1), v4);
    z[6] = f2add(b2, b3); z[7] = cmul(f2sub(b2, b3), v4);
}

// =====================================================================
// template sweeps kept for remaining mid-stages
// =====================================================================
template<bool INV, int NTT, int SP, int SL1, int LG1, int SL2, int LG2, int LOGN, int S, bool LAST>
__device__ __forceinline__ void pass4(float4* __restrict__ base,
                                      const float2* __restrict__ tw, float scale) {
    constexpr int L = 1 << (LG1 + LG2);
    constexpr int ITEMS = L << (LOGN - 2);
    constexpr int h = 1 << S;
    for (int u = threadIdx.x; u < ITEMS; u += NTT) {
        const int line = u & (L - 1);
        const int loff = (line & ((1 << LG1) - 1)) * SL1 + (line >> LG1) * SL2;
        const int v = u >> (LG1 + LG2);
        const int t = v & (h - 1);
        const int p = ((v >> S) << (S + 2)) + t;
        float4* e = base + loff + p * SP;
        float4 a = e[0], b = e[h * SP], c = e[2 * h * SP], d = e[3 * h * SP];
        const float2 w0 = tw[t << (5 - S)];
        const float2 w1 = make_float2(w0.y, -w0.x);
        const float2 w2 = csq(w0);
        if constexpr (!INV) {
            float4 ac = f4add(a, c), bd = f4add(b, d);
            float4 cP = c4mul(f4sub(a, c), w0);
            float4 dP = c4mul(f4sub(b, d), w1);
            e[0]          = f4add(ac, bd);
            e[h * SP]     = c4mul(f4sub(ac, bd), w2);
            e[2 * h * SP] = f4add(cP, dP);
            e[3 * h * SP] = c4mul(f4sub(cP, dP), w2);
        } else {
            float4 bw = c4mulc(b, w2), dw = c4mulc(d, w2);
            float4 aP = f4add(a, bw), bP = f4sub(a, bw);
            float4 cP = f4add(c, dw), dP = f4sub(c, dw);
            float4 cw = c4mulc(cP, w0), dq = c4mulc(dP, w1);
            float4 o0 = f4add(aP, cw), o2 = f4sub(aP, cw);
            float4 o1 = f4add(bP, dq), o3 = f4sub(bP, dq);
            if constexpr (LAST) {
                o0 = f4sc(o0, scale); o1 = f4sc(o1, scale);
                o2 = f4sc(o2, scale); o3 = f4sc(o3, scale);
            }
            e[0] = o0; e[h * SP] = o1; e[2 * h * SP] = o2; e[3 * h * SP] = o3;
        }
    }
    __syncthreads();
}

// ---------------- float2 passes (p1 only) ----------------
template<int NTT, int SP, int LG1, int LOGN, int S>
__device__ __forceinline__ void pass8s(float2* __restrict__ base,
                                       const float2* __restrict__ tw) {
    constexpr int L = 1 << LG1;
    constexpr int ITEMS = L << (LOGN - 3);
    constexpr int h = 1 << S;
    for (int u = threadIdx.x; u < ITEMS; u += NTT) {
        const int loff = (u & (L - 1));
        const int v = u >> LG1;
        const int t = v & (h - 1);
        const int p = ((v >> S) << (S + 3)) + t;
        float2* e = base + loff + p * SP;
        float2 z[8];
        #pragma unroll
        for (int j = 0; j < 8; ++j) z[j] = e[j * h * SP];
        fwd8t2(z, tw[t << (4 - S)]);
        #pragma unroll
        for (int j = 0; j < 8; ++j) e[j * h * SP] = z[j];
    }
    __syncthreads();
}
template<int NTT, int SP, int LG1, int LOGN, int S>
__device__ __forceinline__ void pass2s(float2* __restrict__ base,
                                       const float2* __restrict__ tw) {
    constexpr int L = 1 << LG1;
    constexpr int ITEMS = L << (LOGN - 1);
    constexpr int h = 1 << S;
    for (int u = threadIdx.x; u < ITEMS; u += NTT) {
        const int loff = (u & (L - 1));
        const int v = u >> LG1;
        const int t = v & (h - 1);
        const int p = ((v >> S) << (S + 1)) + t;
        float2* e = base + loff + p * SP;
        float2 a = e[0], b = e[h * SP];
        const float2 w = tw[t << (6 - S)];
        e[0]      = f2add(a, b);
        e[h * SP] = cmul(f2sub(a, b), w);
    }
    __syncthreads();
}

// ---------------- K0: precompute ----------------
__device__ __forceinline__ void writeU(float4* dst, float axf, float ayf, float azf) {
    double ax = axf, ay = ayf, az = azf;
    double r = sqrt(ax * ax + ay * ay + az * az + 1e-20);
    double cr = cos(r), sn = sin(r) / r;
    dst[0] = make_float4((float)cr, (float)(-az * sn), (float)(-ay * sn), (float)(-ax * sn));
}

__global__ void k0(const float* __restrict__ mux0, const float* __restrict__ mux1,
                   const float* __restrict__ mux2) {
    int idx = blockIdx.x * blockDim.x + threadIdx.x;   // 16384 threads
    if (idx < 64) {
        double ang = -2.0 * PI_D * (double)idx / 128.0;
        g_TW[idx] = make_float2((float)cos(ang), (float)sin(ang));
    }
    {   // U0: [kxb][kyb]
        int kxb = idx >> 7, kyb = idx & 127;
        int kx = __brev((unsigned)kxb) >> 25, ky = __brev((unsigned)kyb) >> 25;
        const float* c = mux0 + (kx * 128 + ky) * 3;
        writeU(&g_U0[idx], c[0], c[1], c[2]);
    }
    {   // U1: TRANSPOSED [cx][cy][kyb][kxb]
        int cx = idx >> 13, cy = (idx >> 12) & 1, kxb = (idx >> 6) & 63, kyb = idx & 63;
        int kx = __brev((unsigned)kxb) >> 26, ky = __brev((unsigned)kyb) >> 26;
        const float* c = mux1 + (((cx * 2 + cy) * 64 + kx) * 64 + ky) * 3;
        int tidx = (cx << 13) + (cy << 12) + (kyb << 6) + kxb;
        writeU(&g_U1[tidx], c[0], c[1], c[2]);
    }
    if (idx < 4096) {   // U2: TRANSPOSED [cx][cy][kyb][kxb]
        int cx = idx >> 11, cy = (idx >> 10) & 1, kxb = (idx >> 5) & 31, kyb = idx & 31;
        int kx = __brev((unsigned)kxb) >> 27, ky = __brev((unsigned)kyb) >> 27;
        const float* c = mux2 + (((cx * 2 + cy) * 32 + kx) * 32 + ky) * 3;
        int tidx = (cx << 11) + (cy << 10) + (kyb << 5) + kxb;
        writeU(&g_U2[tidx], c[0], c[1], c[2]);
    }
}

// ---------------- P1: encode + y-FFT128 (Hermitian packed) ----------------
#define NT1 512
__global__ __launch_bounds__(NT1) void p1(const float* __restrict__ images) {
    __shared__ float2 z[128 * 33];
    __shared__ float2 tw[64];
    const int b = blockIdx.y, X0 = blockIdx.x * 32;
    for (int i = threadIdx.x; i < 64; i += NT1) tw[i] = g_TW[i];
    __syncthreads();
    // FUSED: encode (FRQI sincos) + fwd128-y stages 6,5,4 (8 pixels stride 16 per thread)
    for (int u = threadIdx.x; u < 512; u += NT1) {
        int t = u & 15, l = u >> 4;                    // l in [0,32)
        const float* img = images + (b * 128 + X0 + l) * 128 + t;
        float2 z8[8];
        #pragma unroll
        for (int j = 0; j < 8; ++j) {
            float sv, cv;
            sincosf(0.5f * (float)PI_D * img[16 * j], &sv, &cv);
            z8[j] = make_float2(cv * (1.0f / 128.0f), sv * (1.0f / 128.0f));
        }
        fwd8t2(z8, tw[t]);
        #pragma unroll
        for (int j = 0; j < 8; ++j) z[(t + 16 * j) * 33 + l] = z8[j];
    }
    __syncthreads();
    pass8s<NT1, 33, 5, 7, 1>(z, tw);   // stages 3,2,1
    pass2s<NT1, 33, 5, 7, 0>(z, tw);   // stage 0
    // unpack Hermitian pair (arithmetic bitrev-negation, no table)
    for (int idx = threadIdx.x; idx < 4096; idx += NT1) {
        int l = idx >> 7, kb = idx & 127;
        int k = (int)(__brev((unsigned)kb) >> 25);
        int nr = (int)(__brev((unsigned)((128 - k) & 127)) >> 25);
        float2 Z = z[kb * 33 + l];
        float2 Zn = z[nr * 33 + l];
        float2 C  = make_float2(0.5f * (Z.x + Zn.x), 0.5f * (Z.y - Zn.y));
        float2 Sf = make_float2(0.5f * (Z.y + Zn.y), 0.5f * (Zn.x - Z.x));
        int X = X0 + l;
        g_S4[(b * 128 + X) * 128 + kb] = make_float4(C.x, C.y, Sf.x, Sf.y);
    }
}

// ---------------- P2: x-FFT128 + mux0 + x-IFFT128 + x-FFT64(halves) ----------------
#define NT2 512
__global__ __launch_bounds__(NT2) void p2() {
    __shared__ float4 tile[128 * 16];
    __shared__ float2 tw[64];
    const int b = blockIdx.y, y0 = blockIdx.x * 16;
    for (int i = threadIdx.x; i < 64; i += NT2) tw[i] = g_TW[i];
    __syncthreads();
    // fused: fwd128 stages 6,5 reading directly from global
    for (int u = threadIdx.x; u < 512; u += NT2) {
        int yl = u & 15, v = u >> 4;                 // v in [0,32)
        const float4* g = &g_S4[(b * 128 + v) * 128 + y0 + yl];
        float4 a = g[0], bb = g[32 * 128], c = g[64 * 128], d = g[96 * 128];
        float4 r0, r1, r2, r3;
        fwd4q(a, bb, c, d, tw[v], r0, r1, r2, r3);
        float4* e = tile + v * 16 + yl;
        e[0] = r0; e[32 * 16] = r1; e[64 * 16] = r2; e[96 * 16] = r3;
    }
    __syncthreads();
    // fwd128 stages 4,3,2 (8-pt DIF blocks of 32, t in [0,4))
    for (int u = threadIdx.x; u < 256; u += NT2) {
        int yl = u & 15, r = u >> 4;
        int blk = r >> 2, t = r & 3;
        float4* e = tile + (blk * 32 + t) * 16 + yl;
        float4 z[8];
        #pragma unroll
        for (int j = 0; j < 8; ++j) z[j] = e[j * 64];
        fwd8t(z, tw[t << 2]);
        #pragma unroll
        for (int j = 0; j < 8; ++j) e[j * 64] = z[j];
    }
    __syncthreads();
    // fused: fwd128 stages 1,0 (t=0 quad) + mux0
    for (int u = threadIdx.x; u < 512; u += NT2) {
        int yl = u & 15, v = u >> 4;                 // v in [0,32)
        float4* e = tile + (4 * v) * 16 + yl;
        float4 r0, r1, r2, r3;
        fwd4q(e[0], e[16], e[32], e[48], make_float2(1.f, 0.f), r0, r1, r2, r3);
        int i0 = ((4 * v) << 7) + y0 + yl;
        e[0]  = mux4su(r0, g_U0[i0]);
        e[16] = mux4su(r1, g_U0[i0 + 128]);
        e[32] = mux4su(r2, g_U0[i0 + 256]);
        e[48] = mux4su(r3, g_U0[i0 + 384]);
    }
    __syncthreads();
    // inv128 stages 0,1,2
    for (int u = threadIdx.x; u < 256; u += NT2) {
        int yl = u & 15, v = u >> 4;                 // v in [0,16)
        float4* e = tile + (8 * v) * 16 + yl;
        float4 z[8];
        #pragma unroll
        for (int j = 0; j < 8; ++j) z[j] = e[j * 16];
        inv8t(z, make_float2(1.f, 0.f), 1.f);
        #pragma unroll
        for (int j = 0; j < 8; ++j) e[j * 16] = z[j];
    }
    __syncthreads();
    // inv128 stages 3,4,5
    for (int u = threadIdx.x; u < 256; u += NT2) {
        int yl = u & 15, blk = (u >> 4) & 1, t = u >> 5;  // t in [0,8)
        float4* e = tile + (blk * 64 + t) * 16 + yl;
        float4 z[8];
        #pragma unroll
        for (int j = 0; j < 8; ++j) z[j] = e[j * 8 * 16];
        inv8t(z, tw[2 * t], 1.f);
        #pragma unroll
        for (int j = 0; j < 8; ++j) e[j * 8 * 16] = z[j];
    }
    __syncthreads();
    // FUSION D: inv128 stage 6 (scale 1/128) + fwd64 stages h=32,16
    for (int u = threadIdx.x; u < 256; u += NT2) {
        int yl = u & 15, t = u >> 4;                 // t in [0,16)
        float4* e = tile + yl;
        float4 p0[4], p1[4];
        #pragma unroll
        for (int k = 0; k < 4; ++k) {
            float4 a = e[(t + 16 * k) * 16], bq = e[(t + 64 + 16 * k) * 16];
            float4 bw = c4mulc(bq, tw[t + 16 * k]);
            p0[k] = f4sc(f4add(a, bw), 1.0f / 128.0f);
            p1[k] = f4sc(f4sub(a, bw), 1.0f / 128.0f);
        }
        const float2 wf = tw[2 * t];
        float4 r0, r1, r2, r3;
        fwd4q(p0[0], p0[1], p0[2], p0[3], wf, r0, r1, r2, r3);
        e[t * 16] = r0; e[(t + 16) * 16] = r1; e[(t + 32) * 16] = r2; e[(t + 48) * 16] = r3;
        fwd4q(p1[0], p1[1], p1[2], p1[3], wf, r0, r1, r2, r3);
        e[(t + 64) * 16] = r0; e[(t + 80) * 16] = r1; e[(t + 96) * 16] = r2; e[(t + 112) * 16] = r3;
    }
    __syncthreads();
    // fwd64 halves: h=8,4, then fused h=2,1 + global store
    pass4<false, NT2, 16, 1, 4, 1024, 1, 6, 2, false>(tile, tw, 1.f);
    for (int u = threadIdx.x; u < 512; u += NT2) {
        int yl = u & 15, half = (u >> 4) & 1, v = u >> 5;   // v in [0,16)
        float4* e = tile + half * 1024 + (4 * v) * 16 + yl;
        float4 a = e[0], bb = e[16], c = e[32], d = e[48];
        float4 ac = f4add(a, c), bd = f4add(bb, d);
        float4 cP = f4sub(a, c);
        float4 dP = c4mulnegi(f4sub(bb, d));
        int Xb = half * 64 + 4 * v;
        float4* g = &g_S4[(b * 128 + Xb) * 128 + y0 + yl];
        g[0]   = f4add(ac, bd);
        g[128] = f4sub(ac, bd);
        g[256] = f4add(cP, dP);
        g[384] = f4sub(cP, dP);
    }
}

// ---------------- P35 ----------------
#define NT3 1024
#define P35_SMEM (132096 + 512 + 16896 + 1280)
__global__ __launch_bounds__(NT3) void p35(const float* __restrict__ W) {
    extern __shared__ char sm[];
    float4* tile = (float4*)sm;                            // [64 X][129] float4
    float2* tw   = (float2*)(sm + 132096);
    float*  prob = (float*)(sm + 132096 + 512);            // [2 f][64 X][33 pitch]
    float*  red  = (float*)(sm + 132096 + 512 + 16896);    // 32*10 f32
    const int b = blockIdx.y, xc1 = blockIdx.x;
    for (int i = threadIdx.x; i < 64; i += NT3) tw[i] = g_TW[i];
    __syncthreads();
    // inv128-y stages 0,1,2 reading directly from global
    for (int u = threadIdx.x; u < 1024; u += NT3) {
        int X = u & 63, v = u >> 6;                        // v in [0,16)
        const float4* g = &g_S4[(b * 128 + xc1 * 64 + X) * 128 + 8 * v];
        float4 z[8];
        #pragma unroll
        for (int j = 0; j < 8; ++j) z[j] = g[j];
        inv8t(z, make_float2(1.f, 0.f), 1.f);
        float4* e = tile + X * 129 + 8 * v;
        #pragma unroll
        for (int j = 0; j < 8; ++j) e[j] = z[j];
    }
    __syncthreads();
    // inv128-y stages 3,4,5
    for (int u = threadIdx.x; u < 1024; u += NT3) {
        int X = u & 63, blk = (u >> 6) & 1, t = u >> 7;    // t in [0,8)
        float4* e = tile + X * 129 + blk * 64 + t;
        float4 z[8];
        #pragma unroll
        for (int j = 0; j < 8; ++j) z[j] = e[8 * j];
        inv8t(z, tw[2 * t], 1.f);
        #pragma unroll
        for (int j = 0; j < 8; ++j) e[8 * j] = z[j];
    }
    __syncthreads();
    // FUSION A: inv128-y stage 6 (scale 1/128) + fwd64-y stages h=32,16
    for (int u = threadIdx.x; u < 1024; u += NT3) {
        int X = u & 63, t = u >> 6;                        // t in [0,16)
        float4* e = tile + X * 129;
        float4 p0[4], p1[4];
        #pragma unroll
        for (int k = 0; k < 4; ++k) {
            float4 a = e[t + 16 * k], bq = e[t + 64 + 16 * k];
            float4 bw = c4mulc(bq, tw[t + 16 * k]);
            p0[k] = f4sc(f4add(a, bw), 1.0f / 128.0f);
            p1[k] = f4sc(f4sub(a, bw), 1.0f / 128.0f);
        }
        const float2 wf = tw[2 * t];
        float4 r0, r1, r2, r3;
        fwd4q(p0[0], p0[1], p0[2], p0[3], wf, r0, r1, r2, r3);
        e[t] = r0; e[t + 16] = r1; e[t + 32] = r2; e[t + 48] = r3;
        fwd4q(p1[0], p1[1], p1[2], p1[3], wf, r0, r1, r2, r3);
        e[t + 64] = r0; e[t + 80] = r1; e[t + 96] = r2; e[t + 112] = r3;
    }
    __syncthreads();
    // fwd64 y halves: h=8,4, then fused h=2,1 + mux1
    pass4<false, NT3, 1, 129, 6, 64, 1, 6, 2, false>(tile, tw, 1.f);
    for (int u = threadIdx.x; u < 2048; u += NT3) {
        int X = u & 63, half = (u >> 6) & 1, v = u >> 7;   // v in [0,16)
        float4* e = tile + X * 129 + half * 64 + 4 * v;
        float4 r0, r1, r2, r3;
        fwd4q(e[0], e[1], e[2], e[3], make_float2(1.f, 0.f), r0, r1, r2, r3);
        int ub = ((xc1 * 2 + half) << 12) + ((4 * v) << 6) + X;
        e[0] = mux4su(r0, g_U1[ub]);
        e[1] = mux4su(r1, g_U1[ub + 64]);
        e[2] = mux4su(r2, g_U1[ub + 128]);
        e[3] = mux4su(r3, g_U1[ub + 192]);
    }
    __syncthreads();
    // x junction: inv64-x stages 0,1,2
    for (int u = threadIdx.x; u < 1024; u += NT3) {
        int y = u & 127, m = u >> 7;                       // m in [0,8)
        float4* e = tile + (8 * m) * 129 + y;
        float4 z[8];
        #pragma unroll
        for (int j = 0; j < 8; ++j) z[j] = e[j * 129];
        inv8t(z, make_float2(1.f, 0.f), 1.f);
        #pragma unroll
        for (int j = 0; j < 8; ++j) e[j * 129] = z[j];
    }
    __syncthreads();
    // FUSION B': inv64-x stages 3,4,5 (scale 1/64) + fwd32-x stages h=16,8
    for (int u = threadIdx.x; u < 1024; u += NT3) {
        int y = u & 127, t = u >> 7;                       // t in [0,8)
        float4* e = tile + t * 129 + y;
        float4 z[8];
        #pragma unroll
        for (int j = 0; j < 8; ++j) z[j] = e[8 * j * 129];
        inv8t(z, tw[2 * t], 1.0f / 64.0f);
        const float2 wf = tw[4 * t];
        float4 r0, r1, r2, r3;
        fwd4q(z[0], z[1], z[2], z[3], wf, r0, r1, r2, r3);
        e[0] = r0; e[8 * 129] = r1; e[16 * 129] = r2; e[24 * 129] = r3;
        fwd4q(z[4], z[5], z[6], z[7], wf, r0, r1, r2, r3);
        e[32 * 129] = r0; e[40 * 129] = r1; e[48 * 129] = r2; e[56 * 129] = r3;
    }
    __syncthreads();
    // MERGE P: fwd32-x stages h=4,2,1
    for (int u = threadIdx.x; u < 1024; u += NT3) {
        int y = u & 127, r = u >> 7;
        int m = r & 3, xs = r >> 2;
        float4* e = tile + (xs * 32 + 8 * m) * 129 + y;
        float4 z[8];
        #pragma unroll
        for (int j = 0; j < 8; ++j) z[j] = e[j * 129];
        fwd8q(z);
        #pragma unroll
        for (int j = 0; j < 8; ++j) e[j * 129] = z[j];
    }
    __syncthreads();
    // y junction: inv64-y stages 0,1,2
    for (int u = threadIdx.x; u < 1024; u += NT3) {
        int X = u & 63, half = (u >> 6) & 1, m = u >> 7;   // m in [0,8)
        float4* e = tile + X * 129 + half * 64 + 8 * m;
        float4 z[8];
        #pragma unroll
        for (int j = 0; j < 8; ++j) z[j] = e[j];
        inv8t(z, make_float2(1.f, 0.f), 1.f);
        #pragma unroll
        for (int j = 0; j < 8; ++j) e[j] = z[j];
    }
    __syncthreads();
    // FUSION C': inv64-y stages 3,4,5 (scale 1/64) + fwd32-y stages h=16,8
    for (int u = threadIdx.x; u < 1024; u += NT3) {
        int X = u & 63, half = (u >> 6) & 1, t = u >> 7;   // t in [0,8)
        float4* e = tile + X * 129 + half * 64 + t;
        float4 z[8];
        #pragma unroll
        for (int j = 0; j < 8; ++j) z[j] = e[8 * j];
        inv8t(z, tw[2 * t], 1.0f / 64.0f);
        const float2 wf = tw[4 * t];
        float4 r0, r1, r2, r3;
        fwd4q(z[0], z[1], z[2], z[3], wf, r0, r1, r2, r3);
        e[0] = r0; e[8] = r1; e[16] = r2; e[24] = r3;
        fwd4q(z[4], z[5], z[6], z[7], wf, r0, r1, r2, r3);
        e[32] = r0; e[40] = r1; e[48] = r2; e[56] = r3;
    }
    __syncthreads();
    // MERGE Q: fwd32-y stages h=4,2,1 + mux2
    for (int u = threadIdx.x; u < 1024; u += NT3) {
        int X = u & 63, r = u >> 6;
        int seg = r & 3, m = r >> 2;
        float4* e = tile + X * 129 + seg * 32 + 8 * m;
        float4 z[8];
        #pragma unroll
        for (int j = 0; j < 8; ++j) z[j] = e[j];
        fwd8q(z);
        int xc2 = X >> 5, yc2 = seg & 1;
        int ubase = ((xc2 * 2 + yc2) << 10) + ((8 * m) << 5) + (X & 31);
        #pragma unroll
        for (int j = 0; j < 8; ++j)
            e[j] = mux4su(z[j], g_U2[ubase + 32 * j]);
    }
    __syncthreads();
    // final x inv32: pass4 stages 0,1, then MERGE R (stages 2,3,4 + scale 1/32)
    pass4<true, NT3, 129, 1, 7, 4128, 1, 5, 0, false>(tile, tw, 1.f);
    for (int u = threadIdx.x; u < 1024; u += NT3) {
        int y = u & 127, r = u >> 7;
        int t = r & 3, xs = r >> 2;
        float4* e = tile + (xs * 32 + t) * 129 + y;
        float4 z[8];
        #pragma unroll
        for (int j = 0; j < 8; ++j) z[j] = e[4 * j * 129];
        inv8t(z, tw[4 * t], 1.0f / 32.0f);
        #pragma unroll
        for (int j = 0; j < 8; ++j) e[4 * j * 129] = z[j];
    }
    __syncthreads();
    // final y inv32: stages 0,1,2
    for (int u = threadIdx.x; u < 1024; u += NT3) {
        int X = u & 63, seg = (u >> 6) & 3, m = u >> 8;    // m in [0,4)
        float4* e = tile + X * 129 + seg * 32 + 8 * m;
        float4 z[8];
        #pragma unroll
        for (int j = 0; j < 8; ++j) z[j] = e[j];
        inv8t(z, make_float2(1.f, 0.f), 1.f);
        #pragma unroll
        for (int j = 0; j < 8; ++j) e[j] = z[j];
    }
    __syncthreads();
    // measure': final y inv32 stages 3,4 (inv4q, scale 1/32) + |.|^2 accumulate over segs
    for (int u = threadIdx.x; u < 512; u += NT3) {
        int X = u & 63, t = u >> 6;                        // t in [0,8)
        const float2 w0 = tw[4 * t];
        float s0[4], s1[4];
        #pragma unroll
        for (int j = 0; j < 4; ++j) { s0[j] = 0.f; s1[j] = 0.f; }
        #pragma unroll
        for (int seg = 0; seg < 4; ++seg) {
            const float4* e = tile + X * 129 + seg * 32 + t;
            float4 o0, o1, o2, o3;
            inv4q(e[0], e[8], e[16], e[24], w0, 1.0f / 32.0f, o0, o1, o2, o3);
            s0[0] += o0.x * o0.x + o0.y * o0.y;  s1[0] += o0.z * o0.z + o0.w * o0.w;
            s0[1] += o1.x * o1.x + o1.y * o1.y;  s1[1] += o1.z * o1.z + o1.w * o1.w;
            s0[2] += o2.x * o2.x + o2.y * o2.y;  s1[2] += o2.z * o2.z + o2.w * o2.w;
            s0[3] += o3.x * o3.x + o3.y * o3.y;  s1[3] += o3.z * o3.z + o3.w * o3.w;
        }
        #pragma unroll
        for (int j = 0; j < 4; ++j) {
            prob[X * 33 + t + 8 * j]        = s0[j];
            prob[2112 + X * 33 + t + 8 * j] = s1[j];
        }
    }
    __syncthreads();
    // partial GEMV
    float acc[10];
    #pragma unroll
    for (int c = 0; c < 10; ++c) acc[c] = 0.f;
    {
        int xa = threadIdx.x >> 5, ya = threadIdx.x & 31;
        float p0 = prob[xa * 33 + ya]        + prob[(xa + 32) * 33 + ya];
        float p1 = prob[2112 + xa * 33 + ya] + prob[2112 + (xa + 32) * 33 + ya];
        int j0 = threadIdx.x * 2;
        #pragma unroll
        for (int c = 0; c < 10; ++c) {
            float2 wv = *(const float2*)(W + c * 2048 + j0);
            acc[c] = fmaf(p0, wv.x, fmaf(p1, wv.y, acc[c]));
        }
    }
    #pragma unroll
    for (int c = 0; c < 10; ++c)
        #pragma unroll
        for (int o = 16; o > 0; o >>= 1)
            acc[c] += __shfl_down_sync(0xffffffffu, acc[c], o);
    const int warp = threadIdx.x >> 5, lane = threadIdx.x & 31;
    if (lane == 0)
        #pragma unroll
        for (int c = 0; c < 10; ++c) red[warp * 10 + c] = acc[c];
    __syncthreads();
    if (threadIdx.x < 10) {
        float s = 0.f;
        #pragma unroll
        for (int w = 0; w < 32; ++w) s += red[w * 10 + threadIdx.x];
        g_part[(b * 2 + xc1) * 10 + threadIdx.x] = s;
    }
}

// ---------------- combine ----------------
__global__ void pc(const float* __restrict__ bias, float* __restrict__ out) {
    int i = blockIdx.x * blockDim.x + threadIdx.x;
    if (i < 5120) {
        int b = i / 10, c = i % 10;
        out[i] = bias[c] + g_part[(b * 2) * 10 + c] + g_part[(b * 2 + 1) * 10 + c];
    }
}

// ---------------- launch ----------------
extern "C" void kernel_launch(void* const* d_in, const int* in_sizes, int n_in,
                              void* d_out, int out_size) {
    const float* images = (const float*)d_in[0];
    const float* mux0 = (const float*)d_in[1];
    const float* mux1 = (const float*)d_in[2];
    const float* mux2 = (const float*)d_in[3];
    const float* W = (const float*)d_in[4];
    const float* bias = (const float*)d_in[5];
    float* out = (float*)d_out;
    (void)in_sizes; (void)n_in; (void)out_size;

    cudaFuncSetAttribute(p35, cudaFuncAttributeMaxDynamicSharedMemorySize, P35_SMEM);

    k0<<<64, 256>>>(mux0, mux1, mux2);
    p1<<<dim3(4, 512), NT1>>>(images);
    p2<<<dim3(8, 512), NT2>>>();
    p35<<<dim3(2, 512), NT3, P35_SMEM>>>(W);
    pc<<<10, 512>>>(bias, out);
}